// round 3
// baseline (speedup 1.0000x reference)
#include <cuda_runtime.h>
#include <cuda_bf16.h>

// Problem constants
#define BB 2
#define NN 2048
#define HH 8
#define EE 512
#define DOUT 504          // H * 63
#define DD 64             // lifted dim
#define ROWS 4096         // B*N
#define BHN (BB*HH)       // 16

// ---------------- scratch (device globals; no allocation allowed) ----------
__device__ float g_raw[3 * ROWS * DOUT];        // raw projections q,k,v
__device__ float g_q[BHN * NN * DD];            // lifted q (sign+scale folded)
__device__ float g_k[BHN * NN * DD];
__device__ float g_v[BHN * NN * DD];
__device__ float g_ave[ROWS * HH * DD];         // attention output per head

// ---------------- Kernel 1: QKV projection GEMM ----------------------------
// out[r][c] = sum_k A[r][k] * W[c][k] + b[c]   (A row-major [4096,512], W [504,512])
__global__ void __launch_bounds__(256) gemm_qkv(
    const float* __restrict__ Aq, const float* __restrict__ As,
    const float* __restrict__ Wq, const float* __restrict__ bq,
    const float* __restrict__ Wk, const float* __restrict__ bk,
    const float* __restrict__ Wv, const float* __restrict__ bv)
{
    int z = blockIdx.z;
    const float* A = (z == 0) ? Aq : As;
    const float* W = (z == 0) ? Wq : (z == 1 ? Wk : Wv);
    const float* bias = (z == 0) ? bq : (z == 1 ? bk : bv);
    float* out = g_raw + (size_t)z * ROWS * DOUT;

    __shared__ float a_s[64 * 17];
    __shared__ float w_s[64 * 17];

    int tid = threadIdx.x;
    int tx = tid & 15, ty = tid >> 4;
    int rowTile = blockIdx.x * 64;
    int colTile = blockIdx.y * 64;

    float acc[4][4];
#pragma unroll
    for (int i = 0; i < 4; i++)
#pragma unroll
        for (int j = 0; j < 4; j++) acc[i][j] = 0.f;

    int lrow = tid >> 2;          // 0..63
    int lk4 = (tid & 3) * 4;      // 0,4,8,12

    for (int k0 = 0; k0 < EE; k0 += 16) {
        float4 av = *(const float4*)(A + (size_t)(rowTile + lrow) * EE + k0 + lk4);
        int wcol = colTile + lrow;
        float4 wv = make_float4(0.f, 0.f, 0.f, 0.f);
        if (wcol < DOUT) wv = *(const float4*)(W + (size_t)wcol * EE + k0 + lk4);
        __syncthreads();
        a_s[lrow * 17 + lk4 + 0] = av.x;
        a_s[lrow * 17 + lk4 + 1] = av.y;
        a_s[lrow * 17 + lk4 + 2] = av.z;
        a_s[lrow * 17 + lk4 + 3] = av.w;
        w_s[lrow * 17 + lk4 + 0] = wv.x;
        w_s[lrow * 17 + lk4 + 1] = wv.y;
        w_s[lrow * 17 + lk4 + 2] = wv.z;
        w_s[lrow * 17 + lk4 + 3] = wv.w;
        __syncthreads();
#pragma unroll
        for (int kk = 0; kk < 16; kk++) {
            float a[4], w[4];
#pragma unroll
            for (int i = 0; i < 4; i++) a[i] = a_s[(ty * 4 + i) * 17 + kk];
#pragma unroll
            for (int j = 0; j < 4; j++) w[j] = w_s[(tx * 4 + j) * 17 + kk];
#pragma unroll
            for (int i = 0; i < 4; i++)
#pragma unroll
                for (int j = 0; j < 4; j++) acc[i][j] += a[i] * w[j];
        }
    }

#pragma unroll
    for (int i = 0; i < 4; i++) {
        int r = rowTile + ty * 4 + i;
#pragma unroll
        for (int j = 0; j < 4; j++) {
            int c = colTile + tx * 4 + j;
            if (c < DOUT) out[(size_t)r * DOUT + c] = acc[i][j] + bias[c];
        }
    }
}

// ---------------- Kernel 2: hyperboloid lift --------------------------------
// warp per (z, row, head). q gets sign-negated time and (2/scale) fold.
__global__ void __launch_bounds__(256) lift_kernel(const float* __restrict__ scale_ptr)
{
    int w = (blockIdx.x * blockDim.x + threadIdx.x) >> 5;
    int lane = threadIdx.x & 31;
    // w in [0, 3*4096*8)
    int z = w / (ROWS * HH);
    int rem = w - z * (ROWS * HH);
    int r = rem >> 3;
    int h = rem & 7;
    const float* x = g_raw + (size_t)z * ROWS * DOUT + (size_t)r * DOUT + h * 63;
    float xa = (lane > 0) ? x[lane - 1] : 0.0f;   // out dim = lane   (x[lane-1])
    float xb = x[lane + 31];                      // out dim = lane+32 (x[lane+31])
    float ss = xa * xa + xb * xb;
#pragma unroll
    for (int o = 16; o; o >>= 1) ss += __shfl_xor_sync(0xffffffffu, ss, o);
    float t = sqrtf(ss + 1.0f);

    int b = r >> 11, n = r & (NN - 1);
    int bh = b * HH + h;
    float* dst = (z == 0 ? g_q : (z == 1 ? g_k : g_v)) + ((size_t)bh * NN + n) * DD;
    float w0 = (lane == 0) ? t : xa;
    float w1 = xb;
    if (z == 0) {
        float sc = 2.0f / scale_ptr[0];
        if (lane == 0) w0 = -t;
        w0 *= sc; w1 *= sc;
    }
    dst[lane] = w0;
    dst[lane + 32] = w1;
}

// ---------------- Kernel 3: flash attention ---------------------------------
// block = 64 threads, one query row each; K/V tiles of 64 rows through smem.
__global__ void __launch_bounds__(64) attn_kernel()
{
    __shared__ float4 ks[64 * 16];
    __shared__ float4 vs[64 * 16];
    int tid = threadIdx.x;
    int bh = blockIdx.y;
    int n = blockIdx.x * 64 + tid;

    const float4* qr = (const float4*)(g_q + ((size_t)bh * NN + n) * DD);
    float4 q[16];
#pragma unroll
    for (int i = 0; i < 16; i++) q[i] = qr[i];

    float4 acc[16];
#pragma unroll
    for (int i = 0; i < 16; i++) acc[i] = make_float4(0.f, 0.f, 0.f, 0.f);
    float mx = -1e30f, l = 0.f;

    const float4* kg = (const float4*)(g_k + (size_t)bh * NN * DD);
    const float4* vg = (const float4*)(g_v + (size_t)bh * NN * DD);

    for (int t0 = 0; t0 < NN; t0 += 64) {
        __syncthreads();
#pragma unroll
        for (int i = 0; i < 16; i++) {
            int f = i * 64 + tid;
            ks[f] = kg[t0 * 16 + f];
            vs[f] = vg[t0 * 16 + f];
        }
        __syncthreads();
        for (int mm = 0; mm < 64; mm++) {
            const float4* kr = ks + mm * 16;
            float sx = 0.f, sy = 0.f, sz = 0.f, sw = 0.f;
#pragma unroll
            for (int i = 0; i < 16; i++) {
                float4 kv = kr[i];
                sx += q[i].x * kv.x; sy += q[i].y * kv.y;
                sz += q[i].z * kv.z; sw += q[i].w * kv.w;
            }
            float s = (sx + sy) + (sz + sw);
            if (s > mx) {                    // rare after warmup
                float corr = __expf(mx - s);
                mx = s;
                l *= corr;
#pragma unroll
                for (int i = 0; i < 16; i++) {
                    acc[i].x *= corr; acc[i].y *= corr;
                    acc[i].z *= corr; acc[i].w *= corr;
                }
            }
            float p = __expf(s - mx);
            l += p;
            const float4* vr = vs + mm * 16;
#pragma unroll
            for (int i = 0; i < 16; i++) {
                float4 vv = vr[i];
                acc[i].x += p * vv.x; acc[i].y += p * vv.y;
                acc[i].z += p * vv.z; acc[i].w += p * vv.w;
            }
        }
    }

    float inv = 1.0f / l;
    int b = bh >> 3, h = bh & 7;
    float4* dst = (float4*)(g_ave + (((size_t)(b * NN + n)) * HH + h) * DD);
#pragma unroll
    for (int i = 0; i < 16; i++) {
        float4 o = acc[i];
        o.x *= inv; o.y *= inv; o.z *= inv; o.w *= inv;
        dst[i] = o;
    }
}

// ---------------- Kernel 4: centroid epilogue -------------------------------
// warp per (b,n): per-head Lorentz centroid -> head mean -> centroid -> out.
__device__ __forceinline__ float warp_sum(float v)
{
#pragma unroll
    for (int o = 16; o; o >>= 1) v += __shfl_xor_sync(0xffffffffu, v, o);
    return v;
}

__global__ void __launch_bounds__(256) centroid_kernel(float* __restrict__ out)
{
    int w = (blockIdx.x * blockDim.x + threadIdx.x) >> 5;  // bn index, 0..4095
    int lane = threadIdx.x & 31;
    float m0 = 0.f, m1 = 0.f;
#pragma unroll
    for (int h = 0; h < HH; h++) {
        const float* a = g_ave + ((size_t)w * HH + h) * DD;
        float a0 = a[lane], a1 = a[lane + 32];
        float part = a0 * a0 + a1 * a1;
        if (lane == 0) part -= 2.0f * a0 * a0;
        float inner = warp_sum(part);
        float denom = sqrtf(fmaxf(fabsf(inner), 1e-8f));
        float inv = 1.0f / denom;
        m0 += a0 * inv; m1 += a1 * inv;
    }
    m0 *= (1.0f / HH); m1 *= (1.0f / HH);
    float part = m0 * m0 + m1 * m1;
    if (lane == 0) part -= 2.0f * m0 * m0;
    float inner = warp_sum(part);
    float denom = sqrtf(fmaxf(fabsf(inner), 1e-8f));
    float inv = 1.0f / denom;
    out[(size_t)w * DD + lane] = m0 * inv;
    out[(size_t)w * DD + lane + 32] = m1 * inv;
}

// ---------------- launch -----------------------------------------------------
extern "C" void kernel_launch(void* const* d_in, const int* in_sizes, int n_in,
                              void* d_out, int out_size)
{
    const float* query  = (const float*)d_in[0];
    const float* source = (const float*)d_in[1];
    const float* Wq = (const float*)d_in[2];
    const float* bq = (const float*)d_in[3];
    const float* Wk = (const float*)d_in[4];
    const float* bk = (const float*)d_in[5];
    const float* Wv = (const float*)d_in[6];
    const float* bv = (const float*)d_in[7];
    const float* scale = (const float*)d_in[8];
    float* out = (float*)d_out;

    dim3 ggrid(ROWS / 64, (DOUT + 63) / 64, 3);
    gemm_qkv<<<ggrid, 256>>>(query, source, Wq, bq, Wk, bk, Wv, bv);

    int lift_warps = 3 * ROWS * HH;            // 98304
    lift_kernel<<<lift_warps * 32 / 256, 256>>>(scale);

    attn_kernel<<<dim3(NN / 64, BHN), 64>>>();

    centroid_kernel<<<ROWS * 32 / 256, 256>>>(out);
}

// round 4
// speedup vs baseline: 1.7183x; 1.7183x over previous
#include <cuda_runtime.h>
#include <cuda_bf16.h>

// Problem constants
#define BB 2
#define NN 2048
#define HH 8
#define EE 512
#define DOUT 504          // H * 63
#define DD 64             // lifted dim
#define ROWS 4096         // B*N
#define BHN (BB*HH)       // 16

typedef unsigned long long u64;

// ---------------- packed f32x2 helpers (sm_103a FFMA2 path) -----------------
__device__ __forceinline__ u64 fma2(u64 a, u64 b, u64 c) {
    u64 d; asm("fma.rn.f32x2 %0, %1, %2, %3;" : "=l"(d) : "l"(a), "l"(b), "l"(c));
    return d;
}
__device__ __forceinline__ u64 mul2(u64 a, u64 b) {
    u64 d; asm("mul.rn.f32x2 %0, %1, %2;" : "=l"(d) : "l"(a), "l"(b));
    return d;
}
__device__ __forceinline__ u64 add2(u64 a, u64 b) {
    u64 d; asm("add.rn.f32x2 %0, %1, %2;" : "=l"(d) : "l"(a), "l"(b));
    return d;
}
__device__ __forceinline__ u64 pack2(float lo, float hi) {
    u64 d; asm("mov.b64 %0, {%1, %2};" : "=l"(d) : "f"(lo), "f"(hi));
    return d;
}
__device__ __forceinline__ void unpack2(u64 v, float& lo, float& hi) {
    asm("mov.b64 {%0, %1}, %2;" : "=f"(lo), "=f"(hi) : "l"(v));
}

// ---------------- scratch (device globals; no allocation allowed) ----------
__device__ float g_raw[3 * ROWS * DOUT];        // raw projections q,k,v
__device__ float g_q[BHN * NN * DD];            // lifted q (sign+scale folded)
__device__ float g_k[BHN * NN * DD];
__device__ float g_v[BHN * NN * DD];
__device__ float g_ave[ROWS * HH * DD];         // attention output per head

// ---------------- Kernel 1: QKV projection GEMM (k-major smem + FFMA2) ------
// out[r][c] = sum_k A[r][k] * W[c][k] + b[c]
__global__ void __launch_bounds__(256) gemm_qkv(
    const float* __restrict__ Aq, const float* __restrict__ As,
    const float* __restrict__ Wq, const float* __restrict__ bq,
    const float* __restrict__ Wk, const float* __restrict__ bk,
    const float* __restrict__ Wv, const float* __restrict__ bv)
{
    int z = blockIdx.z;
    const float* A = (z == 0) ? Aq : As;
    const float* W = (z == 0) ? Wq : (z == 1 ? Wk : Wv);
    const float* bias = (z == 0) ? bq : (z == 1 ? bk : bv);
    float* out = g_raw + (size_t)z * ROWS * DOUT;

    // k-major smem: [k][row], row padded to 72 floats (288B, 16B-aligned rows)
    __shared__ float a_s[16][72];
    __shared__ float w_s[16][72];

    int tid = threadIdx.x;
    int tx = tid & 15, ty = tid >> 4;
    int rowTile = blockIdx.x * 64;
    int colTile = blockIdx.y * 64;

    u64 accp[4][2];                  // 4 rows x (2 packed col-pairs) = 4x4 tile
#pragma unroll
    for (int i = 0; i < 4; i++) { accp[i][0] = 0ull; accp[i][1] = 0ull; }

    int lrow = tid >> 2;             // 0..63
    int lk4 = (tid & 3) * 4;         // 0,4,8,12

    for (int k0 = 0; k0 < EE; k0 += 16) {
        float4 av = *(const float4*)(A + (size_t)(rowTile + lrow) * EE + k0 + lk4);
        int wcol = colTile + lrow;
        float4 wv = make_float4(0.f, 0.f, 0.f, 0.f);
        if (wcol < DOUT) wv = *(const float4*)(W + (size_t)wcol * EE + k0 + lk4);
        __syncthreads();
        a_s[lk4 + 0][lrow] = av.x;  a_s[lk4 + 1][lrow] = av.y;
        a_s[lk4 + 2][lrow] = av.z;  a_s[lk4 + 3][lrow] = av.w;
        w_s[lk4 + 0][lrow] = wv.x;  w_s[lk4 + 1][lrow] = wv.y;
        w_s[lk4 + 2][lrow] = wv.z;  w_s[lk4 + 3][lrow] = wv.w;
        __syncthreads();
#pragma unroll
        for (int kk = 0; kk < 16; kk++) {
            float4 af = *(const float4*)&a_s[kk][ty * 4];      // 1 LDS.128 (broadcast)
            ulonglong2 wp = *(const ulonglong2*)&w_s[kk][tx * 4]; // 1 LDS.128, pairs
            u64 ad0 = pack2(af.x, af.x);
            u64 ad1 = pack2(af.y, af.y);
            u64 ad2 = pack2(af.z, af.z);
            u64 ad3 = pack2(af.w, af.w);
            accp[0][0] = fma2(ad0, wp.x, accp[0][0]);
            accp[0][1] = fma2(ad0, wp.y, accp[0][1]);
            accp[1][0] = fma2(ad1, wp.x, accp[1][0]);
            accp[1][1] = fma2(ad1, wp.y, accp[1][1]);
            accp[2][0] = fma2(ad2, wp.x, accp[2][0]);
            accp[2][1] = fma2(ad2, wp.y, accp[2][1]);
            accp[3][0] = fma2(ad3, wp.x, accp[3][0]);
            accp[3][1] = fma2(ad3, wp.y, accp[3][1]);
        }
    }

#pragma unroll
    for (int i = 0; i < 4; i++) {
        int r = rowTile + ty * 4 + i;
        float c0, c1, c2, c3;
        unpack2(accp[i][0], c0, c1);
        unpack2(accp[i][1], c2, c3);
        float vals[4] = {c0, c1, c2, c3};
#pragma unroll
        for (int j = 0; j < 4; j++) {
            int c = colTile + tx * 4 + j;
            if (c < DOUT) out[(size_t)r * DOUT + c] = vals[j] + bias[c];
        }
    }
}

// ---------------- Kernel 2: hyperboloid lift --------------------------------
__global__ void __launch_bounds__(256) lift_kernel(const float* __restrict__ scale_ptr)
{
    int w = (blockIdx.x * blockDim.x + threadIdx.x) >> 5;
    int lane = threadIdx.x & 31;
    int z = w / (ROWS * HH);
    int rem = w - z * (ROWS * HH);
    int r = rem >> 3;
    int h = rem & 7;
    const float* x = g_raw + (size_t)z * ROWS * DOUT + (size_t)r * DOUT + h * 63;
    float xa = (lane > 0) ? x[lane - 1] : 0.0f;
    float xb = x[lane + 31];
    float ss = xa * xa + xb * xb;
#pragma unroll
    for (int o = 16; o; o >>= 1) ss += __shfl_xor_sync(0xffffffffu, ss, o);
    float t = sqrtf(ss + 1.0f);

    int b = r >> 11, n = r & (NN - 1);
    int bh = b * HH + h;
    float* dst = (z == 0 ? g_q : (z == 1 ? g_k : g_v)) + ((size_t)bh * NN + n) * DD;
    float w0 = (lane == 0) ? t : xa;
    float w1 = xb;
    if (z == 0) {
        float sc = 2.0f / scale_ptr[0];
        if (lane == 0) w0 = -t;
        w0 *= sc; w1 *= sc;
    }
    dst[lane] = w0;
    dst[lane + 32] = w1;
}

// ---------------- Kernel 3: flash attention (packed f32x2) ------------------
// block = 64 threads, one query row each; K/V tiles of 64 rows through smem.
__global__ void __launch_bounds__(64) attn_kernel()
{
    __shared__ ulonglong2 ks[64 * 16];   // 64 rows x 64 floats (as 16B pairs)
    __shared__ ulonglong2 vs[64 * 16];
    int tid = threadIdx.x;
    int bh = blockIdx.y;
    int n = blockIdx.x * 64 + tid;

    const ulonglong2* qr = (const ulonglong2*)(g_q + ((size_t)bh * NN + n) * DD);
    u64 q[32];
#pragma unroll
    for (int i = 0; i < 16; i++) { ulonglong2 t = qr[i]; q[2 * i] = t.x; q[2 * i + 1] = t.y; }

    u64 acc[32];
#pragma unroll
    for (int i = 0; i < 32; i++) acc[i] = 0ull;
    float mx = -1e30f, l = 0.f;

    const ulonglong2* kg = (const ulonglong2*)(g_k + (size_t)bh * NN * DD);
    const ulonglong2* vg = (const ulonglong2*)(g_v + (size_t)bh * NN * DD);

    for (int t0 = 0; t0 < NN; t0 += 64) {
        __syncthreads();
#pragma unroll
        for (int i = 0; i < 16; i++) {
            int f = i * 64 + tid;
            ks[f] = kg[t0 * 16 + f];
            vs[f] = vg[t0 * 16 + f];
        }
        __syncthreads();
        for (int mm = 0; mm < 64; mm++) {
            const ulonglong2* kr = ks + mm * 16;
            u64 sa = 0ull, sb = 0ull, sc = 0ull, sd = 0ull;
#pragma unroll
            for (int i = 0; i < 8; i++) {
                ulonglong2 k0 = kr[2 * i];
                ulonglong2 k1 = kr[2 * i + 1];
                sa = fma2(q[4 * i + 0], k0.x, sa);
                sb = fma2(q[4 * i + 1], k0.y, sb);
                sc = fma2(q[4 * i + 2], k1.x, sc);
                sd = fma2(q[4 * i + 3], k1.y, sd);
            }
            u64 st = add2(add2(sa, sb), add2(sc, sd));
            float s0, s1;
            unpack2(st, s0, s1);
            float s = s0 + s1;
            if (s > mx) {                    // rare after warmup
                float corr = __expf(mx - s);
                mx = s;
                l *= corr;
                u64 corrp = pack2(corr, corr);
#pragma unroll
                for (int i = 0; i < 32; i++) acc[i] = mul2(acc[i], corrp);
            }
            float p = __expf(s - mx);
            l += p;
            u64 pp = pack2(p, p);
            const ulonglong2* vr = vs + mm * 16;
#pragma unroll
            for (int i = 0; i < 16; i++) {
                ulonglong2 vv = vr[i];
                acc[2 * i]     = fma2(pp, vv.x, acc[2 * i]);
                acc[2 * i + 1] = fma2(pp, vv.y, acc[2 * i + 1]);
            }
        }
    }

    float inv = 1.0f / l;
    u64 invp = pack2(inv, inv);
    int b = bh >> 3, h = bh & 7;
    ulonglong2* dst = (ulonglong2*)(g_ave + (((size_t)(b * NN + n)) * HH + h) * DD);
#pragma unroll
    for (int i = 0; i < 16; i++) {
        ulonglong2 o;
        o.x = mul2(acc[2 * i], invp);
        o.y = mul2(acc[2 * i + 1], invp);
        dst[i] = o;
    }
}

// ---------------- Kernel 4: centroid epilogue -------------------------------
__device__ __forceinline__ float warp_sum(float v)
{
#pragma unroll
    for (int o = 16; o; o >>= 1) v += __shfl_xor_sync(0xffffffffu, v, o);
    return v;
}

__global__ void __launch_bounds__(256) centroid_kernel(float* __restrict__ out)
{
    int w = (blockIdx.x * blockDim.x + threadIdx.x) >> 5;  // bn index, 0..4095
    int lane = threadIdx.x & 31;
    float m0 = 0.f, m1 = 0.f;
#pragma unroll
    for (int h = 0; h < HH; h++) {
        const float* a = g_ave + ((size_t)w * HH + h) * DD;
        float a0 = a[lane], a1 = a[lane + 32];
        float part = a0 * a0 + a1 * a1;
        if (lane == 0) part -= 2.0f * a0 * a0;
        float inner = warp_sum(part);
        float denom = sqrtf(fmaxf(fabsf(inner), 1e-8f));
        float inv = 1.0f / denom;
        m0 += a0 * inv; m1 += a1 * inv;
    }
    m0 *= (1.0f / HH); m1 *= (1.0f / HH);
    float part = m0 * m0 + m1 * m1;
    if (lane == 0) part -= 2.0f * m0 * m0;
    float inner = warp_sum(part);
    float denom = sqrtf(fmaxf(fabsf(inner), 1e-8f));
    float inv = 1.0f / denom;
    out[(size_t)w * DD + lane] = m0 * inv;
    out[(size_t)w * DD + lane + 32] = m1 * inv;
}

// ---------------- launch -----------------------------------------------------
extern "C" void kernel_launch(void* const* d_in, const int* in_sizes, int n_in,
                              void* d_out, int out_size)
{
    const float* query  = (const float*)d_in[0];
    const float* source = (const float*)d_in[1];
    const float* Wq = (const float*)d_in[2];
    const float* bq = (const float*)d_in[3];
    const float* Wk = (const float*)d_in[4];
    const float* bk = (const float*)d_in[5];
    const float* Wv = (const float*)d_in[6];
    const float* bv = (const float*)d_in[7];
    const float* scale = (const float*)d_in[8];
    float* out = (float*)d_out;

    dim3 ggrid(ROWS / 64, (DOUT + 63) / 64, 3);
    gemm_qkv<<<ggrid, 256>>>(query, source, Wq, bq, Wk, bk, Wv, bv);

    int lift_warps = 3 * ROWS * HH;            // 98304
    lift_kernel<<<lift_warps * 32 / 256, 256>>>(scale);

    attn_kernel<<<dim3(NN / 64, BHN), 64>>>();

    centroid_kernel<<<ROWS * 32 / 256, 256>>>(out);
}

// round 6
// speedup vs baseline: 2.8925x; 1.6833x over previous
#include <cuda_runtime.h>
#include <cuda_bf16.h>
#include <cstdint>

// Problem constants
#define BB 2
#define NN 2048
#define HH 8
#define EE 512
#define DOUT 504          // H * 63
#define DD 64             // lifted dim
#define ROWS 4096         // B*N
#define BHN (BB*HH)       // 16

typedef unsigned long long u64;
typedef uint32_t u32;

// ---------------- packed f32x2 helpers (sm_103a FFMA2 path) -----------------
__device__ __forceinline__ u64 fma2(u64 a, u64 b, u64 c) {
    u64 d; asm("fma.rn.f32x2 %0, %1, %2, %3;" : "=l"(d) : "l"(a), "l"(b), "l"(c));
    return d;
}
__device__ __forceinline__ u64 pack2(float lo, float hi) {
    u64 d; asm("mov.b64 %0, {%1, %2};" : "=l"(d) : "f"(lo), "f"(hi));
    return d;
}
__device__ __forceinline__ void unpack2(u64 v, float& lo, float& hi) {
    asm("mov.b64 {%0, %1}, %2;" : "=f"(lo), "=f"(hi) : "l"(v));
}
__device__ __forceinline__ u32 f2tf32(float f) {
    u32 r; asm("cvt.rna.tf32.f32 %0, %1;" : "=r"(r) : "f"(f)); return r;
}
__device__ __forceinline__ float tf32r(float f) { return __uint_as_float(f2tf32(f)); }
__device__ __forceinline__ void tf32split(float x, float& hi, float& lo) {
    hi = tf32r(x);
    lo = tf32r(x - hi);
}

// ---------------- scratch (device globals; no allocation allowed) ----------
__device__ float g_raw[3 * ROWS * DOUT];        // raw projections q,k,v
// tf32 hi/lo splits, layout [bh][n][64]
__device__ float g_qh[BHN * NN * DD], g_ql[BHN * NN * DD];
__device__ float g_kh[BHN * NN * DD], g_kl[BHN * NN * DD];
__device__ float g_vh[BHN * NN * DD], g_vl[BHN * NN * DD];
__device__ float g_ave[ROWS * HH * DD];         // attention output per head

// ---------------- Kernel 1: QKV projection GEMM (k-major smem + FFMA2) ------
__global__ void __launch_bounds__(256) gemm_qkv(
    const float* __restrict__ Aq, const float* __restrict__ As,
    const float* __restrict__ Wq, const float* __restrict__ bq,
    const float* __restrict__ Wk, const float* __restrict__ bk,
    const float* __restrict__ Wv, const float* __restrict__ bv)
{
    int z = blockIdx.z;
    const float* A = (z == 0) ? Aq : As;
    const float* W = (z == 0) ? Wq : (z == 1 ? Wk : Wv);
    const float* bias = (z == 0) ? bq : (z == 1 ? bk : bv);
    float* out = g_raw + (size_t)z * ROWS * DOUT;

    __shared__ float a_s[16][72];
    __shared__ float w_s[16][72];

    int tid = threadIdx.x;
    int tx = tid & 15, ty = tid >> 4;
    int rowTile = blockIdx.x * 64;
    int colTile = blockIdx.y * 64;

    u64 accp[4][2];
#pragma unroll
    for (int i = 0; i < 4; i++) { accp[i][0] = 0ull; accp[i][1] = 0ull; }

    int lrow = tid >> 2;
    int lk4 = (tid & 3) * 4;

    for (int k0 = 0; k0 < EE; k0 += 16) {
        float4 av = *(const float4*)(A + (size_t)(rowTile + lrow) * EE + k0 + lk4);
        int wcol = colTile + lrow;
        float4 wv = make_float4(0.f, 0.f, 0.f, 0.f);
        if (wcol < DOUT) wv = *(const float4*)(W + (size_t)wcol * EE + k0 + lk4);
        __syncthreads();
        a_s[lk4 + 0][lrow] = av.x;  a_s[lk4 + 1][lrow] = av.y;
        a_s[lk4 + 2][lrow] = av.z;  a_s[lk4 + 3][lrow] = av.w;
        w_s[lk4 + 0][lrow] = wv.x;  w_s[lk4 + 1][lrow] = wv.y;
        w_s[lk4 + 2][lrow] = wv.z;  w_s[lk4 + 3][lrow] = wv.w;
        __syncthreads();
#pragma unroll
        for (int kk = 0; kk < 16; kk++) {
            float4 af = *(const float4*)&a_s[kk][ty * 4];
            ulonglong2 wp = *(const ulonglong2*)&w_s[kk][tx * 4];
            u64 ad0 = pack2(af.x, af.x);
            u64 ad1 = pack2(af.y, af.y);
            u64 ad2 = pack2(af.z, af.z);
            u64 ad3 = pack2(af.w, af.w);
            accp[0][0] = fma2(ad0, wp.x, accp[0][0]);
            accp[0][1] = fma2(ad0, wp.y, accp[0][1]);
            accp[1][0] = fma2(ad1, wp.x, accp[1][0]);
            accp[1][1] = fma2(ad1, wp.y, accp[1][1]);
            accp[2][0] = fma2(ad2, wp.x, accp[2][0]);
            accp[2][1] = fma2(ad2, wp.y, accp[2][1]);
            accp[3][0] = fma2(ad3, wp.x, accp[3][0]);
            accp[3][1] = fma2(ad3, wp.y, accp[3][1]);
        }
    }

#pragma unroll
    for (int i = 0; i < 4; i++) {
        int r = rowTile + ty * 4 + i;
        float c0, c1, c2, c3;
        unpack2(accp[i][0], c0, c1);
        unpack2(accp[i][1], c2, c3);
        float vals[4] = {c0, c1, c2, c3};
#pragma unroll
        for (int j = 0; j < 4; j++) {
            int c = colTile + tx * 4 + j;
            if (c < DOUT) out[(size_t)r * DOUT + c] = vals[j] + bias[c];
        }
    }
}

// ---------------- Kernel 2: hyperboloid lift + tf32 hi/lo split -------------
// warp per (z,row,head). q: negate time, fold 2/scale.
__global__ void __launch_bounds__(256) lift_kernel(const float* __restrict__ scale_ptr)
{
    int w = (blockIdx.x * blockDim.x + threadIdx.x) >> 5;
    int lane = threadIdx.x & 31;
    int z = w / (ROWS * HH);
    int rem = w - z * (ROWS * HH);
    int r = rem >> 3;
    int h = rem & 7;
    const float* x = g_raw + (size_t)z * ROWS * DOUT + (size_t)r * DOUT + h * 63;
    float xa = (lane > 0) ? x[lane - 1] : 0.0f;
    float xb = x[lane + 31];
    float ss = xa * xa + xb * xb;
#pragma unroll
    for (int o = 16; o; o >>= 1) ss += __shfl_xor_sync(0xffffffffu, ss, o);
    float t = sqrtf(ss + 1.0f);

    int b = r >> 11, n = r & (NN - 1);
    int bh = b * HH + h;
    float w0 = (lane == 0) ? t : xa;
    float w1 = xb;
    float *dh, *dl;
    if (z == 0) {
        float sc = 2.0f / scale_ptr[0];
        if (lane == 0) w0 = -t;
        w0 *= sc; w1 *= sc;
        dh = g_qh; dl = g_ql;
    } else if (z == 1) {
        dh = g_kh; dl = g_kl;
    } else {
        dh = g_vh; dl = g_vl;
    }
    size_t base = ((size_t)bh * NN + n) * DD;
    float h0, l0, h1, l1;
    tf32split(w0, h0, l0);
    tf32split(w1, h1, l1);
    dh[base + lane] = h0;        dl[base + lane] = l0;
    dh[base + lane + 32] = h1;   dl[base + lane + 32] = l1;
}

// ---------------- Kernel 3: mma.sync tf32 flash attention -------------------
// block = 256 threads (8 warps), 128 queries/block (M=16 per warp).
// Key tiles of 64, double-buffered via cp.async. 3xTF32 QK^T, 2xTF32 (split-V) PV.
// No online max: hyperboloid guarantees logits in [~-2.5, -0.088].

#define QT 128
#define KT 64
#define NTILES 32          // NN / KT

// smem layout (floats)
#define KH_OFF 0
#define KH_BUF (64 * 68)                 // 4352
#define KL_OFF (2 * KH_BUF)              // 8704
#define VH_OFF (4 * KH_BUF)              // 17408
#define VH_BUF (64 * 72)                 // 4608
#define VL_OFF (VH_OFF + 2 * VH_BUF)     // 26624
#define P_OFF  (VL_OFF + 2 * VH_BUF)     // 35840
#define SM_FLOATS (P_OFF + 8 * 16 * 68)  // 44544
#define SM_BYTES (SM_FLOATS * 4)         // 178176

__device__ __forceinline__ void cpa16(u32 dst, const float* src) {
    asm volatile("cp.async.cg.shared.global [%0], [%1], 16;" :: "r"(dst), "l"(src));
}
__device__ __forceinline__ void cpa_commit() {
    asm volatile("cp.async.commit_group;" ::: "memory");
}
__device__ __forceinline__ void mma8(float* d, const u32* a, u32 b0, u32 b1) {
    asm volatile("mma.sync.aligned.m16n8k8.row.col.f32.tf32.tf32.f32 "
        "{%0,%1,%2,%3}, {%4,%5,%6,%7}, {%8,%9}, {%0,%1,%2,%3};"
        : "+f"(d[0]), "+f"(d[1]), "+f"(d[2]), "+f"(d[3])
        : "r"(a[0]), "r"(a[1]), "r"(a[2]), "r"(a[3]), "r"(b0), "r"(b1));
}

__global__ void __launch_bounds__(256, 1) attn_mma()
{
    extern __shared__ float sm[];
    u32 smb = (u32)__cvta_generic_to_shared(sm);

    const int tid = threadIdx.x;
    const int wid = tid >> 5;
    const int lane = tid & 31;
    const int g = lane >> 2;       // groupID
    const int t4 = lane & 3;       // threadID_in_group
    const int qt = blockIdx.x;
    const int bh = blockIdx.y;
    const int n0 = qt * QT;
    const int b = bh >> 3, h = bh & 7;

    // ---- persistent Q A-fragments (hi & lo), M=16 rows per warp ----
    u32 AH[8][4], AL[8][4];
    {
        const float* qh = g_qh + ((size_t)bh * NN + n0 + wid * 16) * DD;
        const float* ql = g_ql + ((size_t)bh * NN + n0 + wid * 16) * DD;
#pragma unroll
        for (int kk = 0; kk < 8; kk++) {
            int c = kk * 8 + t4;
            AH[kk][0] = __float_as_uint(qh[g * DD + c]);
            AH[kk][1] = __float_as_uint(qh[(g + 8) * DD + c]);
            AH[kk][2] = __float_as_uint(qh[g * DD + c + 4]);
            AH[kk][3] = __float_as_uint(qh[(g + 8) * DD + c + 4]);
            AL[kk][0] = __float_as_uint(ql[g * DD + c]);
            AL[kk][1] = __float_as_uint(ql[(g + 8) * DD + c]);
            AL[kk][2] = __float_as_uint(ql[g * DD + c + 4]);
            AL[kk][3] = __float_as_uint(ql[(g + 8) * DD + c + 4]);
        }
    }

    float O[8][4];
#pragma unroll
    for (int j = 0; j < 8; j++)
#pragma unroll
        for (int r = 0; r < 4; r++) O[j][r] = 0.f;
    float lac0 = 0.f, lac1 = 0.f;

    const float* khg = g_kh + (size_t)bh * NN * DD;
    const float* klg = g_kl + (size_t)bh * NN * DD;
    const float* vhg = g_vh + (size_t)bh * NN * DD;
    const float* vlg = g_vl + (size_t)bh * NN * DD;

    // tile loader: 64 rows x 64 floats per array, 4 arrays
    auto issue = [&](int tile, int buf) {
#pragma unroll
        for (int j = 0; j < 4; j++) {
            int idx = j * 256 + tid;
            int row = idx >> 4;
            int cg = (idx & 15) << 2;
            size_t go = (size_t)(tile * KT + row) * DD + cg;
            cpa16(smb + (KH_OFF + buf * KH_BUF + row * 68 + cg) * 4, khg + go);
            cpa16(smb + (KL_OFF + buf * KH_BUF + row * 68 + cg) * 4, klg + go);
            cpa16(smb + (VH_OFF + buf * VH_BUF + row * 72 + cg) * 4, vhg + go);
            cpa16(smb + (VL_OFF + buf * VH_BUF + row * 72 + cg) * 4, vlg + go);
        }
        cpa_commit();
    };

    issue(0, 0);
    issue(1, 1);

    float* pw = sm + P_OFF + wid * (16 * 68);

    for (int t = 0; t < NTILES; t++) {
        if (t + 1 < NTILES) {
            asm volatile("cp.async.wait_group 1;" ::: "memory");
        } else {
            asm volatile("cp.async.wait_group 0;" ::: "memory");
        }
        __syncthreads();

        const int buf = t & 1;
        const float* kh_s = sm + KH_OFF + buf * KH_BUF;
        const float* kl_s = sm + KL_OFF + buf * KH_BUF;
        const float* vh_s = sm + VH_OFF + buf * VH_BUF;
        const float* vl_s = sm + VL_OFF + buf * VH_BUF;

        // ---- S = Q K^T  (3xTF32) ----
        float S[8][4];
#pragma unroll
        for (int j = 0; j < 8; j++)
#pragma unroll
            for (int r = 0; r < 4; r++) S[j][r] = 0.f;

#pragma unroll
        for (int kk = 0; kk < 8; kk++) {
            int kc = kk * 8 + t4;
#pragma unroll
            for (int j = 0; j < 8; j++) {
                int krow = j * 8 + g;
                u32 b0 = __float_as_uint(kh_s[krow * 68 + kc]);
                u32 b1 = __float_as_uint(kh_s[krow * 68 + kc + 4]);
                u32 c0 = __float_as_uint(kl_s[krow * 68 + kc]);
                u32 c1 = __float_as_uint(kl_s[krow * 68 + kc + 4]);
                mma8(S[j], AH[kk], b0, b1);
                mma8(S[j], AH[kk], c0, c1);
                mma8(S[j], AL[kk], b0, b1);
            }
        }

        // ---- exp (no max needed: logits <= -2/scale < 0, bounded below) ----
#pragma unroll
        for (int j = 0; j < 8; j++) {
            float p0 = __expf(S[j][0]);
            float p1 = __expf(S[j][1]);
            float p2 = __expf(S[j][2]);
            float p3 = __expf(S[j][3]);
            lac0 += p0 + p1;
            lac1 += p2 + p3;
            int col = j * 8 + 2 * t4;
            *(float2*)&pw[g * 68 + col] = make_float2(tf32r(p0), tf32r(p1));
            *(float2*)&pw[(g + 8) * 68 + col] = make_float2(tf32r(p2), tf32r(p3));
        }
        __syncwarp();

        // ---- O += P V  (2xTF32: split V) ----
#pragma unroll
        for (int kk = 0; kk < 8; kk++) {
            int kc = kk * 8 + t4;
            u32 A[4];
            A[0] = __float_as_uint(pw[g * 68 + kc]);
            A[1] = __float_as_uint(pw[(g + 8) * 68 + kc]);
            A[2] = __float_as_uint(pw[g * 68 + kc + 4]);
            A[3] = __float_as_uint(pw[(g + 8) * 68 + kc + 4]);
            int vrow = kk * 8 + t4;
#pragma unroll
            for (int j = 0; j < 8; j++) {
                int vcol = j * 8 + g;
                u32 b0 = __float_as_uint(vh_s[vrow * 72 + vcol]);
                u32 b1 = __float_as_uint(vh_s[(vrow + 4) * 72 + vcol]);
                u32 c0 = __float_as_uint(vl_s[vrow * 72 + vcol]);
                u32 c1 = __float_as_uint(vl_s[(vrow + 4) * 72 + vcol]);
                mma8(O[j], A, b0, b1);
                mma8(O[j], A, c0, c1);
            }
        }
        __syncwarp();

        __syncthreads();
        if (t + 2 < NTILES) issue(t + 2, buf);
    }

    // ---- epilogue: reduce l across the 4 lanes sharing each row ----
    lac0 += __shfl_xor_sync(0xffffffffu, lac0, 1);
    lac0 += __shfl_xor_sync(0xffffffffu, lac0, 2);
    lac1 += __shfl_xor_sync(0xffffffffu, lac1, 1);
    lac1 += __shfl_xor_sync(0xffffffffu, lac1, 2);
    float inv0 = 1.0f / lac0;
    float inv1 = 1.0f / lac1;

    int nq0 = n0 + wid * 16 + g;
    int nq1 = nq0 + 8;
    float* d0 = g_ave + (((size_t)(b * NN + nq0)) * HH + h) * DD;
    float* d1 = g_ave + (((size_t)(b * NN + nq1)) * HH + h) * DD;
#pragma unroll
    for (int j = 0; j < 8; j++) {
        int dcol = j * 8 + 2 * t4;
        *(float2*)&d0[dcol] = make_float2(O[j][0] * inv0, O[j][1] * inv0);
        *(float2*)&d1[dcol] = make_float2(O[j][2] * inv1, O[j][3] * inv1);
    }
}

// ---------------- Kernel 4: centroid epilogue -------------------------------
__device__ __forceinline__ float warp_sum(float v)
{
#pragma unroll
    for (int o = 16; o; o >>= 1) v += __shfl_xor_sync(0xffffffffu, v, o);
    return v;
}

__global__ void __launch_bounds__(256) centroid_kernel(float* __restrict__ out)
{
    int w = (blockIdx.x * blockDim.x + threadIdx.x) >> 5;
    int lane = threadIdx.x & 31;
    float m0 = 0.f, m1 = 0.f;
#pragma unroll
    for (int h = 0; h < HH; h++) {
        const float* a = g_ave + ((size_t)w * HH + h) * DD;
        float a0 = a[lane], a1 = a[lane + 32];
        float part = a0 * a0 + a1 * a1;
        if (lane == 0) part -= 2.0f * a0 * a0;
        float inner = warp_sum(part);
        float denom = sqrtf(fmaxf(fabsf(inner), 1e-8f));
        float inv = 1.0f / denom;
        m0 += a0 * inv; m1 += a1 * inv;
    }
    m0 *= (1.0f / HH); m1 *= (1.0f / HH);
    float part = m0 * m0 + m1 * m1;
    if (lane == 0) part -= 2.0f * m0 * m0;
    float inner = warp_sum(part);
    float denom = sqrtf(fmaxf(fabsf(inner), 1e-8f));
    float inv = 1.0f / denom;
    out[(size_t)w * DD + lane] = m0 * inv;
    out[(size_t)w * DD + lane + 32] = m1 * inv;
}

// ---------------- launch -----------------------------------------------------
extern "C" void kernel_launch(void* const* d_in, const int* in_sizes, int n_in,
                              void* d_out, int out_size)
{
    const float* query  = (const float*)d_in[0];
    const float* source = (const float*)d_in[1];
    const float* Wq = (const float*)d_in[2];
    const float* bq = (const float*)d_in[3];
    const float* Wk = (const float*)d_in[4];
    const float* bk = (const float*)d_in[5];
    const float* Wv = (const float*)d_in[6];
    const float* bv = (const float*)d_in[7];
    const float* scale = (const float*)d_in[8];
    float* out = (float*)d_out;

    cudaFuncSetAttribute(attn_mma, cudaFuncAttributeMaxDynamicSharedMemorySize, SM_BYTES);

    dim3 ggrid(ROWS / 64, (DOUT + 63) / 64, 3);
    gemm_qkv<<<ggrid, 256>>>(query, source, Wq, bq, Wk, bk, Wv, bv);

    int lift_warps = 3 * ROWS * HH;
    lift_kernel<<<lift_warps * 32 / 256, 256>>>(scale);

    attn_mma<<<dim3(NN / QT, BHN), 256, SM_BYTES>>>();

    centroid_kernel<<<ROWS * 32 / 256, 256>>>(out);
}

// round 7
// speedup vs baseline: 3.9644x; 1.3706x over previous
#include <cuda_runtime.h>
#include <cuda_bf16.h>
#include <cstdint>

// Problem constants
#define BB 2
#define NN 2048
#define HH 8
#define EE 512
#define DOUT 504          // H * 63
#define DD 64             // lifted dim
#define ROWS 4096         // B*N
#define BHN (BB*HH)       // 16

typedef unsigned long long u64;
typedef uint32_t u32;

__device__ __forceinline__ u32 f2tf32(float f) {
    u32 r; asm("cvt.rna.tf32.f32 %0, %1;" : "=r"(r) : "f"(f)); return r;
}
__device__ __forceinline__ float tf32r(float f) { return __uint_as_float(f2tf32(f)); }
__device__ __forceinline__ void tf32split(float x, float& hi, float& lo) {
    hi = tf32r(x);
    lo = tf32r(x - hi);
}

// ---------------- scratch (device globals; no allocation allowed) ----------
__device__ float g_raw[3 * ROWS * DOUT];          // raw projections q,k,v
__device__ float g_ah[2 * ROWS * EE];             // input splits (query, source)
__device__ float g_al[2 * ROWS * EE];
__device__ float g_wh[3 * EE * EE];               // W splits, padded to 512 rows
__device__ float g_wl[3 * EE * EE];
__device__ float g_qh[BHN * NN * DD];             // lifted q (sign+scale folded, tf32)
__device__ float g_kh[BHN * NN * DD], g_kl[BHN * NN * DD];
__device__ float g_vh[BHN * NN * DD];             // lifted v (tf32)
__device__ float g_ave[ROWS * HH * DD];           // attention output per head

// ---------------- Kernel 0a: split inputs to tf32 hi/lo ---------------------
__global__ void __launch_bounds__(256) split_inputs(
    const float* __restrict__ q, const float* __restrict__ s)
{
    int i = blockIdx.x * blockDim.x + threadIdx.x;   // 0 .. 2*ROWS*EE-1
    const int half = ROWS * EE;
    float v = (i < half) ? q[i] : s[i - half];
    float hi, lo;
    tf32split(v, hi, lo);
    g_ah[i] = hi;
    g_al[i] = lo;
}

// ---------------- Kernel 0b: split weights (pad rows 504..511 with 0) -------
__global__ void __launch_bounds__(256) split_w(
    const float* __restrict__ Wq, const float* __restrict__ Wk,
    const float* __restrict__ Wv)
{
    int i = blockIdx.x * blockDim.x + threadIdx.x;   // 0 .. 3*512*512-1
    int z = i / (EE * EE);
    int rem = i - z * (EE * EE);
    int row = rem >> 9;
    int col = rem & 511;
    const float* W = (z == 0) ? Wq : (z == 1 ? Wk : Wv);
    float v = (row < DOUT) ? W[row * EE + col] : 0.0f;
    float hi, lo;
    tf32split(v, hi, lo);
    g_wh[i] = hi;
    g_wl[i] = lo;
}

// ---------------- Kernel 1: QKV projection GEMM (mma.sync tf32 3x) ---------
// out[r][c] = sum_k A[r][k] * W[c][k] + b[c]
// Block: 256 thr (8 warps: 4 along M x 2 along N), tile M=128 N=64, K-chunk 32.
#define GK 32              // k-chunk
#define GKS 36             // padded k stride
// smem float offsets (2 stages)
#define GA_H 0
#define GA_STG (128 * GKS)           // 4608
#define GA_L (2 * GA_STG)            // 9216
#define GW_H (4 * GA_STG)            // 18432
#define GW_STG (64 * GKS)            // 2304
#define GW_L (GW_H + 2 * GW_STG)     // 23040
#define GSM_FLOATS (GW_L + 2 * GW_STG)   // 27648
#define GSM_BYTES (GSM_FLOATS * 4)       // 110592

__device__ __forceinline__ void cpa16(u32 dst, const float* src) {
    asm volatile("cp.async.cg.shared.global [%0], [%1], 16;" :: "r"(dst), "l"(src));
}
__device__ __forceinline__ void cpa_commit() {
    asm volatile("cp.async.commit_group;" ::: "memory");
}
__device__ __forceinline__ void mma8(float* d, const u32* a, u32 b0, u32 b1) {
    asm volatile("mma.sync.aligned.m16n8k8.row.col.f32.tf32.tf32.f32 "
        "{%0,%1,%2,%3}, {%4,%5,%6,%7}, {%8,%9}, {%0,%1,%2,%3};"
        : "+f"(d[0]), "+f"(d[1]), "+f"(d[2]), "+f"(d[3])
        : "r"(a[0]), "r"(a[1]), "r"(a[2]), "r"(a[3]), "r"(b0), "r"(b1));
}

__global__ void __launch_bounds__(256, 1) gemm_tc(
    const float* __restrict__ bq, const float* __restrict__ bk,
    const float* __restrict__ bv)
{
    extern __shared__ float sm[];
    u32 smb = (u32)__cvta_generic_to_shared(sm);

    const int tid = threadIdx.x;
    const int wid = tid >> 5;
    const int lane = tid & 31;
    const int g = lane >> 2;
    const int t4 = lane & 3;
    const int wm = wid & 3;          // 0..3 (M)
    const int wn = wid >> 2;         // 0..1 (N)

    const int mTile = blockIdx.x * 128;
    const int nTile = blockIdx.y * 64;
    const int z = blockIdx.z;

    const float* ah = g_ah + (size_t)(z ? 1 : 0) * ROWS * EE;
    const float* al = g_al + (size_t)(z ? 1 : 0) * ROWS * EE;
    const float* wh = g_wh + (size_t)z * EE * EE;
    const float* wl = g_wl + (size_t)z * EE * EE;
    const float* bias = (z == 0) ? bq : (z == 1 ? bk : bv);
    float* out = g_raw + (size_t)z * ROWS * DOUT;

    float acc[2][4][4];
#pragma unroll
    for (int j = 0; j < 2; j++)
#pragma unroll
        for (int n = 0; n < 4; n++)
#pragma unroll
            for (int r = 0; r < 4; r++) acc[j][n][r] = 0.f;

    auto issue = [&](int chunk, int stg) {
        int k0 = chunk * GK;
        // A: 128 rows x 32k, hi+lo : 1024 float4 each
#pragma unroll
        for (int it = 0; it < 4; it++) {
            int idx = it * 256 + tid;
            int row = idx >> 3;
            int c4 = (idx & 7) << 2;
            size_t go = (size_t)(mTile + row) * EE + k0 + c4;
            u32 so = (row * GKS + c4) * 4;
            cpa16(smb + (GA_H + stg * GA_STG) * 4 + so, ah + go);
            cpa16(smb + (GA_L + stg * GA_STG) * 4 + so, al + go);
        }
        // W: 64 rows x 32k, hi+lo : 512 float4 each
#pragma unroll
        for (int it = 0; it < 2; it++) {
            int idx = it * 256 + tid;
            int row = idx >> 3;
            int c4 = (idx & 7) << 2;
            size_t go = (size_t)(nTile + row) * EE + k0 + c4;
            u32 so = (row * GKS + c4) * 4;
            cpa16(smb + (GW_H + stg * GW_STG) * 4 + so, wh + go);
            cpa16(smb + (GW_L + stg * GW_STG) * 4 + so, wl + go);
        }
        cpa_commit();
    };

    issue(0, 0);
    issue(1, 1);

    const int NCH = EE / GK;   // 16
    for (int t = 0; t < NCH; t++) {
        if (t + 1 < NCH) asm volatile("cp.async.wait_group 1;" ::: "memory");
        else             asm volatile("cp.async.wait_group 0;" ::: "memory");
        __syncthreads();

        const int stg = t & 1;
        const float* a_h = sm + GA_H + stg * GA_STG;
        const float* a_l = sm + GA_L + stg * GA_STG;
        const float* w_h = sm + GW_H + stg * GW_STG;
        const float* w_l = sm + GW_L + stg * GW_STG;

#pragma unroll
        for (int kk = 0; kk < 4; kk++) {
            int kc = kk * 8 + t4;
            u32 AH[2][4], AL[2][4];
#pragma unroll
            for (int j = 0; j < 2; j++) {
                int r0 = wm * 32 + j * 16 + g;
                AH[j][0] = __float_as_uint(a_h[r0 * GKS + kc]);
                AH[j][1] = __float_as_uint(a_h[(r0 + 8) * GKS + kc]);
                AH[j][2] = __float_as_uint(a_h[r0 * GKS + kc + 4]);
                AH[j][3] = __float_as_uint(a_h[(r0 + 8) * GKS + kc + 4]);
                AL[j][0] = __float_as_uint(a_l[r0 * GKS + kc]);
                AL[j][1] = __float_as_uint(a_l[(r0 + 8) * GKS + kc]);
                AL[j][2] = __float_as_uint(a_l[r0 * GKS + kc + 4]);
                AL[j][3] = __float_as_uint(a_l[(r0 + 8) * GKS + kc + 4]);
            }
#pragma unroll
            for (int n = 0; n < 4; n++) {
                int nr = wn * 32 + n * 8 + g;
                u32 bh0 = __float_as_uint(w_h[nr * GKS + kc]);
                u32 bh1 = __float_as_uint(w_h[nr * GKS + kc + 4]);
                u32 bl0 = __float_as_uint(w_l[nr * GKS + kc]);
                u32 bl1 = __float_as_uint(w_l[nr * GKS + kc + 4]);
#pragma unroll
                for (int j = 0; j < 2; j++) {
                    mma8(acc[j][n], AH[j], bh0, bh1);
                    mma8(acc[j][n], AH[j], bl0, bl1);
                    mma8(acc[j][n], AL[j], bh0, bh1);
                }
            }
        }
        __syncthreads();
        if (t + 2 < NCH) issue(t + 2, stg);
    }

    // epilogue: D[row g][col 2t4], rows j*16+{g,g+8}
#pragma unroll
    for (int j = 0; j < 2; j++) {
#pragma unroll
        for (int n = 0; n < 4; n++) {
            int c = nTile + wn * 32 + n * 8 + 2 * t4;
            if (c < DOUT) {
                float b0 = bias[c], b1 = bias[c + 1];
                int r0 = mTile + wm * 32 + j * 16 + g;
                *(float2*)&out[(size_t)r0 * DOUT + c] =
                    make_float2(acc[j][n][0] + b0, acc[j][n][1] + b1);
                *(float2*)&out[(size_t)(r0 + 8) * DOUT + c] =
                    make_float2(acc[j][n][2] + b0, acc[j][n][3] + b1);
            }
        }
    }
}

// ---------------- Kernel 2: hyperboloid lift --------------------------------
// warp per (z,row,head). q: negate time, fold 2/scale, tf32 (hi only).
// k: tf32 hi/lo split. v: tf32 hi only.
__global__ void __launch_bounds__(256) lift_kernel(const float* __restrict__ scale_ptr)
{
    int w = (blockIdx.x * blockDim.x + threadIdx.x) >> 5;
    int lane = threadIdx.x & 31;
    int z = w / (ROWS * HH);
    int rem = w - z * (ROWS * HH);
    int r = rem >> 3;
    int h = rem & 7;
    const float* x = g_raw + (size_t)z * ROWS * DOUT + (size_t)r * DOUT + h * 63;
    float xa = (lane > 0) ? x[lane - 1] : 0.0f;
    float xb = x[lane + 31];
    float ss = xa * xa + xb * xb;
#pragma unroll
    for (int o = 16; o; o >>= 1) ss += __shfl_xor_sync(0xffffffffu, ss, o);
    float t = sqrtf(ss + 1.0f);

    int b = r >> 11, n = r & (NN - 1);
    int bh = b * HH + h;
    size_t base = ((size_t)bh * NN + n) * DD;
    float w0 = (lane == 0) ? t : xa;
    float w1 = xb;
    if (z == 0) {
        float sc = 2.0f / scale_ptr[0];
        if (lane == 0) w0 = -t;
        g_qh[base + lane] = tf32r(w0 * sc);
        g_qh[base + lane + 32] = tf32r(w1 * sc);
    } else if (z == 1) {
        float h0, l0, h1, l1;
        tf32split(w0, h0, l0);
        tf32split(w1, h1, l1);
        g_kh[base + lane] = h0;        g_kl[base + lane] = l0;
        g_kh[base + lane + 32] = h1;   g_kl[base + lane + 32] = l1;
    } else {
        g_vh[base + lane] = tf32r(w0);
        g_vh[base + lane + 32] = tf32r(w1);
    }
}

// ---------------- Kernel 3: mma.sync tf32 flash attention -------------------
// block = 256 threads (8 warps), 128 queries/block (M=16 per warp).
// Key tiles of 64, double-buffered cp.async. QK: q_hi x (k_hi + k_lo) = 2 MMA.
// PV: P x v_hi = 1 MMA. No online max (hyperboloid: logits in [~-2.5, -0.088]).

#define QT 128
#define KT 64
#define NTILES 32          // NN / KT

// smem layout (floats)
#define KH_OFF 0
#define KH_BUF (64 * 68)                 // 4352
#define KL_OFF (2 * KH_BUF)              // 8704
#define VH_OFF (4 * KH_BUF)              // 17408
#define VH_BUF (64 * 72)                 // 4608
#define P_OFF  (VH_OFF + 2 * VH_BUF)     // 26624
#define SM_FLOATS (P_OFF + 8 * 16 * 68)  // 35328
#define SM_BYTES (SM_FLOATS * 4)         // 141312

__global__ void __launch_bounds__(256, 1) attn_mma()
{
    extern __shared__ float sm[];
    u32 smb = (u32)__cvta_generic_to_shared(sm);

    const int tid = threadIdx.x;
    const int wid = tid >> 5;
    const int lane = tid & 31;
    const int g = lane >> 2;       // groupID
    const int t4 = lane & 3;       // threadID_in_group
    const int qt = blockIdx.x;
    const int bh = blockIdx.y;
    const int n0 = qt * QT;
    const int b = bh >> 3, h = bh & 7;

    // ---- persistent Q A-fragments (hi only), M=16 rows per warp ----
    u32 AH[8][4];
    {
        const float* qh = g_qh + ((size_t)bh * NN + n0 + wid * 16) * DD;
#pragma unroll
        for (int kk = 0; kk < 8; kk++) {
            int c = kk * 8 + t4;
            AH[kk][0] = __float_as_uint(qh[g * DD + c]);
            AH[kk][1] = __float_as_uint(qh[(g + 8) * DD + c]);
            AH[kk][2] = __float_as_uint(qh[g * DD + c + 4]);
            AH[kk][3] = __float_as_uint(qh[(g + 8) * DD + c + 4]);
        }
    }

    float O[8][4];
#pragma unroll
    for (int j = 0; j < 8; j++)
#pragma unroll
        for (int r = 0; r < 4; r++) O[j][r] = 0.f;
    float lac0 = 0.f, lac1 = 0.f;

    const float* khg = g_kh + (size_t)bh * NN * DD;
    const float* klg = g_kl + (size_t)bh * NN * DD;
    const float* vhg = g_vh + (size_t)bh * NN * DD;

    auto issue = [&](int tile, int buf) {
#pragma unroll
        for (int j = 0; j < 4; j++) {
            int idx = j * 256 + tid;
            int row = idx >> 4;
            int cg = (idx & 15) << 2;
            size_t go = (size_t)(tile * KT + row) * DD + cg;
            cpa16(smb + (KH_OFF + buf * KH_BUF + row * 68 + cg) * 4, khg + go);
            cpa16(smb + (KL_OFF + buf * KH_BUF + row * 68 + cg) * 4, klg + go);
            cpa16(smb + (VH_OFF + buf * VH_BUF + row * 72 + cg) * 4, vhg + go);
        }
        cpa_commit();
    };

    issue(0, 0);
    issue(1, 1);

    float* pw = sm + P_OFF + wid * (16 * 68);

    for (int t = 0; t < NTILES; t++) {
        if (t + 1 < NTILES) asm volatile("cp.async.wait_group 1;" ::: "memory");
        else                asm volatile("cp.async.wait_group 0;" ::: "memory");
        __syncthreads();

        const int buf = t & 1;
        const float* kh_s = sm + KH_OFF + buf * KH_BUF;
        const float* kl_s = sm + KL_OFF + buf * KH_BUF;
        const float* vh_s = sm + VH_OFF + buf * VH_BUF;

        // ---- S = Q K^T  (q_hi x k_hi + q_hi x k_lo) ----
        float S[8][4];
#pragma unroll
        for (int j = 0; j < 8; j++)
#pragma unroll
            for (int r = 0; r < 4; r++) S[j][r] = 0.f;

#pragma unroll
        for (int kk = 0; kk < 8; kk++) {
            int kc = kk * 8 + t4;
#pragma unroll
            for (int j = 0; j < 8; j++) {
                int krow = j * 8 + g;
                u32 b0 = __float_as_uint(kh_s[krow * 68 + kc]);
                u32 b1 = __float_as_uint(kh_s[krow * 68 + kc + 4]);
                u32 c0 = __float_as_uint(kl_s[krow * 68 + kc]);
                u32 c1 = __float_as_uint(kl_s[krow * 68 + kc + 4]);
                mma8(S[j], AH[kk], b0, b1);
                mma8(S[j], AH[kk], c0, c1);
            }
        }

        // ---- exp (no max needed: logits bounded) ----
#pragma unroll
        for (int j = 0; j < 8; j++) {
            float p0 = __expf(S[j][0]);
            float p1 = __expf(S[j][1]);
            float p2 = __expf(S[j][2]);
            float p3 = __expf(S[j][3]);
            lac0 += p0 + p1;
            lac1 += p2 + p3;
            int col = j * 8 + 2 * t4;
            *(float2*)&pw[g * 68 + col] = make_float2(tf32r(p0), tf32r(p1));
            *(float2*)&pw[(g + 8) * 68 + col] = make_float2(tf32r(p2), tf32r(p3));
        }
        __syncwarp();

        // ---- O += P V  (v_hi only) ----
#pragma unroll
        for (int kk = 0; kk < 8; kk++) {
            int kc = kk * 8 + t4;
            u32 A[4];
            A[0] = __float_as_uint(pw[g * 68 + kc]);
            A[1] = __float_as_uint(pw[(g + 8) * 68 + kc]);
            A[2] = __float_as_uint(pw[g * 68 + kc + 4]);
            A[3] = __float_as_uint(pw[(g + 8) * 68 + kc + 4]);
            int vrow = kk * 8 + t4;
#pragma unroll
            for (int j = 0; j < 8; j++) {
                int vcol = j * 8 + g;
                u32 b0 = __float_as_uint(vh_s[vrow * 72 + vcol]);
                u32 b1 = __float_as_uint(vh_s[(vrow + 4) * 72 + vcol]);
                mma8(O[j], A, b0, b1);
            }
        }
        __syncwarp();

        __syncthreads();
        if (t + 2 < NTILES) issue(t + 2, buf);
    }

    // ---- epilogue ----
    lac0 += __shfl_xor_sync(0xffffffffu, lac0, 1);
    lac0 += __shfl_xor_sync(0xffffffffu, lac0, 2);
    lac1 += __shfl_xor_sync(0xffffffffu, lac1, 1);
    lac1 += __shfl_xor_sync(0xffffffffu, lac1, 2);
    float inv0 = 1.0f / lac0;
    float inv1 = 1.0f / lac1;

    int nq0 = n0 + wid * 16 + g;
    int nq1 = nq0 + 8;
    float* d0 = g_ave + (((size_t)(b * NN + nq0)) * HH + h) * DD;
    float* d1 = g_ave + (((size_t)(b * NN + nq1)) * HH + h) * DD;
#pragma unroll
    for (int j = 0; j < 8; j++) {
        int dcol = j * 8 + 2 * t4;
        *(float2*)&d0[dcol] = make_float2(O[j][0] * inv0, O[j][1] * inv0);
        *(float2*)&d1[dcol] = make_float2(O[j][2] * inv1, O[j][3] * inv1);
    }
}

// ---------------- Kernel 4: centroid epilogue -------------------------------
__device__ __forceinline__ float warp_sum(float v)
{
#pragma unroll
    for (int o = 16; o; o >>= 1) v += __shfl_xor_sync(0xffffffffu, v, o);
    return v;
}

__global__ void __launch_bounds__(256) centroid_kernel(float* __restrict__ out)
{
    int w = (blockIdx.x * blockDim.x + threadIdx.x) >> 5;
    int lane = threadIdx.x & 31;
    float m0 = 0.f, m1 = 0.f;
#pragma unroll
    for (int h = 0; h < HH; h++) {
        const float* a = g_ave + ((size_t)w * HH + h) * DD;
        float a0 = a[lane], a1 = a[lane + 32];
        float part = a0 * a0 + a1 * a1;
        if (lane == 0) part -= 2.0f * a0 * a0;
        float inner = warp_sum(part);
        float denom = sqrtf(fmaxf(fabsf(inner), 1e-8f));
        float inv = 1.0f / denom;
        m0 += a0 * inv; m1 += a1 * inv;
    }
    m0 *= (1.0f / HH); m1 *= (1.0f / HH);
    float part = m0 * m0 + m1 * m1;
    if (lane == 0) part -= 2.0f * m0 * m0;
    float inner = warp_sum(part);
    float denom = sqrtf(fmaxf(fabsf(inner), 1e-8f));
    float inv = 1.0f / denom;
    out[(size_t)w * DD + lane] = m0 * inv;
    out[(size_t)w * DD + lane + 32] = m1 * inv;
}

// ---------------- launch -----------------------------------------------------
extern "C" void kernel_launch(void* const* d_in, const int* in_sizes, int n_in,
                              void* d_out, int out_size)
{
    const float* query  = (const float*)d_in[0];
    const float* source = (const float*)d_in[1];
    const float* Wq = (const float*)d_in[2];
    const float* bq = (const float*)d_in[3];
    const float* Wk = (const float*)d_in[4];
    const float* bk = (const float*)d_in[5];
    const float* Wv = (const float*)d_in[6];
    const float* bv = (const float*)d_in[7];
    const float* scale = (const float*)d_in[8];
    float* out = (float*)d_out;

    cudaFuncSetAttribute(gemm_tc, cudaFuncAttributeMaxDynamicSharedMemorySize, GSM_BYTES);
    cudaFuncSetAttribute(attn_mma, cudaFuncAttributeMaxDynamicSharedMemorySize, SM_BYTES);

    split_inputs<<<2 * ROWS * EE / 256, 256>>>(query, source);
    split_w<<<3 * EE * EE / 256, 256>>>(Wq, Wk, Wv);

    gemm_tc<<<dim3(ROWS / 128, EE / 64, 3), 256, GSM_BYTES>>>(bq, bk, bv);

    int lift_warps = 3 * ROWS * HH;
    lift_kernel<<<lift_warps * 32 / 256, 256>>>(scale);

    attn_mma<<<dim3(NN / QT, BHN), 256, SM_BYTES>>>();

    centroid_kernel<<<ROWS * 32 / 256, 256>>>(out);
}

// round 8
// speedup vs baseline: 6.4586x; 1.6291x over previous
#include <cuda_runtime.h>
#include <cuda_bf16.h>
#include <cstdint>

// Problem constants
#define BB 2
#define NN 2048
#define HH 8
#define EE 512
#define DOUT 504          // H * 63
#define DD 64             // lifted dim
#define ROWS 4096         // B*N
#define BHN (BB*HH)       // 16

typedef unsigned long long u64;
typedef uint32_t u32;
typedef __nv_bfloat16 bf16;

// ---------------- scratch (device globals; no allocation allowed) ----------
__device__ float g_raw[3 * ROWS * DOUT];            // raw projections q,k,v (f32)
__device__ alignas(16) bf16 g_ah[2 * ROWS * EE];    // input splits (query, source)
__device__ alignas(16) bf16 g_al[2 * ROWS * EE];
__device__ alignas(16) bf16 g_wh[3 * EE * EE];      // W splits, rows padded to 512
__device__ alignas(16) bf16 g_wl[3 * EE * EE];
__device__ alignas(16) bf16 g_qh[BHN * NN * DD];    // lifted q (sign+scale folded)
__device__ alignas(16) bf16 g_ql[BHN * NN * DD];
__device__ alignas(16) bf16 g_kh[BHN * NN * DD];
__device__ alignas(16) bf16 g_kl[BHN * NN * DD];
__device__ alignas(16) bf16 g_vh[BHN * NN * DD];    // lifted v (hi only)
__device__ float g_ave[ROWS * HH * DD];             // attention output per head

// ---------------- helpers ----------------------------------------------------
__device__ __forceinline__ void bfsplit(float x, bf16& hi, bf16& lo) {
    hi = __float2bfloat16_rn(x);
    lo = __float2bfloat16_rn(x - __bfloat162float(hi));
}
__device__ __forceinline__ void cpa16(u32 dst, const void* src) {
    asm volatile("cp.async.cg.shared.global [%0], [%1], 16;" :: "r"(dst), "l"(src));
}
__device__ __forceinline__ void cpa_commit() {
    asm volatile("cp.async.commit_group;" ::: "memory");
}
__device__ __forceinline__ void mmabf(float* d, const u32* a, u32 b0, u32 b1) {
    asm volatile("mma.sync.aligned.m16n8k16.row.col.f32.bf16.bf16.f32 "
        "{%0,%1,%2,%3}, {%4,%5,%6,%7}, {%8,%9}, {%0,%1,%2,%3};"
        : "+f"(d[0]), "+f"(d[1]), "+f"(d[2]), "+f"(d[3])
        : "r"(a[0]), "r"(a[1]), "r"(a[2]), "r"(a[3]), "r"(b0), "r"(b1));
}
__device__ __forceinline__ void ldm4(u32* r, u32 addr) {
    asm volatile("ldmatrix.sync.aligned.m8n8.x4.shared.b16 {%0,%1,%2,%3}, [%4];"
        : "=r"(r[0]), "=r"(r[1]), "=r"(r[2]), "=r"(r[3]) : "r"(addr));
}
__device__ __forceinline__ void ldm4t(u32* r, u32 addr) {
    asm volatile("ldmatrix.sync.aligned.m8n8.x4.trans.shared.b16 {%0,%1,%2,%3}, [%4];"
        : "=r"(r[0]), "=r"(r[1]), "=r"(r[2]), "=r"(r[3]) : "r"(addr));
}

// ---------------- Kernel 0a: split inputs to bf16 hi/lo ---------------------
__global__ void __launch_bounds__(256) split_inputs(
    const float* __restrict__ q, const float* __restrict__ s)
{
    int i = (blockIdx.x * blockDim.x + threadIdx.x) * 2;
    const int half = ROWS * EE;
    float2 v = (i < half) ? *(const float2*)(q + i) : *(const float2*)(s + i - half);
    bf16 h0, l0, h1, l1;
    bfsplit(v.x, h0, l0);
    bfsplit(v.y, h1, l1);
    __nv_bfloat162 hh; hh.x = h0; hh.y = h1;
    __nv_bfloat162 ll; ll.x = l0; ll.y = l1;
    *(u32*)&g_ah[i] = *(u32*)&hh;
    *(u32*)&g_al[i] = *(u32*)&ll;
}

// ---------------- Kernel 0b: split weights (pad rows 504..511 with 0) -------
__global__ void __launch_bounds__(256) split_w(
    const float* __restrict__ Wq, const float* __restrict__ Wk,
    const float* __restrict__ Wv)
{
    int i = (blockIdx.x * blockDim.x + threadIdx.x) * 2;
    int z = i / (EE * EE);
    int rem = i - z * (EE * EE);
    int row = rem >> 9;
    int col = rem & 511;
    const float* W = (z == 0) ? Wq : (z == 1 ? Wk : Wv);
    float2 v = make_float2(0.f, 0.f);
    if (row < DOUT) v = *(const float2*)(W + (size_t)row * EE + col);
    bf16 h0, l0, h1, l1;
    bfsplit(v.x, h0, l0);
    bfsplit(v.y, h1, l1);
    __nv_bfloat162 hh; hh.x = h0; hh.y = h1;
    __nv_bfloat162 ll; ll.x = l0; ll.y = l1;
    *(u32*)&g_wh[i] = *(u32*)&hh;
    *(u32*)&g_wl[i] = *(u32*)&ll;
}

// ---------------- Kernel 1: QKV projection GEMM (bf16x3 mma + ldmatrix) -----
// out[r][c] = sum_k A[r][k]*W[c][k] + b[c]. Tile M=128 N=64 Kchunk=32, 2 stages.
#define ASTR 40                       // bf16 stride (80B rows)
#define ABUF (128 * ASTR)             // 5120
#define WBUF (64 * ASTR)              // 2560
#define GAH 0
#define GAL (2 * ABUF)                // 10240
#define GWH (4 * ABUF)                // 20480
#define GWL (GWH + 2 * WBUF)          // 25600
#define GSM_BYTES ((GWL + 2 * WBUF) * 2)   // 61440

__global__ void __launch_bounds__(256, 2) gemm_tc(
    const float* __restrict__ bq, const float* __restrict__ bk,
    const float* __restrict__ bv)
{
    extern __shared__ bf16 smbf[];
    u32 smb = (u32)__cvta_generic_to_shared(smbf);

    const int tid = threadIdx.x;
    const int wid = tid >> 5;
    const int lane = tid & 31;
    const int g = lane >> 2;
    const int t4 = lane & 3;
    const int wm = wid & 3;          // 0..3 (M)
    const int wn = wid >> 2;         // 0..1 (N)
    const int mi = lane >> 3, lr = lane & 7;
    const int a_row = (mi & 1) * 8 + lr;      // A-style ldmatrix lane row
    const int a_kb  = (mi >> 1) * 16;         // A-style k byte offset
    const int b_row = (mi >> 1) * 8 + lr;     // B-style
    const int b_kb  = (mi & 1) * 16;

    const int mTile = blockIdx.x * 128;
    const int nTile = blockIdx.y * 64;
    const int z = blockIdx.z;

    const bf16* ahg = g_ah + (size_t)(z ? 1 : 0) * ROWS * EE;
    const bf16* alg = g_al + (size_t)(z ? 1 : 0) * ROWS * EE;
    const bf16* whg = g_wh + (size_t)z * EE * EE;
    const bf16* wlg = g_wl + (size_t)z * EE * EE;
    const float* bias = (z == 0) ? bq : (z == 1 ? bk : bv);
    float* out = g_raw + (size_t)z * ROWS * DOUT;

    float acc[2][4][4];
#pragma unroll
    for (int j = 0; j < 2; j++)
#pragma unroll
        for (int n = 0; n < 4; n++)
#pragma unroll
            for (int r = 0; r < 4; r++) acc[j][n][r] = 0.f;

    auto issue = [&](int chunk, int stg) {
        int k0 = chunk * 32;
#pragma unroll
        for (int it = 0; it < 2; it++) {
            int idx = it * 256 + tid;
            int row = idx >> 2, c = idx & 3;
            size_t go = (size_t)(mTile + row) * EE + k0 + c * 8;
            u32 so = row * (ASTR * 2) + c * 16;
            cpa16(smb + (GAH + stg * ABUF) * 2 + so, ahg + go);
            cpa16(smb + (GAL + stg * ABUF) * 2 + so, alg + go);
        }
        {
            int row = tid >> 2, c = tid & 3;
            size_t go = (size_t)(nTile + row) * EE + k0 + c * 8;
            u32 so = row * (ASTR * 2) + c * 16;
            cpa16(smb + (GWH + stg * WBUF) * 2 + so, whg + go);
            cpa16(smb + (GWL + stg * WBUF) * 2 + so, wlg + go);
        }
        cpa_commit();
    };

    issue(0, 0);
    issue(1, 1);

    const int NCH = EE / 32;   // 16
    for (int t = 0; t < NCH; t++) {
        if (t + 1 < NCH) asm volatile("cp.async.wait_group 1;" ::: "memory");
        else             asm volatile("cp.async.wait_group 0;" ::: "memory");
        __syncthreads();

        const int stg = t & 1;
        u32 ahb = smb + (GAH + stg * ABUF) * 2;
        u32 alb = smb + (GAL + stg * ABUF) * 2;
        u32 whb = smb + (GWH + stg * WBUF) * 2;
        u32 wlb = smb + (GWL + stg * WBUF) * 2;

#pragma unroll
        for (int kk = 0; kk < 2; kk++) {
            u32 AH[2][4], AL[2][4];
#pragma unroll
            for (int j = 0; j < 2; j++) {
                u32 ao = (u32)(wm * 32 + j * 16 + a_row) * (ASTR * 2) + kk * 32 + a_kb;
                ldm4(AH[j], ahb + ao);
                ldm4(AL[j], alb + ao);
            }
#pragma unroll
            for (int jj = 0; jj < 2; jj++) {
                u32 WH[4], WL[4];
                u32 wo = (u32)(wn * 32 + jj * 16 + b_row) * (ASTR * 2) + kk * 32 + b_kb;
                ldm4(WH, whb + wo);
                ldm4(WL, wlb + wo);
#pragma unroll
                for (int j = 0; j < 2; j++) {
                    mmabf(acc[j][2 * jj],     AH[j], WH[0], WH[1]);
                    mmabf(acc[j][2 * jj],     AH[j], WL[0], WL[1]);
                    mmabf(acc[j][2 * jj],     AL[j], WH[0], WH[1]);
                    mmabf(acc[j][2 * jj + 1], AH[j], WH[2], WH[3]);
                    mmabf(acc[j][2 * jj + 1], AH[j], WL[2], WL[3]);
                    mmabf(acc[j][2 * jj + 1], AL[j], WH[2], WH[3]);
                }
            }
        }
        __syncthreads();
        if (t + 2 < NCH) issue(t + 2, stg);
    }

#pragma unroll
    for (int j = 0; j < 2; j++) {
#pragma unroll
        for (int n = 0; n < 4; n++) {
            int c = nTile + wn * 32 + n * 8 + 2 * t4;
            if (c < DOUT) {
                float b0 = bias[c], b1 = bias[c + 1];
                int r0 = mTile + wm * 32 + j * 16 + g;
                *(float2*)&out[(size_t)r0 * DOUT + c] =
                    make_float2(acc[j][n][0] + b0, acc[j][n][1] + b1);
                *(float2*)&out[(size_t)(r0 + 8) * DOUT + c] =
                    make_float2(acc[j][n][2] + b0, acc[j][n][3] + b1);
            }
        }
    }
}

// ---------------- Kernel 2: hyperboloid lift --------------------------------
// warp per (z,row,head). q: negate time, fold 2/scale, bf16 hi/lo.
// k: bf16 hi/lo. v: bf16 hi only.
__global__ void __launch_bounds__(256) lift_kernel(const float* __restrict__ scale_ptr)
{
    int w = (blockIdx.x * blockDim.x + threadIdx.x) >> 5;
    int lane = threadIdx.x & 31;
    int z = w / (ROWS * HH);
    int rem = w - z * (ROWS * HH);
    int r = rem >> 3;
    int h = rem & 7;
    const float* x = g_raw + (size_t)z * ROWS * DOUT + (size_t)r * DOUT + h * 63;
    float xa = (lane > 0) ? x[lane - 1] : 0.0f;
    float xb = x[lane + 31];
    float ss = xa * xa + xb * xb;
#pragma unroll
    for (int o = 16; o; o >>= 1) ss += __shfl_xor_sync(0xffffffffu, ss, o);
    float t = sqrtf(ss + 1.0f);

    int b = r >> 11, n = r & (NN - 1);
    int bh = b * HH + h;
    size_t base = ((size_t)bh * NN + n) * DD;
    float w0 = (lane == 0) ? t : xa;
    float w1 = xb;
    if (z == 0) {
        float sc = 2.0f / scale_ptr[0];
        if (lane == 0) w0 = -t;
        w0 *= sc; w1 *= sc;
        bf16 h0, l0, h1, l1;
        bfsplit(w0, h0, l0);
        bfsplit(w1, h1, l1);
        g_qh[base + lane] = h0;        g_ql[base + lane] = l0;
        g_qh[base + lane + 32] = h1;   g_ql[base + lane + 32] = l1;
    } else if (z == 1) {
        bf16 h0, l0, h1, l1;
        bfsplit(w0, h0, l0);
        bfsplit(w1, h1, l1);
        g_kh[base + lane] = h0;        g_kl[base + lane] = l0;
        g_kh[base + lane + 32] = h1;   g_kl[base + lane + 32] = l1;
    } else {
        g_vh[base + lane] = __float2bfloat16_rn(w0);
        g_vh[base + lane + 32] = __float2bfloat16_rn(w1);
    }
}

// ---------------- Kernel 3: bf16 mma flash attention -------------------------
// 256 thr (8 warps), 128 queries/block (M=16/warp). Key tiles of 64, 2-stage
// cp.async. QK: qh*kh + qh*kl + ql*kh (3 MMA / k16). PV: P_bf16 x V_hi.
// No online max (hyperboloid: logits bounded in [~-2.5, -0.088]).
#define QT 128
#define KT 64
#define NTILES 32

#define KSTR 72                        // bf16 stride (144B rows)
#define TBUF (64 * KSTR)               // 4608 bf16
#define KH_OFF 0
#define KL_OFF (2 * TBUF)              // 9216
#define VH_OFF (4 * TBUF)              // 18432
#define P_OFF  (6 * TBUF)              // 27648
#define PW_SZ  (16 * KSTR)             // 1152
#define ASM_BYTES ((P_OFF + 8 * PW_SZ) * 2)   // 73728

__global__ void __launch_bounds__(256, 1) attn_mma()
{
    extern __shared__ bf16 smbf[];
    u32 smb = (u32)__cvta_generic_to_shared(smbf);

    const int tid = threadIdx.x;
    const int wid = tid >> 5;
    const int lane = tid & 31;
    const int g = lane >> 2;
    const int t4 = lane & 3;
    const int mi = lane >> 3, lr = lane & 7;
    const int a_row = (mi & 1) * 8 + lr;
    const int a_kb  = (mi >> 1) * 16;
    const int b_row = (mi >> 1) * 8 + lr;
    const int b_kb  = (mi & 1) * 16;

    const int qt = blockIdx.x;
    const int bh = blockIdx.y;
    const int n0 = qt * QT;
    const int b = bh >> 3, h = bh & 7;

    // ---- persistent Q A-fragments (hi & lo), M=16 rows per warp ----
    u32 AH[4][4], AL[4][4];
    {
        const bf16* qh = g_qh + ((size_t)bh * NN + n0 + wid * 16) * DD;
        const bf16* ql = g_ql + ((size_t)bh * NN + n0 + wid * 16) * DD;
#pragma unroll
        for (int kk = 0; kk < 4; kk++) {
            int c = kk * 16 + 2 * t4;
            AH[kk][0] = *(const u32*)(qh + g * DD + c);
            AH[kk][1] = *(const u32*)(qh + (g + 8) * DD + c);
            AH[kk][2] = *(const u32*)(qh + g * DD + c + 8);
            AH[kk][3] = *(const u32*)(qh + (g + 8) * DD + c + 8);
            AL[kk][0] = *(const u32*)(ql + g * DD + c);
            AL[kk][1] = *(const u32*)(ql + (g + 8) * DD + c);
            AL[kk][2] = *(const u32*)(ql + g * DD + c + 8);
            AL[kk][3] = *(const u32*)(ql + (g + 8) * DD + c + 8);
        }
    }

    float O[8][4];
#pragma unroll
    for (int j = 0; j < 8; j++)
#pragma unroll
        for (int r = 0; r < 4; r++) O[j][r] = 0.f;
    float lac0 = 0.f, lac1 = 0.f;

    const bf16* khg = g_kh + (size_t)bh * NN * DD;
    const bf16* klg = g_kl + (size_t)bh * NN * DD;
    const bf16* vhg = g_vh + (size_t)bh * NN * DD;

    auto issue = [&](int tile, int buf) {
#pragma unroll
        for (int j = 0; j < 6; j++) {
            int idx = j * 256 + tid;
            int arr = idx >> 9;            // compile-time per j
            int w = idx & 511;
            int row = w >> 3, c = w & 7;
            const bf16* src = (arr == 0 ? khg : (arr == 1 ? klg : vhg))
                              + (size_t)(tile * KT + row) * DD + c * 8;
            u32 off = (arr == 0 ? KH_OFF : (arr == 1 ? KL_OFF : VH_OFF));
            cpa16(smb + (off + buf * TBUF + row * KSTR) * 2 + c * 16, src);
        }
        cpa_commit();
    };

    issue(0, 0);
    issue(1, 1);

    u32 pwb = smb + (P_OFF + wid * PW_SZ) * 2;
    bf16* pwp = smbf + P_OFF + wid * PW_SZ;

    for (int t = 0; t < NTILES; t++) {
        if (t + 1 < NTILES) asm volatile("cp.async.wait_group 1;" ::: "memory");
        else                asm volatile("cp.async.wait_group 0;" ::: "memory");
        __syncthreads();

        const int buf = t & 1;
        u32 khb = smb + (KH_OFF + buf * TBUF) * 2;
        u32 klb = smb + (KL_OFF + buf * TBUF) * 2;
        u32 vhb = smb + (VH_OFF + buf * TBUF) * 2;

        // ---- S = Q K^T  (hh + hl + lh) ----
        float S[8][4];
#pragma unroll
        for (int j = 0; j < 8; j++)
#pragma unroll
            for (int r = 0; r < 4; r++) S[j][r] = 0.f;

#pragma unroll
        for (int kk = 0; kk < 4; kk++) {
#pragma unroll
            for (int jj = 0; jj < 4; jj++) {
                u32 ko = (u32)(jj * 16 + b_row) * (KSTR * 2) + kk * 32 + b_kb;
                u32 BH[4], BL[4];
                ldm4(BH, khb + ko);
                ldm4(BL, klb + ko);
                mmabf(S[2 * jj],     AH[kk], BH[0], BH[1]);
                mmabf(S[2 * jj],     AH[kk], BL[0], BL[1]);
                mmabf(S[2 * jj],     AL[kk], BH[0], BH[1]);
                mmabf(S[2 * jj + 1], AH[kk], BH[2], BH[3]);
                mmabf(S[2 * jj + 1], AH[kk], BL[2], BL[3]);
                mmabf(S[2 * jj + 1], AL[kk], BH[2], BH[3]);
            }
        }

        // ---- exp (logits bounded; l from exact fp32 p), P -> bf16 smem ----
#pragma unroll
        for (int j = 0; j < 8; j++) {
            float p0 = __expf(S[j][0]);
            float p1 = __expf(S[j][1]);
            float p2 = __expf(S[j][2]);
            float p3 = __expf(S[j][3]);
            lac0 += p0 + p1;
            lac1 += p2 + p3;
            int col = j * 8 + 2 * t4;
            __nv_bfloat162 lop = __floats2bfloat162_rn(p0, p1);
            __nv_bfloat162 hip = __floats2bfloat162_rn(p2, p3);
            *(u32*)(pwp + g * KSTR + col) = *(u32*)&lop;
            *(u32*)(pwp + (g + 8) * KSTR + col) = *(u32*)&hip;
        }
        __syncwarp();

        // ---- O += P V  (ldmatrix A from P smem; trans ldmatrix for V) ----
#pragma unroll
        for (int kk = 0; kk < 4; kk++) {
            u32 PA[4];
            ldm4(PA, pwb + (u32)a_row * (KSTR * 2) + kk * 32 + a_kb);
#pragma unroll
            for (int jj = 0; jj < 4; jj++) {
                u32 BV[4];
                ldm4t(BV, vhb + (u32)(kk * 16 + a_row) * (KSTR * 2) + jj * 32 + a_kb);
                mmabf(O[2 * jj],     PA, BV[0], BV[1]);
                mmabf(O[2 * jj + 1], PA, BV[2], BV[3]);
            }
        }
        __syncwarp();

        __syncthreads();
        if (t + 2 < NTILES) issue(t + 2, buf);
    }

    // ---- epilogue ----
    lac0 += __shfl_xor_sync(0xffffffffu, lac0, 1);
    lac0 += __shfl_xor_sync(0xffffffffu, lac0, 2);
    lac1 += __shfl_xor_sync(0xffffffffu, lac1, 1);
    lac1 += __shfl_xor_sync(0xffffffffu, lac1, 2);
    float inv0 = 1.0f / lac0;
    float inv1 = 1.0f / lac1;

    int nq0 = n0 + wid * 16 + g;
    int nq1 = nq0 + 8;
    float* d0 = g_ave + (((size_t)(b * NN + nq0)) * HH + h) * DD;
    float* d1 = g_ave + (((size_t)(b * NN + nq1)) * HH + h) * DD;
#pragma unroll
    for (int j = 0; j < 8; j++) {
        int dcol = j * 8 + 2 * t4;
        *(float2*)&d0[dcol] = make_float2(O[j][0] * inv0, O[j][1] * inv0);
        *(float2*)&d1[dcol] = make_float2(O[j][2] * inv1, O[j][3] * inv1);
    }
}

// ---------------- Kernel 4: centroid epilogue -------------------------------
__device__ __forceinline__ float warp_sum(float v)
{
#pragma unroll
    for (int o = 16; o; o >>= 1) v += __shfl_xor_sync(0xffffffffu, v, o);
    return v;
}

__global__ void __launch_bounds__(256) centroid_kernel(float* __restrict__ out)
{
    int w = (blockIdx.x * blockDim.x + threadIdx.x) >> 5;
    int lane = threadIdx.x & 31;
    float m0 = 0.f, m1 = 0.f;
#pragma unroll
    for (int h = 0; h < HH; h++) {
        const float* a = g_ave + ((size_t)w * HH + h) * DD;
        float a0 = a[lane], a1 = a[lane + 32];
        float part = a0 * a0 + a1 * a1;
        if (lane == 0) part -= 2.0f * a0 * a0;
        float inner = warp_sum(part);
        float denom = sqrtf(fmaxf(fabsf(inner), 1e-8f));
        float inv = 1.0f / denom;
        m0 += a0 * inv; m1 += a1 * inv;
    }
    m0 *= (1.0f / HH); m1 *= (1.0f / HH);
    float part = m0 * m0 + m1 * m1;
    if (lane == 0) part -= 2.0f * m0 * m0;
    float inner = warp_sum(part);
    float denom = sqrtf(fmaxf(fabsf(inner), 1e-8f));
    float inv = 1.0f / denom;
    out[(size_t)w * DD + lane] = m0 * inv;
    out[(size_t)w * DD + lane + 32] = m1 * inv;
}

// ---------------- launch -----------------------------------------------------
extern "C" void kernel_launch(void* const* d_in, const int* in_sizes, int n_in,
                              void* d_out, int out_size)
{
    const float* query  = (const float*)d_in[0];
    const float* source = (const float*)d_in[1];
    const float* Wq = (const float*)d_in[2];
    const float* bq = (const float*)d_in[3];
    const float* Wk = (const float*)d_in[4];
    const float* bk = (const float*)d_in[5];
    const float* Wv = (const float*)d_in[6];
    const float* bv = (const float*)d_in[7];
    const float* scale = (const float*)d_in[8];
    float* out = (float*)d_out;

    cudaFuncSetAttribute(gemm_tc, cudaFuncAttributeMaxDynamicSharedMemorySize, GSM_BYTES);
    cudaFuncSetAttribute(attn_mma, cudaFuncAttributeMaxDynamicSharedMemorySize, ASM_BYTES);

    split_inputs<<<(2 * ROWS * EE / 2) / 256, 256>>>(query, source);
    split_w<<<(3 * EE * EE / 2) / 256, 256>>>(Wq, Wk, Wv);

    gemm_tc<<<dim3(ROWS / 128, EE / 64, 3), 256, GSM_BYTES>>>(bq, bk, bv);

    int lift_warps = 3 * ROWS * HH;
    lift_kernel<<<lift_warps * 32 / 256, 256>>>(scale);

    attn_mma<<<dim3(NN / QT, BHN), 256, ASM_BYTES>>>();

    centroid_kernel<<<ROWS * 32 / 256, 256>>>(out);
}

// round 10
// speedup vs baseline: 7.4896x; 1.1596x over previous
#include <cuda_runtime.h>
#include <cuda_bf16.h>
#include <cstdint>

// Problem constants
#define BB 2
#define NN 2048
#define HH 8
#define EE 512
#define DOUT 504          // H * 63
#define DD 64             // lifted dim
#define ROWS 4096         // B*N
#define BHN (BB*HH)       // 16

typedef unsigned long long u64;
typedef uint32_t u32;
typedef __nv_bfloat16 bf16;

// ---------------- scratch (device globals; no allocation allowed) ----------
__device__ float g_raw[3 * ROWS * DOUT];            // raw projections q,k,v (f32)
__device__ alignas(16) bf16 g_ah[2 * ROWS * EE];    // input splits (query, source)
__device__ alignas(16) bf16 g_al[2 * ROWS * EE];
__device__ alignas(16) bf16 g_wh[3 * EE * EE];      // W splits, rows padded to 512
__device__ alignas(16) bf16 g_wl[3 * EE * EE];
__device__ alignas(16) bf16 g_qh[BHN * NN * DD];    // lifted q (sign+scale folded, hi only)
__device__ alignas(16) bf16 g_kh[BHN * NN * DD];
__device__ alignas(16) bf16 g_kl[BHN * NN * DD];
__device__ alignas(16) bf16 g_vh[BHN * NN * DD];    // lifted v (hi only)
__device__ float g_ave[ROWS * HH * DD];             // attention output per head

// ---------------- helpers ----------------------------------------------------
__device__ __forceinline__ void bfsplit(float x, bf16& hi, bf16& lo) {
    hi = __float2bfloat16_rn(x);
    lo = __float2bfloat16_rn(x - __bfloat162float(hi));
}
__device__ __forceinline__ void cpa16(u32 dst, const void* src) {
    asm volatile("cp.async.cg.shared.global [%0], [%1], 16;" :: "r"(dst), "l"(src));
}
__device__ __forceinline__ void cpa_commit() {
    asm volatile("cp.async.commit_group;" ::: "memory");
}
__device__ __forceinline__ void mmabf(float* d, const u32* a, u32 b0, u32 b1) {
    asm volatile("mma.sync.aligned.m16n8k16.row.col.f32.bf16.bf16.f32 "
        "{%0,%1,%2,%3}, {%4,%5,%6,%7}, {%8,%9}, {%0,%1,%2,%3};"
        : "+f"(d[0]), "+f"(d[1]), "+f"(d[2]), "+f"(d[3])
        : "r"(a[0]), "r"(a[1]), "r"(a[2]), "r"(a[3]), "r"(b0), "r"(b1));
}
__device__ __forceinline__ void ldm4(u32* r, u32 addr) {
    asm volatile("ldmatrix.sync.aligned.m8n8.x4.shared.b16 {%0,%1,%2,%3}, [%4];"
        : "=r"(r[0]), "=r"(r[1]), "=r"(r[2]), "=r"(r[3]) : "r"(addr));
}
__device__ __forceinline__ void ldm4t(u32* r, u32 addr) {
    asm volatile("ldmatrix.sync.aligned.m8n8.x4.trans.shared.b16 {%0,%1,%2,%3}, [%4];"
        : "=r"(r[0]), "=r"(r[1]), "=r"(r[2]), "=r"(r[3]) : "r"(addr));
}

// ---------------- Kernel 0a: split inputs to bf16 hi/lo ---------------------
__global__ void __launch_bounds__(256) split_inputs(
    const float* __restrict__ q, const float* __restrict__ s)
{
    int i = (blockIdx.x * blockDim.x + threadIdx.x) * 2;
    const int half = ROWS * EE;
    float2 v = (i < half) ? *(const float2*)(q + i) : *(const float2*)(s + i - half);
    bf16 h0, l0, h1, l1;
    bfsplit(v.x, h0, l0);
    bfsplit(v.y, h1, l1);
    __nv_bfloat162 hh; hh.x = h0; hh.y = h1;
    __nv_bfloat162 ll; ll.x = l0; ll.y = l1;
    *(u32*)&g_ah[i] = *(u32*)&hh;
    *(u32*)&g_al[i] = *(u32*)&ll;
}

// ---------------- Kernel 0b: split weights (pad rows 504..511 with 0) -------
__global__ void __launch_bounds__(256) split_w(
    const float* __restrict__ Wq, const float* __restrict__ Wk,
    const float* __restrict__ Wv)
{
    int i = (blockIdx.x * blockDim.x + threadIdx.x) * 2;
    int z = i / (EE * EE);
    int rem = i - z * (EE * EE);
    int row = rem >> 9;
    int col = rem & 511;
    const float* W = (z == 0) ? Wq : (z == 1 ? Wk : Wv);
    float2 v = make_float2(0.f, 0.f);
    if (row < DOUT) v = *(const float2*)(W + (size_t)row * EE + col);
    bf16 h0, l0, h1, l1;
    bfsplit(v.x, h0, l0);
    bfsplit(v.y, h1, l1);
    __nv_bfloat162 hh; hh.x = h0; hh.y = h1;
    __nv_bfloat162 ll; ll.x = l0; ll.y = l1;
    *(u32*)&g_wh[i] = *(u32*)&hh;
    *(u32*)&g_wl[i] = *(u32*)&ll;
}

// ---------------- Kernel 1: QKV projection GEMM (bf16x3 mma + ldmatrix) -----
#define ASTR 40                       // bf16 stride (80B rows)
#define ABUF (128 * ASTR)             // 5120
#define WBUF (64 * ASTR)              // 2560
#define GAH 0
#define GAL (2 * ABUF)                // 10240
#define GWH (4 * ABUF)                // 20480
#define GWL (GWH + 2 * WBUF)          // 25600
#define GSM_BYTES ((GWL + 2 * WBUF) * 2)   // 61440

__global__ void __launch_bounds__(256, 2) gemm_tc(
    const float* __restrict__ bq, const float* __restrict__ bk,
    const float* __restrict__ bv)
{
    extern __shared__ bf16 smbf[];
    u32 smb = (u32)__cvta_generic_to_shared(smbf);

    const int tid = threadIdx.x;
    const int wid = tid >> 5;
    const int lane = tid & 31;
    const int g = lane >> 2;
    const int t4 = lane & 3;
    const int wm = wid & 3;          // 0..3 (M)
    const int wn = wid >> 2;         // 0..1 (N)
    const int mi = lane >> 3, lr = lane & 7;
    const int a_row = (mi & 1) * 8 + lr;
    const int a_kb  = (mi >> 1) * 16;
    const int b_row = (mi >> 1) * 8 + lr;
    const int b_kb  = (mi & 1) * 16;

    const int mTile = blockIdx.x * 128;
    const int nTile = blockIdx.y * 64;
    const int z = blockIdx.z;

    const bf16* ahg = g_ah + (size_t)(z ? 1 : 0) * ROWS * EE;
    const bf16* alg = g_al + (size_t)(z ? 1 : 0) * ROWS * EE;
    const bf16* whg = g_wh + (size_t)z * EE * EE;
    const bf16* wlg = g_wl + (size_t)z * EE * EE;
    const float* bias = (z == 0) ? bq : (z == 1 ? bk : bv);
    float* out = g_raw + (size_t)z * ROWS * DOUT;

    float acc[2][4][4];
#pragma unroll
    for (int j = 0; j < 2; j++)
#pragma unroll
        for (int n = 0; n < 4; n++)
#pragma unroll
            for (int r = 0; r < 4; r++) acc[j][n][r] = 0.f;

    auto issue = [&](int chunk, int stg) {
        int k0 = chunk * 32;
#pragma unroll
        for (int it = 0; it < 2; it++) {
            int idx = it * 256 + tid;
            int row = idx >> 2, c = idx & 3;
            size_t go = (size_t)(mTile + row) * EE + k0 + c * 8;
            u32 so = row * (ASTR * 2) + c * 16;
            cpa16(smb + (GAH + stg * ABUF) * 2 + so, ahg + go);
            cpa16(smb + (GAL + stg * ABUF) * 2 + so, alg + go);
        }
        {
            int row = tid >> 2, c = tid & 3;
            size_t go = (size_t)(nTile + row) * EE + k0 + c * 8;
            u32 so = row * (ASTR * 2) + c * 16;
            cpa16(smb + (GWH + stg * WBUF) * 2 + so, whg + go);
            cpa16(smb + (GWL + stg * WBUF) * 2 + so, wlg + go);
        }
        cpa_commit();
    };

    issue(0, 0);
    issue(1, 1);

    const int NCH = EE / 32;   // 16
    for (int t = 0; t < NCH; t++) {
        if (t + 1 < NCH) asm volatile("cp.async.wait_group 1;" ::: "memory");
        else             asm volatile("cp.async.wait_group 0;" ::: "memory");
        __syncthreads();

        const int stg = t & 1;
        u32 ahb = smb + (GAH + stg * ABUF) * 2;
        u32 alb = smb + (GAL + stg * ABUF) * 2;
        u32 whb = smb + (GWH + stg * WBUF) * 2;
        u32 wlb = smb + (GWL + stg * WBUF) * 2;

#pragma unroll
        for (int kk = 0; kk < 2; kk++) {
            u32 AH[2][4], AL[2][4];
#pragma unroll
            for (int j = 0; j < 2; j++) {
                u32 ao = (u32)(wm * 32 + j * 16 + a_row) * (ASTR * 2) + kk * 32 + a_kb;
                ldm4(AH[j], ahb + ao);
                ldm4(AL[j], alb + ao);
            }
#pragma unroll
            for (int jj = 0; jj < 2; jj++) {
                u32 WH[4], WL[4];
                u32 wo = (u32)(wn * 32 + jj * 16 + b_row) * (ASTR * 2) + kk * 32 + b_kb;
                ldm4(WH, whb + wo);
                ldm4(WL, wlb + wo);
#pragma unroll
                for (int j = 0; j < 2; j++) {
                    mmabf(acc[j][2 * jj],     AH[j], WH[0], WH[1]);
                    mmabf(acc[j][2 * jj],     AH[j], WL[0], WL[1]);
                    mmabf(acc[j][2 * jj],     AL[j], WH[0], WH[1]);
                    mmabf(acc[j][2 * jj + 1], AH[j], WH[2], WH[3]);
                    mmabf(acc[j][2 * jj + 1], AH[j], WL[2], WL[3]);
                    mmabf(acc[j][2 * jj + 1], AL[j], WH[2], WH[3]);
                }
            }
        }
        __syncthreads();
        if (t + 2 < NCH) issue(t + 2, stg);
    }

#pragma unroll
    for (int j = 0; j < 2; j++) {
#pragma unroll
        for (int n = 0; n < 4; n++) {
            int c = nTile + wn * 32 + n * 8 + 2 * t4;
            if (c < DOUT) {
                float b0 = bias[c], b1 = bias[c + 1];
                int r0 = mTile + wm * 32 + j * 16 + g;
                *(float2*)&out[(size_t)r0 * DOUT + c] =
                    make_float2(acc[j][n][0] + b0, acc[j][n][1] + b1);
                *(float2*)&out[(size_t)(r0 + 8) * DOUT + c] =
                    make_float2(acc[j][n][2] + b0, acc[j][n][3] + b1);
            }
        }
    }
}

// ---------------- Kernel 2: hyperboloid lift --------------------------------
// warp per (z,row,head). q: negate time, fold 2/scale, bf16 hi only.
// k: bf16 hi/lo. v: bf16 hi only.
__global__ void __launch_bounds__(256) lift_kernel(const float* __restrict__ scale_ptr)
{
    int w = (blockIdx.x * blockDim.x + threadIdx.x) >> 5;
    int lane = threadIdx.x & 31;
    int z = w / (ROWS * HH);
    int rem = w - z * (ROWS * HH);
    int r = rem >> 3;
    int h = rem & 7;
    const float* x = g_raw + (size_t)z * ROWS * DOUT + (size_t)r * DOUT + h * 63;
    float xa = (lane > 0) ? x[lane - 1] : 0.0f;
    float xb = x[lane + 31];
    float ss = xa * xa + xb * xb;
#pragma unroll
    for (int o = 16; o; o >>= 1) ss += __shfl_xor_sync(0xffffffffu, ss, o);
    float t = sqrtf(ss + 1.0f);

    int b = r >> 11, n = r & (NN - 1);
    int bh = b * HH + h;
    size_t base = ((size_t)bh * NN + n) * DD;
    float w0 = (lane == 0) ? t : xa;
    float w1 = xb;
    if (z == 0) {
        float sc = 2.0f / scale_ptr[0];
        if (lane == 0) w0 = -t;
        g_qh[base + lane] = __float2bfloat16_rn(w0 * sc);
        g_qh[base + lane + 32] = __float2bfloat16_rn(w1 * sc);
    } else if (z == 1) {
        bf16 h0, l0, h1, l1;
        bfsplit(w0, h0, l0);
        bfsplit(w1, h1, l1);
        g_kh[base + lane] = h0;        g_kl[base + lane] = l0;
        g_kh[base + lane + 32] = h1;   g_kl[base + lane + 32] = l1;
    } else {
        g_vh[base + lane] = __float2bfloat16_rn(w0);
        g_vh[base + lane + 32] = __float2bfloat16_rn(w1);
    }
}

// ---------------- Kernel 3: bf16 mma flash attention -------------------------
// 256 thr (8 warps), 128 queries/block (M=16/warp). Key tiles of 64, 2-stage
// cp.async, 2 CTAs/SM. QK: qh*kh + qh*kl (2 MMA / k16). PV: P_bf16 x V_hi.
// No online max (hyperboloid: logits bounded in [~-2.5, -0.088]).
#define QT 128
#define KT 64
#define NTILES 32

#define KSTR 72                        // bf16 stride (144B rows)
#define TBUF (64 * KSTR)               // 4608 bf16
#define KH_OFF 0
#define KL_OFF (2 * TBUF)              // 9216
#define VH_OFF (4 * TBUF)              // 18432
#define P_OFF  (6 * TBUF)              // 27648
#define PW_SZ  (16 * KSTR)             // 1152
#define ASM_BYTES ((P_OFF + 8 * PW_SZ) * 2)   // 73728

__global__ void __launch_bounds__(256, 2) attn_mma()
{
    extern __shared__ bf16 smbf[];
    u32 smb = (u32)__cvta_generic_to_shared(smbf);

    const int tid = threadIdx.x;
    const int wid = tid >> 5;
    const int lane = tid & 31;
    const int g = lane >> 2;
    const int t4 = lane & 3;
    const int mi = lane >> 3, lr = lane & 7;
    const int a_row = (mi & 1) * 8 + lr;
    const int a_kb  = (mi >> 1) * 16;
    const int b_row = (mi >> 1) * 8 + lr;
    const int b_kb  = (mi & 1) * 16;

    const int qt = blockIdx.x;
    const int bh = blockIdx.y;
    const int n0 = qt * QT;
    const int b = bh >> 3, h = bh & 7;

    // ---- persistent Q A-fragments (hi only), M=16 rows per warp ----
    u32 AH[4][4];
    {
        const bf16* qh = g_qh + ((size_t)bh * NN + n0 + wid * 16) * DD;
#pragma unroll
        for (int kk = 0; kk < 4; kk++) {
            int c = kk * 16 + 2 * t4;
            AH[kk][0] = *(const u32*)(qh + g * DD + c);
            AH[kk][1] = *(const u32*)(qh + (g + 8) * DD + c);
            AH[kk][2] = *(const u32*)(qh + g * DD + c + 8);
            AH[kk][3] = *(const u32*)(qh + (g + 8) * DD + c + 8);
        }
    }

    float O[8][4];
#pragma unroll
    for (int j = 0; j < 8; j++)
#pragma unroll
        for (int r = 0; r < 4; r++) O[j][r] = 0.f;
    float lac0 = 0.f, lac1 = 0.f;

    const bf16* khg = g_kh + (size_t)bh * NN * DD;
    const bf16* klg = g_kl + (size_t)bh * NN * DD;
    const bf16* vhg = g_vh + (size_t)bh * NN * DD;

    auto issue = [&](int tile, int buf) {
#pragma unroll
        for (int j = 0; j < 6; j++) {
            int idx = j * 256 + tid;
            int arr = idx >> 9;
            int w = idx & 511;
            int row = w >> 3, c = w & 7;
            const bf16* src = (arr == 0 ? khg : (arr == 1 ? klg : vhg))
                              + (size_t)(tile * KT + row) * DD + c * 8;
            u32 off = (arr == 0 ? KH_OFF : (arr == 1 ? KL_OFF : VH_OFF));
            cpa16(smb + (off + buf * TBUF + row * KSTR) * 2 + c * 16, src);
        }
        cpa_commit();
    };

    issue(0, 0);
    issue(1, 1);

    u32 pwb = smb + (P_OFF + wid * PW_SZ) * 2;
    bf16* pwp = smbf + P_OFF + wid * PW_SZ;

    for (int t = 0; t < NTILES; t++) {
        if (t + 1 < NTILES) asm volatile("cp.async.wait_group 1;" ::: "memory");
        else                asm volatile("cp.async.wait_group 0;" ::: "memory");
        __syncthreads();

        const int buf = t & 1;
        u32 khb = smb + (KH_OFF + buf * TBUF) * 2;
        u32 klb = smb + (KL_OFF + buf * TBUF) * 2;
        u32 vhb = smb + (VH_OFF + buf * TBUF) * 2;

        // ---- S = Q K^T  (qh*kh + qh*kl) ----
        float S[8][4];
#pragma unroll
        for (int j = 0; j < 8; j++)
#pragma unroll
            for (int r = 0; r < 4; r++) S[j][r] = 0.f;

#pragma unroll
        for (int kk = 0; kk < 4; kk++) {
#pragma unroll
            for (int jj = 0; jj < 4; jj++) {
                u32 ko = (u32)(jj * 16 + b_row) * (KSTR * 2) + kk * 32 + b_kb;
                u32 BH[4], BL[4];
                ldm4(BH, khb + ko);
                ldm4(BL, klb + ko);
                mmabf(S[2 * jj],     AH[kk], BH[0], BH[1]);
                mmabf(S[2 * jj],     AH[kk], BL[0], BL[1]);
                mmabf(S[2 * jj + 1], AH[kk], BH[2], BH[3]);
                mmabf(S[2 * jj + 1], AH[kk], BL[2], BL[3]);
            }
        }

        // ---- exp (logits bounded; l from exact fp32 p), P -> bf16 smem ----
#pragma unroll
        for (int j = 0; j < 8; j++) {
            float p0 = __expf(S[j][0]);
            float p1 = __expf(S[j][1]);
            float p2 = __expf(S[j][2]);
            float p3 = __expf(S[j][3]);
            lac0 += p0 + p1;
            lac1 += p2 + p3;
            int col = j * 8 + 2 * t4;
            __nv_bfloat162 lop = __floats2bfloat162_rn(p0, p1);
            __nv_bfloat162 hip = __floats2bfloat162_rn(p2, p3);
            *(u32*)(pwp + g * KSTR + col) = *(u32*)&lop;
            *(u32*)(pwp + (g + 8) * KSTR + col) = *(u32*)&hip;
        }
        __syncwarp();

        // ---- O += P V  (ldmatrix A from P smem; trans ldmatrix for V) ----
#pragma unroll
        for (int kk = 0; kk < 4; kk++) {
            u32 PA[4];
            ldm4(PA, pwb + (u32)a_row * (KSTR * 2) + kk * 32 + a_kb);
#pragma unroll
            for (int jj = 0; jj < 4; jj++) {
                u32 BV[4];
                ldm4t(BV, vhb + (u32)(kk * 16 + a_row) * (KSTR * 2) + jj * 32 + a_kb);
                mmabf(O[2 * jj],     PA, BV[0], BV[1]);
                mmabf(O[2 * jj + 1], PA, BV[2], BV[3]);
            }
        }
        __syncwarp();

        __syncthreads();
        if (t + 2 < NTILES) issue(t + 2, buf);
    }

    // ---- epilogue ----
    lac0 += __shfl_xor_sync(0xffffffffu, lac0, 1);
    lac0 += __shfl_xor_sync(0xffffffffu, lac0, 2);
    lac1 += __shfl_xor_sync(0xffffffffu, lac1, 1);
    lac1 += __shfl_xor_sync(0xffffffffu, lac1, 2);
    float inv0 = 1.0f / lac0;
    float inv1 = 1.0f / lac1;

    int nq0 = n0 + wid * 16 + g;
    int nq1 = nq0 + 8;
    float* d0 = g_ave + (((size_t)(b * NN + nq0)) * HH + h) * DD;
    float* d1 = g_ave + (((size_t)(b * NN + nq1)) * HH + h) * DD;
#pragma unroll
    for (int j = 0; j < 8; j++) {
        int dcol = j * 8 + 2 * t4;
        *(float2*)&d0[dcol] = make_float2(O[j][0] * inv0, O[j][1] * inv0);
        *(float2*)&d1[dcol] = make_float2(O[j][2] * inv1, O[j][3] * inv1);
    }
}

// ---------------- Kernel 4: centroid epilogue -------------------------------
__device__ __forceinline__ float warp_sum(float v)
{
#pragma unroll
    for (int o = 16; o; o >>= 1) v += __shfl_xor_sync(0xffffffffu, v, o);
    return v;
}

__global__ void __launch_bounds__(256) centroid_kernel(float* __restrict__ out)
{
    int w = (blockIdx.x * blockDim.x + threadIdx.x) >> 5;
    int lane = threadIdx.x & 31;
    float m0 = 0.f, m1 = 0.f;
#pragma unroll
    for (int h = 0; h < HH; h++) {
        const float* a = g_ave + ((size_t)w * HH + h) * DD;
        float a0 = a[lane], a1 = a[lane + 32];
        float part = a0 * a0 + a1 * a1;
        if (lane == 0) part -= 2.0f * a0 * a0;
        float inner = warp_sum(part);
        float denom = sqrtf(fmaxf(fabsf(inner), 1e-8f));
        float inv = 1.0f / denom;
        m0 += a0 * inv; m1 += a1 * inv;
    }
    m0 *= (1.0f / HH); m1 *= (1.0f / HH);
    float part = m0 * m0 + m1 * m1;
    if (lane == 0) part -= 2.0f * m0 * m0;
    float inner = warp_sum(part);
    float denom = sqrtf(fmaxf(fabsf(inner), 1e-8f));
    float inv = 1.0f / denom;
    out[(size_t)w * DD + lane] = m0 * inv;
    out[(size_t)w * DD + lane + 32] = m1 * inv;
}

// ---------------- launch -----------------------------------------------------
extern "C" void kernel_launch(void* const* d_in, const int* in_sizes, int n_in,
                              void* d_out, int out_size)
{
    const float* query  = (const float*)d_in[0];
    const float* source = (const float*)d_in[1];
    const float* Wq = (const float*)d_in[2];
    const float* bq = (const float*)d_in[3];
    const float* Wk = (const float*)d_in[4];
    const float* bk = (const float*)d_in[5];
    const float* Wv = (const float*)d_in[6];
    const float* bv = (const float*)d_in[7];
    const float* scale = (const float*)d_in[8];
    float* out = (float*)d_out;

    cudaFuncSetAttribute(gemm_tc, cudaFuncAttributeMaxDynamicSharedMemorySize, GSM_BYTES);
    cudaFuncSetAttribute(attn_mma, cudaFuncAttributeMaxDynamicSharedMemorySize, ASM_BYTES);

    split_inputs<<<(2 * ROWS * EE / 2) / 256, 256>>>(query, source);
    split_w<<<(3 * EE * EE / 2) / 256, 256>>>(Wq, Wk, Wv);

    gemm_tc<<<dim3(ROWS / 128, EE / 64, 3), 256, GSM_BYTES>>>(bq, bk, bv);

    int lift_warps = 3 * ROWS * HH;
    lift_kernel<<<lift_warps * 32 / 256, 256>>>(scale);

    attn_mma<<<dim3(NN / QT, BHN), 256, ASM_BYTES>>>();

    centroid_kernel<<<ROWS * 32 / 256, 256>>>(out);
}

// round 11
// speedup vs baseline: 8.0255x; 1.0715x over previous
#include <cuda_runtime.h>
#include <cuda_bf16.h>
#include <cstdint>

// Problem constants
#define BB 2
#define NN 2048
#define HH 8
#define EE 512
#define DOUT 504          // H * 63
#define DD 64             // lifted dim
#define ROWS 4096         // B*N
#define BHN (BB*HH)       // 16

typedef unsigned long long u64;
typedef uint32_t u32;
typedef __nv_bfloat16 bf16;

// ---------------- scratch (device globals; no allocation allowed) ----------
__device__ alignas(16) bf16 g_ah[2 * ROWS * EE];    // input splits (query, source)
__device__ alignas(16) bf16 g_al[2 * ROWS * EE];
__device__ alignas(16) bf16 g_wh[3 * EE * EE];      // W splits, head-padded rows (h*64+d)
__device__ alignas(16) bf16 g_wl[3 * EE * EE];
__device__ alignas(16) bf16 g_qh[BHN * NN * DD];    // lifted q (sign+scale folded, hi only)
__device__ alignas(16) bf16 g_kh[BHN * NN * DD];
__device__ alignas(16) bf16 g_kl[BHN * NN * DD];
__device__ alignas(16) bf16 g_vh[BHN * NN * DD];    // lifted v (hi only)
__device__ float g_ave[ROWS * HH * DD];             // attention output per head

// ---------------- helpers ----------------------------------------------------
__device__ __forceinline__ void bfsplit(float x, bf16& hi, bf16& lo) {
    hi = __float2bfloat16_rn(x);
    lo = __float2bfloat16_rn(x - __bfloat162float(hi));
}
__device__ __forceinline__ void cpa16(u32 dst, const void* src) {
    asm volatile("cp.async.cg.shared.global [%0], [%1], 16;" :: "r"(dst), "l"(src));
}
__device__ __forceinline__ void cpa_commit() {
    asm volatile("cp.async.commit_group;" ::: "memory");
}
__device__ __forceinline__ void mmabf(float* d, const u32* a, u32 b0, u32 b1) {
    asm volatile("mma.sync.aligned.m16n8k16.row.col.f32.bf16.bf16.f32 "
        "{%0,%1,%2,%3}, {%4,%5,%6,%7}, {%8,%9}, {%0,%1,%2,%3};"
        : "+f"(d[0]), "+f"(d[1]), "+f"(d[2]), "+f"(d[3])
        : "r"(a[0]), "r"(a[1]), "r"(a[2]), "r"(a[3]), "r"(b0), "r"(b1));
}
__device__ __forceinline__ void ldm4(u32* r, u32 addr) {
    asm volatile("ldmatrix.sync.aligned.m8n8.x4.shared.b16 {%0,%1,%2,%3}, [%4];"
        : "=r"(r[0]), "=r"(r[1]), "=r"(r[2]), "=r"(r[3]) : "r"(addr));
}
__device__ __forceinline__ void ldm4t(u32* r, u32 addr) {
    asm volatile("ldmatrix.sync.aligned.m8n8.x4.trans.shared.b16 {%0,%1,%2,%3}, [%4];"
        : "=r"(r[0]), "=r"(r[1]), "=r"(r[2]), "=r"(r[3]) : "r"(addr));
}

// ---------------- Kernel 0: fused split (inputs + head-padded weights) ------
// inputs: straight bf16 hi/lo split. weights: padded row h*64+d; d==0 -> 0,
// d>=1 -> original row h*63+(d-1).
__global__ void __launch_bounds__(256) split_all(
    const float* __restrict__ q, const float* __restrict__ s,
    const float* __restrict__ Wq, const float* __restrict__ Wk,
    const float* __restrict__ Wv)
{
    int i = (blockIdx.x * blockDim.x + threadIdx.x) * 2;
    const int half = ROWS * EE;
    const int tot_in = 2 * half;
    if (i < tot_in) {
        float2 v = (i < half) ? *(const float2*)(q + i) : *(const float2*)(s + i - half);
        bf16 h0, l0, h1, l1;
        bfsplit(v.x, h0, l0);
        bfsplit(v.y, h1, l1);
        __nv_bfloat162 hh; hh.x = h0; hh.y = h1;
        __nv_bfloat162 ll; ll.x = l0; ll.y = l1;
        *(u32*)&g_ah[i] = *(u32*)&hh;
        *(u32*)&g_al[i] = *(u32*)&ll;
    } else {
        int j = i - tot_in;
        int z = j / (EE * EE);
        int rem = j - z * (EE * EE);
        int row = rem >> 9;
        int col = rem & 511;
        int d = row & 63, h = row >> 6;
        const float* W = (z == 0) ? Wq : (z == 1 ? Wk : Wv);
        float2 v = make_float2(0.f, 0.f);
        if (d > 0) v = *(const float2*)(W + (size_t)(h * 63 + d - 1) * EE + col);
        bf16 h0, l0, h1, l1;
        bfsplit(v.x, h0, l0);
        bfsplit(v.y, h1, l1);
        __nv_bfloat162 hh; hh.x = h0; hh.y = h1;
        __nv_bfloat162 ll; ll.x = l0; ll.y = l1;
        *(u32*)&g_wh[j] = *(u32*)&hh;
        *(u32*)&g_wl[j] = *(u32*)&ll;
    }
}

// ---------------- Kernel 1: QKV GEMM + fused hyperboloid lift ----------------
// Block: 256 thr, 8 warps ALL along M (warp tile 16 x 64). Tile M=128, N=64
// (= exactly one head, via padded-W layout), k-chunk 32, 2-stage cp.async.
// Epilogue: row ||x||^2 via quad shfl -> t -> write bf16 q/k(hi,lo)/v directly.
#define ASTR 40                       // bf16 k-stride (80B rows)
#define ABUF (128 * ASTR)             // 5120
#define WBUF (64 * ASTR)              // 2560
#define GAH 0
#define GAL (2 * ABUF)                // 10240
#define GWH (4 * ABUF)                // 20480
#define GWL (GWH + 2 * WBUF)          // 25600
#define GSM_BYTES ((GWL + 2 * WBUF) * 2)   // 61440

__global__ void __launch_bounds__(256, 2) gemm_lift(
    const float* __restrict__ bq, const float* __restrict__ bk,
    const float* __restrict__ bv, const float* __restrict__ scale_ptr)
{
    extern __shared__ bf16 smbf[];
    u32 smb = (u32)__cvta_generic_to_shared(smbf);

    const int tid = threadIdx.x;
    const int wid = tid >> 5;
    const int lane = tid & 31;
    const int g = lane >> 2;
    const int t4 = lane & 3;
    const int mi = lane >> 3, lr = lane & 7;
    const int a_row = (mi & 1) * 8 + lr;
    const int a_kb  = (mi >> 1) * 16;
    const int b_row = (mi >> 1) * 8 + lr;
    const int b_kb  = (mi & 1) * 16;

    const int mTile = blockIdx.x * 128;
    const int h = blockIdx.y;          // head 0..7
    const int z = blockIdx.z;

    const bf16* ahg = g_ah + (size_t)(z ? 1 : 0) * ROWS * EE;
    const bf16* alg = g_al + (size_t)(z ? 1 : 0) * ROWS * EE;
    const bf16* whg = g_wh + (size_t)z * EE * EE;
    const bf16* wlg = g_wl + (size_t)z * EE * EE;

    float acc[8][4];
#pragma unroll
    for (int n = 0; n < 8; n++)
#pragma unroll
        for (int r = 0; r < 4; r++) acc[n][r] = 0.f;

    auto issue = [&](int chunk, int stg) {
        int k0 = chunk * 32;
#pragma unroll
        for (int it = 0; it < 2; it++) {
            int idx = it * 256 + tid;
            int row = idx >> 2, c = idx & 3;
            size_t go = (size_t)(mTile + row) * EE + k0 + c * 8;
            u32 so = row * (ASTR * 2) + c * 16;
            cpa16(smb + (GAH + stg * ABUF) * 2 + so, ahg + go);
            cpa16(smb + (GAL + stg * ABUF) * 2 + so, alg + go);
        }
        {
            int row = tid >> 2, c = tid & 3;
            size_t go = (size_t)(h * 64 + row) * EE + k0 + c * 8;
            u32 so = row * (ASTR * 2) + c * 16;
            cpa16(smb + (GWH + stg * WBUF) * 2 + so, whg + go);
            cpa16(smb + (GWL + stg * WBUF) * 2 + so, wlg + go);
        }
        cpa_commit();
    };

    issue(0, 0);
    issue(1, 1);

    const int NCH = EE / 32;   // 16
    for (int t = 0; t < NCH; t++) {
        if (t + 1 < NCH) asm volatile("cp.async.wait_group 1;" ::: "memory");
        else             asm volatile("cp.async.wait_group 0;" ::: "memory");
        __syncthreads();

        const int stg = t & 1;
        u32 ahb = smb + (GAH + stg * ABUF) * 2;
        u32 alb = smb + (GAL + stg * ABUF) * 2;
        u32 whb = smb + (GWH + stg * WBUF) * 2;
        u32 wlb = smb + (GWL + stg * WBUF) * 2;

#pragma unroll
        for (int kk = 0; kk < 2; kk++) {
            u32 AHf[4], ALf[4];
            u32 ao = (u32)(wid * 16 + a_row) * (ASTR * 2) + kk * 32 + a_kb;
            ldm4(AHf, ahb + ao);
            ldm4(ALf, alb + ao);
#pragma unroll
            for (int nt = 0; nt < 4; nt++) {
                u32 WH[4], WL[4];
                u32 wo = (u32)(nt * 16 + b_row) * (ASTR * 2) + kk * 32 + b_kb;
                ldm4(WH, whb + wo);
                ldm4(WL, wlb + wo);
                mmabf(acc[2 * nt],     AHf, WH[0], WH[1]);
                mmabf(acc[2 * nt],     AHf, WL[0], WL[1]);
                mmabf(acc[2 * nt],     ALf, WH[0], WH[1]);
                mmabf(acc[2 * nt + 1], AHf, WH[2], WH[3]);
                mmabf(acc[2 * nt + 1], AHf, WL[2], WL[3]);
                mmabf(acc[2 * nt + 1], ALf, WH[2], WH[3]);
            }
        }
        __syncthreads();
        if (t + 2 < NCH) issue(t + 2, stg);
    }

    // ---- fused lift epilogue ----
    // add (padded) bias, then row sum-of-squares over the 64 head cols
    const float* bias = (z == 0) ? bq : (z == 1 ? bk : bv);
    float s0 = 0.f, s1 = 0.f;
#pragma unroll
    for (int j = 0; j < 8; j++) {
        int c = j * 8 + 2 * t4;
        float b0 = (c == 0) ? 0.f : __ldg(&bias[h * 63 + c - 1]);
        float b1 = __ldg(&bias[h * 63 + c]);
        acc[j][0] += b0;  acc[j][1] += b1;
        acc[j][2] += b0;  acc[j][3] += b1;
        s0 += acc[j][0] * acc[j][0] + acc[j][1] * acc[j][1];
        s1 += acc[j][2] * acc[j][2] + acc[j][3] * acc[j][3];
    }
    s0 += __shfl_xor_sync(0xffffffffu, s0, 1);
    s0 += __shfl_xor_sync(0xffffffffu, s0, 2);
    s1 += __shfl_xor_sync(0xffffffffu, s1, 1);
    s1 += __shfl_xor_sync(0xffffffffu, s1, 2);
    float t0 = sqrtf(s0 + 1.0f);
    float t1 = sqrtf(s1 + 1.0f);

    int n0 = mTile + wid * 16 + g;      // global row (0..4095)
    int n1 = n0 + 8;
    int b0i = n0 >> 11;
    int bh = b0i * HH + h;
    size_t base0 = ((size_t)bh * NN + (n0 & (NN - 1))) * DD;
    size_t base1 = ((size_t)bh * NN + (n1 & (NN - 1))) * DD;

    if (z == 0) {
        float sc = 2.0f / __ldg(scale_ptr);
#pragma unroll
        for (int j = 0; j < 8; j++) {
            int c = j * 8 + 2 * t4;
            float a0 = (c == 0) ? -t0 : acc[j][0];
            float a2 = (c == 0) ? -t1 : acc[j][2];
            __nv_bfloat162 p0 = __floats2bfloat162_rn(a0 * sc, acc[j][1] * sc);
            __nv_bfloat162 p1 = __floats2bfloat162_rn(a2 * sc, acc[j][3] * sc);
            *(u32*)&g_qh[base0 + c] = *(u32*)&p0;
            *(u32*)&g_qh[base1 + c] = *(u32*)&p1;
        }
    } else if (z == 1) {
#pragma unroll
        for (int j = 0; j < 8; j++) {
            int c = j * 8 + 2 * t4;
            float a0 = (c == 0) ? t0 : acc[j][0];
            float a2 = (c == 0) ? t1 : acc[j][2];
            bf16 h00, l00, h01, l01, h10, l10, h11, l11;
            bfsplit(a0, h00, l00);
            bfsplit(acc[j][1], h01, l01);
            bfsplit(a2, h10, l10);
            bfsplit(acc[j][3], h11, l11);
            __nv_bfloat162 ph0; ph0.x = h00; ph0.y = h01;
            __nv_bfloat162 pl0; pl0.x = l00; pl0.y = l01;
            __nv_bfloat162 ph1; ph1.x = h10; ph1.y = h11;
            __nv_bfloat162 pl1; pl1.x = l10; pl1.y = l11;
            *(u32*)&g_kh[base0 + c] = *(u32*)&ph0;
            *(u32*)&g_kl[base0 + c] = *(u32*)&pl0;
            *(u32*)&g_kh[base1 + c] = *(u32*)&ph1;
            *(u32*)&g_kl[base1 + c] = *(u32*)&pl1;
        }
    } else {
#pragma unroll
        for (int j = 0; j < 8; j++) {
            int c = j * 8 + 2 * t4;
            float a0 = (c == 0) ? t0 : acc[j][0];
            float a2 = (c == 0) ? t1 : acc[j][2];
            __nv_bfloat162 p0 = __floats2bfloat162_rn(a0, acc[j][1]);
            __nv_bfloat162 p1 = __floats2bfloat162_rn(a2, acc[j][3]);
            *(u32*)&g_vh[base0 + c] = *(u32*)&p0;
            *(u32*)&g_vh[base1 + c] = *(u32*)&p1;
        }
    }
}

// ---------------- Kernel 3: bf16 mma flash attention -------------------------
// 256 thr (8 warps), 128 queries/block (M=16/warp). Key tiles of 64, 2-stage
// cp.async, 2 CTAs/SM. QK: qh*kh + qh*kl (2 MMA / k16). PV: P_bf16 x V_hi.
// No online max (hyperboloid: logits bounded in [~-2.5, -0.088]).
#define QT 128
#define KT 64
#define NTILES 32

#define KSTR 72                        // bf16 stride (144B rows)
#define TBUF (64 * KSTR)               // 4608 bf16
#define KH_OFF 0
#define KL_OFF (2 * TBUF)              // 9216
#define VH_OFF (4 * TBUF)              // 18432
#define P_OFF  (6 * TBUF)              // 27648
#define PW_SZ  (16 * KSTR)             // 1152
#define ASM_BYTES ((P_OFF + 8 * PW_SZ) * 2)   // 73728

__global__ void __launch_bounds__(256, 2) attn_mma()
{
    extern __shared__ bf16 smbf[];
    u32 smb = (u32)__cvta_generic_to_shared(smbf);

    const int tid = threadIdx.x;
    const int wid = tid >> 5;
    const int lane = tid & 31;
    const int g = lane >> 2;
    const int t4 = lane & 3;
    const int mi = lane >> 3, lr = lane & 7;
    const int a_row = (mi & 1) * 8 + lr;
    const int a_kb  = (mi >> 1) * 16;
    const int b_row = (mi >> 1) * 8 + lr;
    const int b_kb  = (mi & 1) * 16;

    const int qt = blockIdx.x;
    const int bh = blockIdx.y;
    const int n0 = qt * QT;
    const int b = bh >> 3, h = bh & 7;

    // ---- persistent Q A-fragments (hi only), M=16 rows per warp ----
    u32 AH[4][4];
    {
        const bf16* qh = g_qh + ((size_t)bh * NN + n0 + wid * 16) * DD;
#pragma unroll
        for (int kk = 0; kk < 4; kk++) {
            int c = kk * 16 + 2 * t4;
            AH[kk][0] = *(const u32*)(qh + g * DD + c);
            AH[kk][1] = *(const u32*)(qh + (g + 8) * DD + c);
            AH[kk][2] = *(const u32*)(qh + g * DD + c + 8);
            AH[kk][3] = *(const u32*)(qh + (g + 8) * DD + c + 8);
        }
    }

    float O[8][4];
#pragma unroll
    for (int j = 0; j < 8; j++)
#pragma unroll
        for (int r = 0; r < 4; r++) O[j][r] = 0.f;
    float lac0 = 0.f, lac1 = 0.f;

    const bf16* khg = g_kh + (size_t)bh * NN * DD;
    const bf16* klg = g_kl + (size_t)bh * NN * DD;
    const bf16* vhg = g_vh + (size_t)bh * NN * DD;

    auto issue = [&](int tile, int buf) {
#pragma unroll
        for (int j = 0; j < 6; j++) {
            int idx = j * 256 + tid;
            int arr = idx >> 9;
            int w = idx & 511;
            int row = w >> 3, c = w & 7;
            const bf16* src = (arr == 0 ? khg : (arr == 1 ? klg : vhg))
                              + (size_t)(tile * KT + row) * DD + c * 8;
            u32 off = (arr == 0 ? KH_OFF : (arr == 1 ? KL_OFF : VH_OFF));
            cpa16(smb + (off + buf * TBUF + row * KSTR) * 2 + c * 16, src);
        }
        cpa_commit();
    };

    issue(0, 0);
    issue(1, 1);

    u32 pwb = smb + (P_OFF + wid * PW_SZ) * 2;
    bf16* pwp = smbf + P_OFF + wid * PW_SZ;

    for (int t = 0; t < NTILES; t++) {
        if (t + 1 < NTILES) asm volatile("cp.async.wait_group 1;" ::: "memory");
        else                asm volatile("cp.async.wait_group 0;" ::: "memory");
        __syncthreads();

        const int buf = t & 1;
        u32 khb = smb + (KH_OFF + buf * TBUF) * 2;
        u32 klb = smb + (KL_OFF + buf * TBUF) * 2;
        u32 vhb = smb + (VH_OFF + buf * TBUF) * 2;

        // ---- S = Q K^T  (qh*kh + qh*kl) ----
        float S[8][4];
#pragma unroll
        for (int j = 0; j < 8; j++)
#pragma unroll
            for (int r = 0; r < 4; r++) S[j][r] = 0.f;

#pragma unroll
        for (int kk = 0; kk < 4; kk++) {
#pragma unroll
            for (int jj = 0; jj < 4; jj++) {
                u32 ko = (u32)(jj * 16 + b_row) * (KSTR * 2) + kk * 32 + b_kb;
                u32 BH[4], BL[4];
                ldm4(BH, khb + ko);
                ldm4(BL, klb + ko);
                mmabf(S[2 * jj],     AH[kk], BH[0], BH[1]);
                mmabf(S[2 * jj],     AH[kk], BL[0], BL[1]);
                mmabf(S[2 * jj + 1], AH[kk], BH[2], BH[3]);
                mmabf(S[2 * jj + 1], AH[kk], BL[2], BL[3]);
            }
        }

        // ---- exp (logits bounded; l from exact fp32 p), P -> bf16 smem ----
#pragma unroll
        for (int j = 0; j < 8; j++) {
            float p0 = __expf(S[j][0]);
            float p1 = __expf(S[j][1]);
            float p2 = __expf(S[j][2]);
            float p3 = __expf(S[j][3]);
            lac0 += p0 + p1;
            lac1 += p2 + p3;
            int col = j * 8 + 2 * t4;
            __nv_bfloat162 lop = __floats2bfloat162_rn(p0, p1);
            __nv_bfloat162 hip = __floats2bfloat162_rn(p2, p3);
            *(u32*)(pwp + g * KSTR + col) = *(u32*)&lop;
            *(u32*)(pwp + (g + 8) * KSTR + col) = *(u32*)&hip;
        }
        __syncwarp();

        // ---- O += P V  (ldmatrix A from P smem; trans ldmatrix for V) ----
#pragma unroll
        for (int kk = 0; kk < 4; kk++) {
            u32 PA[4];
            ldm4(PA, pwb + (u32)a_row * (KSTR * 2) + kk * 32 + a_kb);
#pragma unroll
            for (int jj = 0; jj < 4; jj++) {
                u32 BV[4];
                ldm4t(BV, vhb + (u32)(kk * 16 + a_row) * (KSTR * 2) + jj * 32 + a_kb);
                mmabf(O[2 * jj],     PA, BV[0], BV[1]);
                mmabf(O[2 * jj + 1], PA, BV[2], BV[3]);
            }
        }
        __syncwarp();

        __syncthreads();
        if (t + 2 < NTILES) issue(t + 2, buf);
    }

    // ---- epilogue ----
    lac0 += __shfl_xor_sync(0xffffffffu, lac0, 1);
    lac0 += __shfl_xor_sync(0xffffffffu, lac0, 2);
    lac1 += __shfl_xor_sync(0xffffffffu, lac1, 1);
    lac1 += __shfl_xor_sync(0xffffffffu, lac1, 2);
    float inv0 = 1.0f / lac0;
    float inv1 = 1.0f / lac1;

    int nq0 = n0 + wid * 16 + g;
    int nq1 = nq0 + 8;
    float* d0 = g_ave + (((size_t)(b * NN + nq0)) * HH + h) * DD;
    float* d1 = g_ave + (((size_t)(b * NN + nq1)) * HH + h) * DD;
#pragma unroll
    for (int j = 0; j < 8; j++) {
        int dcol = j * 8 + 2 * t4;
        *(float2*)&d0[dcol] = make_float2(O[j][0] * inv0, O[j][1] * inv0);
        *(float2*)&d1[dcol] = make_float2(O[j][2] * inv1, O[j][3] * inv1);
    }
}

// ---------------- Kernel 4: centroid epilogue -------------------------------
__device__ __forceinline__ float warp_sum(float v)
{
#pragma unroll
    for (int o = 16; o; o >>= 1) v += __shfl_xor_sync(0xffffffffu, v, o);
    return v;
}

__global__ void __launch_bounds__(256) centroid_kernel(float* __restrict__ out)
{
    int w = (blockIdx.x * blockDim.x + threadIdx.x) >> 5;
    int lane = threadIdx.x & 31;
    float m0 = 0.f, m1 = 0.f;
#pragma unroll
    for (int h = 0; h < HH; h++) {
        const float* a = g_ave + ((size_t)w * HH + h) * DD;
        float a0 = a[lane], a1 = a[lane + 32];
        float part = a0 * a0 + a1 * a1;
        if (lane == 0) part -= 2.0f * a0 * a0;
        float inner = warp_sum(part);
        float denom = sqrtf(fmaxf(fabsf(inner), 1e-8f));
        float inv = 1.0f / denom;
        m0 += a0 * inv; m1 += a1 * inv;
    }
    m0 *= (1.0f / HH); m1 *= (1.0f / HH);
    float part = m0 * m0 + m1 * m1;
    if (lane == 0) part -= 2.0f * m0 * m0;
    float inner = warp_sum(part);
    float denom = sqrtf(fmaxf(fabsf(inner), 1e-8f));
    float inv = 1.0f / denom;
    out[(size_t)w * DD + lane] = m0 * inv;
    out[(size_t)w * DD + lane + 32] = m1 * inv;
}

// ---------------- launch -----------------------------------------------------
extern "C" void kernel_launch(void* const* d_in, const int* in_sizes, int n_in,
                              void* d_out, int out_size)
{
    const float* query  = (const float*)d_in[0];
    const float* source = (const float*)d_in[1];
    const float* Wq = (const float*)d_in[2];
    const float* bq = (const float*)d_in[3];
    const float* Wk = (const float*)d_in[4];
    const float* bk = (const float*)d_in[5];
    const float* Wv = (const float*)d_in[6];
    const float* bv = (const float*)d_in[7];
    const float* scale = (const float*)d_in[8];
    float* out = (float*)d_out;

    cudaFuncSetAttribute(gemm_lift, cudaFuncAttributeMaxDynamicSharedMemorySize, GSM_BYTES);
    cudaFuncSetAttribute(attn_mma, cudaFuncAttributeMaxDynamicSharedMemorySize, ASM_BYTES);

    // total split elements: 2*ROWS*EE + 3*EE*EE, processed 2 per thread
    int split_blocks = (2 * ROWS * EE + 3 * EE * EE) / 2 / 256;
    split_all<<<split_blocks, 256>>>(query, source, Wq, Wk, Wv);

    gemm_lift<<<dim3(ROWS / 128, HH, 3), 256, GSM_BYTES>>>(bq, bk, bv, scale);

    attn_mma<<<dim3(NN / QT, BHN), 256, ASM_BYTES>>>();

    centroid_kernel<<<ROWS * 32 / 256, 256>>>(out);
}

// round 13
// speedup vs baseline: 8.4898x; 1.0579x over previous
#include <cuda_runtime.h>
#include <cuda_bf16.h>
#include <cstdint>

// Problem constants
#define BB 2
#define NN 2048
#define HH 8
#define EE 512
#define DOUT 504          // H * 63
#define DD 64             // lifted dim
#define ROWS 4096         // B*N
#define BHN (BB*HH)       // 16

typedef unsigned long long u64;
typedef uint32_t u32;
typedef __nv_bfloat16 bf16;

// ---------------- scratch (device globals; no allocation allowed) ----------
__device__ alignas(16) bf16 g_ah[2 * ROWS * EE];    // input splits (query, source)
__device__ alignas(16) bf16 g_al[2 * ROWS * EE];
__device__ alignas(16) bf16 g_wh[3 * EE * EE];      // W splits, head-padded rows (h*64+d)
__device__ alignas(16) bf16 g_wl[3 * EE * EE];
__device__ alignas(16) bf16 g_qh[BHN * NN * DD];    // lifted q (sign+scale folded, hi only)
__device__ alignas(16) bf16 g_kh[BHN * NN * DD];
__device__ alignas(16) bf16 g_kl[BHN * NN * DD];
__device__ alignas(16) bf16 g_vh[BHN * NN * DD];    // lifted v (hi only)
__device__ float g_ave[ROWS * HH * DD];             // attention output per head

// ---------------- helpers ----------------------------------------------------
__device__ __forceinline__ void bfsplit(float x, bf16& hi, bf16& lo) {
    hi = __float2bfloat16_rn(x);
    lo = __float2bfloat16_rn(x - __bfloat162float(hi));
}
__device__ __forceinline__ void cpa16(u32 dst, const void* src) {
    asm volatile("cp.async.cg.shared.global [%0], [%1], 16;" :: "r"(dst), "l"(src));
}
__device__ __forceinline__ void cpa_commit() {
    asm volatile("cp.async.commit_group;" ::: "memory");
}
__device__ __forceinline__ void mmabf(float* d, const u32* a, u32 b0, u32 b1) {
    asm volatile("mma.sync.aligned.m16n8k16.row.col.f32.bf16.bf16.f32 "
        "{%0,%1,%2,%3}, {%4,%5,%6,%7}, {%8,%9}, {%0,%1,%2,%3};"
        : "+f"(d[0]), "+f"(d[1]), "+f"(d[2]), "+f"(d[3])
        : "r"(a[0]), "r"(a[1]), "r"(a[2]), "r"(a[3]), "r"(b0), "r"(b1));
}
__device__ __forceinline__ void ldm4(u32* r, u32 addr) {
    asm volatile("ldmatrix.sync.aligned.m8n8.x4.shared.b16 {%0,%1,%2,%3}, [%4];"
        : "=r"(r[0]), "=r"(r[1]), "=r"(r[2]), "=r"(r[3]) : "r"(addr));
}
__device__ __forceinline__ void ldm4t(u32* r, u32 addr) {
    asm volatile("ldmatrix.sync.aligned.m8n8.x4.trans.shared.b16 {%0,%1,%2,%3}, [%4];"
        : "=r"(r[0]), "=r"(r[1]), "=r"(r[2]), "=r"(r[3]) : "r"(addr));
}

// ---------------- Kernel 0: fused split (inputs + head-padded weights) ------
// 4 elems/thread. inputs: straight bf16 hi/lo split. weights: padded row
// h*64+d; d==0 -> 0, d>=1 -> original row h*63+(d-1).
__global__ void __launch_bounds__(256) split_all(
    const float* __restrict__ q, const float* __restrict__ s,
    const float* __restrict__ Wq, const float* __restrict__ Wk,
    const float* __restrict__ Wv)
{
    int i = (blockIdx.x * blockDim.x + threadIdx.x) * 4;
    const int half = ROWS * EE;
    const int tot_in = 2 * half;
    float4 v;
    bf16* dh;
    bf16* dl;
    int o;
    if (i < tot_in) {
        v = (i < half) ? *(const float4*)(q + i) : *(const float4*)(s + i - half);
        dh = g_ah; dl = g_al; o = i;
    } else {
        int j = i - tot_in;
        int z = j / (EE * EE);
        int rem = j - z * (EE * EE);
        int row = rem >> 9;
        int col = rem & 511;
        int d = row & 63, h = row >> 6;
        const float* W = (z == 0) ? Wq : (z == 1 ? Wk : Wv);
        v = make_float4(0.f, 0.f, 0.f, 0.f);
        if (d > 0) v = *(const float4*)(W + (size_t)(h * 63 + d - 1) * EE + col);
        dh = g_wh; dl = g_wl; o = j;
    }
    bf16 h0, l0, h1, l1, h2, l2, h3, l3;
    bfsplit(v.x, h0, l0);
    bfsplit(v.y, h1, l1);
    bfsplit(v.z, h2, l2);
    bfsplit(v.w, h3, l3);
    __nv_bfloat162 hh0; hh0.x = h0; hh0.y = h1;
    __nv_bfloat162 hh1; hh1.x = h2; hh1.y = h3;
    __nv_bfloat162 ll0; ll0.x = l0; ll0.y = l1;
    __nv_bfloat162 ll1; ll1.x = l2; ll1.y = l3;
    u64 ph, pl;
    asm("mov.b64 %0, {%1, %2};" : "=l"(ph) : "r"(*(u32*)&hh0), "r"(*(u32*)&hh1));
    asm("mov.b64 %0, {%1, %2};" : "=l"(pl) : "r"(*(u32*)&ll0), "r"(*(u32*)&ll1));
    *(u64*)&dh[o] = ph;
    *(u64*)&dl[o] = pl;
}

// ---------------- Kernel 1: QKV GEMM + fused hyperboloid lift ----------------
// Block: 256 thr, 8 warps along M (warp tile 16 x 64). Tile M=128, N=64
// (= exactly one head via padded-W layout), k-chunk 32, 2-stage cp.async,
// 3 CTAs/SM. Epilogue: row ||x||^2 via quad shfl -> t -> bf16 q/k/v directly.
#define ASTR 40                       // bf16 k-stride (80B rows)
#define ABUF (128 * ASTR)             // 5120
#define WBUF (64 * ASTR)              // 2560
#define GAH 0
#define GAL (2 * ABUF)                // 10240
#define GWH (4 * ABUF)                // 20480
#define GWL (GWH + 2 * WBUF)          // 25600
#define GSM_BYTES ((GWL + 2 * WBUF) * 2)   // 61440

__global__ void __launch_bounds__(256, 3) gemm_lift(
    const float* __restrict__ bq, const float* __restrict__ bk,
    const float* __restrict__ bv, const float* __restrict__ scale_ptr)
{
    extern __shared__ bf16 smbf[];
    u32 smb = (u32)__cvta_generic_to_shared(smbf);

    const int tid = threadIdx.x;
    const int wid = tid >> 5;
    const int lane = tid & 31;
    const int g = lane >> 2;
    const int t4 = lane & 3;
    const int mi = lane >> 3, lr = lane & 7;
    const int a_row = (mi & 1) * 8 + lr;
    const int a_kb  = (mi >> 1) * 16;
    const int b_row = (mi >> 1) * 8 + lr;
    const int b_kb  = (mi & 1) * 16;

    const int mTile = blockIdx.x * 128;
    const int h = blockIdx.y;          // head 0..7
    const int z = blockIdx.z;

    const bf16* ahg = g_ah + (size_t)(z ? 1 : 0) * ROWS * EE;
    const bf16* alg = g_al + (size_t)(z ? 1 : 0) * ROWS * EE;
    const bf16* whg = g_wh + (size_t)z * EE * EE;
    const bf16* wlg = g_wl + (size_t)z * EE * EE;

    float acc[8][4];
#pragma unroll
    for (int n = 0; n < 8; n++)
#pragma unroll
        for (int r = 0; r < 4; r++) acc[n][r] = 0.f;

    auto issue = [&](int chunk, int stg) {
        int k0 = chunk * 32;
#pragma unroll
        for (int it = 0; it < 2; it++) {
            int idx = it * 256 + tid;
            int row = idx >> 2, c = idx & 3;
            size_t go = (size_t)(mTile + row) * EE + k0 + c * 8;
            u32 so = row * (ASTR * 2) + c * 16;
            cpa16(smb + (GAH + stg * ABUF) * 2 + so, ahg + go);
            cpa16(smb + (GAL + stg * ABUF) * 2 + so, alg + go);
        }
        {
            int row = tid >> 2, c = tid & 3;
            size_t go = (size_t)(h * 64 + row) * EE + k0 + c * 8;
            u32 so = row * (ASTR * 2) + c * 16;
            cpa16(smb + (GWH + stg * WBUF) * 2 + so, whg + go);
            cpa16(smb + (GWL + stg * WBUF) * 2 + so, wlg + go);
        }
        cpa_commit();
    };

    issue(0, 0);
    issue(1, 1);

    const int NCH = EE / 32;   // 16
    for (int t = 0; t < NCH; t++) {
        if (t + 1 < NCH) asm volatile("cp.async.wait_group 1;" ::: "memory");
        else             asm volatile("cp.async.wait_group 0;" ::: "memory");
        __syncthreads();

        const int stg = t & 1;
        u32 ahb = smb + (GAH + stg * ABUF) * 2;
        u32 alb = smb + (GAL + stg * ABUF) * 2;
        u32 whb = smb + (GWH + stg * WBUF) * 2;
        u32 wlb = smb + (GWL + stg * WBUF) * 2;

#pragma unroll
        for (int kk = 0; kk < 2; kk++) {
            u32 AHf[4], ALf[4];
            u32 ao = (u32)(wid * 16 + a_row) * (ASTR * 2) + kk * 32 + a_kb;
            ldm4(AHf, ahb + ao);
            ldm4(ALf, alb + ao);
#pragma unroll
            for (int nt = 0; nt < 4; nt++) {
                u32 WH[4], WL[4];
                u32 wo = (u32)(nt * 16 + b_row) * (ASTR * 2) + kk * 32 + b_kb;
                ldm4(WH, whb + wo);
                ldm4(WL, wlb + wo);
                mmabf(acc[2 * nt],     AHf, WH[0], WH[1]);
                mmabf(acc[2 * nt],     AHf, WL[0], WL[1]);
                mmabf(acc[2 * nt],     ALf, WH[0], WH[1]);
                mmabf(acc[2 * nt + 1], AHf, WH[2], WH[3]);
                mmabf(acc[2 * nt + 1], AHf, WL[2], WL[3]);
                mmabf(acc[2 * nt + 1], ALf, WH[2], WH[3]);
            }
        }
        __syncthreads();
        if (t + 2 < NCH) issue(t + 2, stg);
    }

    // ---- fused lift epilogue ----
    const float* bias = (z == 0) ? bq : (z == 1 ? bk : bv);
    float s0 = 0.f, s1 = 0.f;
#pragma unroll
    for (int j = 0; j < 8; j++) {
        int c = j * 8 + 2 * t4;
        float b0 = (c == 0) ? 0.f : __ldg(&bias[h * 63 + c - 1]);
        float b1 = __ldg(&bias[h * 63 + c]);
        acc[j][0] += b0;  acc[j][1] += b1;
        acc[j][2] += b0;  acc[j][3] += b1;
        s0 += acc[j][0] * acc[j][0] + acc[j][1] * acc[j][1];
        s1 += acc[j][2] * acc[j][2] + acc[j][3] * acc[j][3];
    }
    s0 += __shfl_xor_sync(0xffffffffu, s0, 1);
    s0 += __shfl_xor_sync(0xffffffffu, s0, 2);
    s1 += __shfl_xor_sync(0xffffffffu, s1, 1);
    s1 += __shfl_xor_sync(0xffffffffu, s1, 2);
    float t0 = sqrtf(s0 + 1.0f);
    float t1 = sqrtf(s1 + 1.0f);

    int n0 = mTile + wid * 16 + g;      // global row (0..4095)
    int n1 = n0 + 8;
    int b0i = n0 >> 11;
    int bh = b0i * HH + h;
    size_t base0 = ((size_t)bh * NN + (n0 & (NN - 1))) * DD;
    size_t base1 = ((size_t)bh * NN + (n1 & (NN - 1))) * DD;

    if (z == 0) {
        float sc = 2.0f / __ldg(scale_ptr);
#pragma unroll
        for (int j = 0; j < 8; j++) {
            int c = j * 8 + 2 * t4;
            float a0 = (c == 0) ? -t0 : acc[j][0];
            float a2 = (c == 0) ? -t1 : acc[j][2];
            __nv_bfloat162 p0 = __floats2bfloat162_rn(a0 * sc, acc[j][1] * sc);
            __nv_bfloat162 p1 = __floats2bfloat162_rn(a2 * sc, acc[j][3] * sc);
            *(u32*)&g_qh[base0 + c] = *(u32*)&p0;
            *(u32*)&g_qh[base1 + c] = *(u32*)&p1;
        }
    } else if (z == 1) {
#pragma unroll
        for (int j = 0; j < 8; j++) {
            int c = j * 8 + 2 * t4;
            float a0 = (c == 0) ? t0 : acc[j][0];
            float a2 = (c == 0) ? t1 : acc[j][2];
            bf16 h00, l00, h01, l01, h10, l10, h11, l11;
            bfsplit(a0, h00, l00);
            bfsplit(acc[j][1], h01, l01);
            bfsplit(a2, h10, l10);
            bfsplit(acc[j][3], h11, l11);
            __nv_bfloat162 ph0; ph0.x = h00; ph0.y = h01;
            __nv_bfloat162 pl0; pl0.x = l00; pl0.y = l01;
            __nv_bfloat162 ph1; ph1.x = h10; ph1.y = h11;
            __nv_bfloat162 pl1; pl1.x = l10; pl1.y = l11;
            *(u32*)&g_kh[base0 + c] = *(u32*)&ph0;
            *(u32*)&g_kl[base0 + c] = *(u32*)&pl0;
            *(u32*)&g_kh[base1 + c] = *(u32*)&ph1;
            *(u32*)&g_kl[base1 + c] = *(u32*)&pl1;
        }
    } else {
#pragma unroll
        for (int j = 0; j < 8; j++) {
            int c = j * 8 + 2 * t4;
            float a0 = (c == 0) ? t0 : acc[j][0];
            float a2 = (c == 0) ? t1 : acc[j][2];
            __nv_bfloat162 p0 = __floats2bfloat162_rn(a0, acc[j][1]);
            __nv_bfloat162 p1 = __floats2bfloat162_rn(a2, acc[j][3]);
            *(u32*)&g_vh[base0 + c] = *(u32*)&p0;
            *(u32*)&g_vh[base1 + c] = *(u32*)&p1;
        }
    }
}

// ---------------- Kernel 3: bf16 mma flash attention -------------------------
// 256 thr (8 warps), 128 queries/block (M=16/warp). Key tiles of 64, 2-stage
// cp.async, 2 CTAs/SM. QK: qh*kh + qh*kl (2 MMA / k16). PV: P_bf16 x V_hi.
// No online max (hyperboloid: logits bounded in [~-2.5, -0.088]).
#define QT 128
#define KT 64
#define NTILES 32

#define KSTR 72                        // bf16 stride (144B rows)
#define TBUF (64 * KSTR)               // 4608 bf16
#define KH_OFF 0
#define KL_OFF (2 * TBUF)              // 9216
#define VH_OFF (4 * TBUF)              // 18432
#define P_OFF  (6 * TBUF)              // 27648
#define PW_SZ  (16 * KSTR)             // 1152
#define ASM_BYTES ((P_OFF + 8 * PW_SZ) * 2)   // 73728

__global__ void __launch_bounds__(256, 2) attn_mma()
{
    extern __shared__ bf16 smbf[];
    u32 smb = (u32)__cvta_generic_to_shared(smbf);

    const int tid = threadIdx.x;
    const int wid = tid >> 5;
    const int lane = tid & 31;
    const int g = lane >> 2;
    const int t4 = lane & 3;
    const int mi = lane >> 3, lr = lane & 7;
    const int a_row = (mi & 1) * 8 + lr;
    const int a_kb  = (mi >> 1) * 16;
    const int b_row = (mi >> 1) * 8 + lr;
    const int b_kb  = (mi & 1) * 16;

    const int qt = blockIdx.x;
    const int bh = blockIdx.y;
    const int n0 = qt * QT;
    const int b = bh >> 3, h = bh & 7;

    // ---- persistent Q A-fragments (hi only), M=16 rows per warp ----
    u32 AH[4][4];
    {
        const bf16* qh = g_qh + ((size_t)bh * NN + n0 + wid * 16) * DD;
#pragma unroll
        for (int kk = 0; kk < 4; kk++) {
            int c = kk * 16 + 2 * t4;
            AH[kk][0] = *(const u32*)(qh + g * DD + c);
            AH[kk][1] = *(const u32*)(qh + (g + 8) * DD + c);
            AH[kk][2] = *(const u32*)(qh + g * DD + c + 8);
            AH[kk][3] = *(const u32*)(qh + (g + 8) * DD + c + 8);
        }
    }

    float O[8][4];
#pragma unroll
    for (int j = 0; j < 8; j++)
#pragma unroll
        for (int r = 0; r < 4; r++) O[j][r] = 0.f;
    float lac0 = 0.f, lac1 = 0.f;

    const bf16* khg = g_kh + (size_t)bh * NN * DD;
    const bf16* klg = g_kl + (size_t)bh * NN * DD;
    const bf16* vhg = g_vh + (size_t)bh * NN * DD;

    auto issue = [&](int tile, int buf) {
#pragma unroll
        for (int j = 0; j < 6; j++) {
            int idx = j * 256 + tid;
            int arr = idx >> 9;
            int w = idx & 511;
            int row = w >> 3, c = w & 7;
            const bf16* src = (arr == 0 ? khg : (arr == 1 ? klg : vhg))
                              + (size_t)(tile * KT + row) * DD + c * 8;
            u32 off = (arr == 0 ? KH_OFF : (arr == 1 ? KL_OFF : VH_OFF));
            cpa16(smb + (off + buf * TBUF + row * KSTR) * 2 + c * 16, src);
        }
        cpa_commit();
    };

    issue(0, 0);
    issue(1, 1);

    u32 pwb = smb + (P_OFF + wid * PW_SZ) * 2;
    bf16* pwp = smbf + P_OFF + wid * PW_SZ;

    for (int t = 0; t < NTILES; t++) {
        if (t + 1 < NTILES) asm volatile("cp.async.wait_group 1;" ::: "memory");
        else                asm volatile("cp.async.wait_group 0;" ::: "memory");
        __syncthreads();

        const int buf = t & 1;
        u32 khb = smb + (KH_OFF + buf * TBUF) * 2;
        u32 klb = smb + (KL_OFF + buf * TBUF) * 2;
        u32 vhb = smb + (VH_OFF + buf * TBUF) * 2;

        // ---- S = Q K^T  (qh*kh + qh*kl) ----
        float S[8][4];
#pragma unroll
        for (int j = 0; j < 8; j++)
#pragma unroll
            for (int r = 0; r < 4; r++) S[j][r] = 0.f;

#pragma unroll
        for (int kk = 0; kk < 4; kk++) {
#pragma unroll
            for (int jj = 0; jj < 4; jj++) {
                u32 ko = (u32)(jj * 16 + b_row) * (KSTR * 2) + kk * 32 + b_kb;
                u32 BH[4], BL[4];
                ldm4(BH, khb + ko);
                ldm4(BL, klb + ko);
                mmabf(S[2 * jj],     AH[kk], BH[0], BH[1]);
                mmabf(S[2 * jj],     AH[kk], BL[0], BL[1]);
                mmabf(S[2 * jj + 1], AH[kk], BH[2], BH[3]);
                mmabf(S[2 * jj + 1], AH[kk], BL[2], BL[3]);
            }
        }

        // ---- exp (logits bounded; l from exact fp32 p), P -> bf16 smem ----
#pragma unroll
        for (int j = 0; j < 8; j++) {
            float p0 = __expf(S[j][0]);
            float p1 = __expf(S[j][1]);
            float p2 = __expf(S[j][2]);
            float p3 = __expf(S[j][3]);
            lac0 += p0 + p1;
            lac1 += p2 + p3;
            int col = j * 8 + 2 * t4;
            __nv_bfloat162 lop = __floats2bfloat162_rn(p0, p1);
            __nv_bfloat162 hip = __floats2bfloat162_rn(p2, p3);
            *(u32*)(pwp + g * KSTR + col) = *(u32*)&lop;
            *(u32*)(pwp + (g + 8) * KSTR + col) = *(u32*)&hip;
        }
        __syncwarp();

        // ---- O += P V  (ldmatrix A from P smem; trans ldmatrix for V) ----
#pragma unroll
        for (int kk = 0; kk < 4; kk++) {
            u32 PA[4];
            ldm4(PA, pwb + (u32)a_row * (KSTR * 2) + kk * 32 + a_kb);
#pragma unroll
            for (int jj = 0; jj < 4; jj++) {
                u32 BV[4];
                ldm4t(BV, vhb + (u32)(kk * 16 + a_row) * (KSTR * 2) + jj * 32 + a_kb);
                mmabf(O[2 * jj],     PA, BV[0], BV[1]);
                mmabf(O[2 * jj + 1], PA, BV[2], BV[3]);
            }
        }

        __syncthreads();
        if (t + 2 < NTILES) issue(t + 2, buf);
    }

    // ---- epilogue ----
    lac0 += __shfl_xor_sync(0xffffffffu, lac0, 1);
    lac0 += __shfl_xor_sync(0xffffffffu, lac0, 2);
    lac1 += __shfl_xor_sync(0xffffffffu, lac1, 1);
    lac1 += __shfl_xor_sync(0xffffffffu, lac1, 2);
    float inv0 = 1.0f / lac0;
    float inv1 = 1.0f / lac1;

    int nq0 = n0 + wid * 16 + g;
    int nq1 = nq0 + 8;
    float* d0 = g_ave + (((size_t)(b * NN + nq0)) * HH + h) * DD;
    float* d1 = g_ave + (((size_t)(b * NN + nq1)) * HH + h) * DD;
#pragma unroll
    for (int j = 0; j < 8; j++) {
        int dcol = j * 8 + 2 * t4;
        *(float2*)&d0[dcol] = make_float2(O[j][0] * inv0, O[j][1] * inv0);
        *(float2*)&d1[dcol] = make_float2(O[j][2] * inv1, O[j][3] * inv1);
    }
}

// ---------------- Kernel 4: centroid epilogue -------------------------------
// warp per (b,n): prefetch ALL 8 heads first (parallel loads), then 8
// independent interleaved shuffle-reduction chains.
__device__ __forceinline__ float warp_sum(float v)
{
#pragma unroll
    for (int o = 16; o; o >>= 1) v += __shfl_xor_sync(0xffffffffu, v, o);
    return v;
}

__global__ void __launch_bounds__(256) centroid_kernel(float* __restrict__ out)
{
    int w = (blockIdx.x * blockDim.x + threadIdx.x) >> 5;
    int lane = threadIdx.x & 31;
    const float* a = g_ave + (size_t)w * HH * DD;

    float a0[HH], a1[HH];
#pragma unroll
    for (int h = 0; h < HH; h++) {
        a0[h] = a[h * DD + lane];
        a1[h] = a[h * DD + lane + 32];
    }

    float part[HH];
#pragma unroll
    for (int h = 0; h < HH; h++) {
        part[h] = a0[h] * a0[h] + a1[h] * a1[h];
        if (lane == 0) part[h] -= 2.0f * a0[h] * a0[h];
    }
    // 8 independent reduction chains (ILP across h)
#pragma unroll
    for (int o = 16; o; o >>= 1) {
#pragma unroll
        for (int h = 0; h < HH; h++)
            part[h] += __shfl_xor_sync(0xffffffffu, part[h], o);
    }

    float m0 = 0.f, m1 = 0.f;
#pragma unroll
    for (int h = 0; h < HH; h++) {
        float inv = rsqrtf(fmaxf(fabsf(part[h]), 1e-8f));
        m0 += a0[h] * inv;
        m1 += a1[h] * inv;
    }
    m0 *= (1.0f / HH); m1 *= (1.0f / HH);
    float p = m0 * m0 + m1 * m1;
    if (lane == 0) p -= 2.0f * m0 * m0;
    float inner = warp_sum(p);
    float inv = rsqrtf(fmaxf(fabsf(inner), 1e-8f));
    out[(size_t)w * DD + lane] = m0 * inv;
    out[(size_t)w * DD + lane + 32] = m1 * inv;
}

// ---------------- launch -----------------------------------------------------
extern "C" void kernel_launch(void* const* d_in, const int* in_sizes, int n_in,
                              void* d_out, int out_size)
{
    const float* query  = (const float*)d_in[0];
    const float* source = (const float*)d_in[1];
    const float* Wq = (const float*)d_in[2];
    const float* bq = (const float*)d_in[3];
    const float* Wk = (const float*)d_in[4];
    const float* bk = (const float*)d_in[5];
    const float* Wv = (const float*)d_in[6];
    const float* bv = (const float*)d_in[7];
    const float* scale = (const float*)d_in[8];
    float* out = (float*)d_out;

    cudaFuncSetAttribute(gemm_lift, cudaFuncAttributeMaxDynamicSharedMemorySize, GSM_BYTES);
    cudaFuncSetAttribute(attn_mma, cudaFuncAttributeMaxDynamicSharedMemorySize, ASM_BYTES);

    // total split elements: 2*ROWS*EE + 3*EE*EE, processed 4 per thread
    int split_blocks = (2 * ROWS * EE + 3 * EE * EE) / 4 / 256;
    split_all<<<split_blocks, 256>>>(query, source, Wq, Wk, Wv);

    gemm_lift<<<dim3(ROWS / 128, HH, 3), 256, GSM_BYTES>>>(bq, bk, bv, scale);

    attn_mma<<<dim3(NN / QT, BHN), 256, ASM_BYTES>>>();

    centroid_kernel<<<ROWS * 32 / 256, 256>>>(out);
}

// round 14
// speedup vs baseline: 10.0988x; 1.1895x over previous
#include <cuda_runtime.h>
#include <cuda_bf16.h>
#include <cuda_fp16.h>
#include <cstdint>

// Problem constants
#define BB 2
#define NN 2048
#define HH 8
#define EE 512
#define DOUT 504          // H * 63
#define DD 64             // lifted dim
#define ROWS 4096         // B*N
#define BHN (BB*HH)       // 16

typedef unsigned long long u64;
typedef uint32_t u32;
typedef __nv_bfloat16 bf16;

// ---------------- scratch (device globals; no allocation allowed) ----------
__device__ alignas(16) bf16 g_ah[2 * ROWS * EE];    // input splits (query, source)
__device__ alignas(16) bf16 g_al[2 * ROWS * EE];
__device__ alignas(16) bf16 g_wh[3 * EE * EE];      // W splits, head-padded rows (h*64+d)
__device__ alignas(16) bf16 g_wl[3 * EE * EE];
__device__ alignas(16) __half g_qh[BHN * NN * DD];  // lifted q (sign, 2*log2e/scale folded)
__device__ alignas(16) __half g_kh[BHN * NN * DD];  // lifted k (single f16)
__device__ alignas(16) __half g_vh[BHN * NN * DD];  // lifted v (f16)
__device__ float g_ave[ROWS * HH * DD];             // attention output per head

// ---------------- helpers ----------------------------------------------------
__device__ __forceinline__ void bfsplit(float x, bf16& hi, bf16& lo) {
    hi = __float2bfloat16_rn(x);
    lo = __float2bfloat16_rn(x - __bfloat162float(hi));
}
__device__ __forceinline__ void cpa16(u32 dst, const void* src) {
    asm volatile("cp.async.cg.shared.global [%0], [%1], 16;" :: "r"(dst), "l"(src));
}
__device__ __forceinline__ void cpa_commit() {
    asm volatile("cp.async.commit_group;" ::: "memory");
}
__device__ __forceinline__ void mmabf(float* d, const u32* a, u32 b0, u32 b1) {
    asm volatile("mma.sync.aligned.m16n8k16.row.col.f32.bf16.bf16.f32 "
        "{%0,%1,%2,%3}, {%4,%5,%6,%7}, {%8,%9}, {%0,%1,%2,%3};"
        : "+f"(d[0]), "+f"(d[1]), "+f"(d[2]), "+f"(d[3])
        : "r"(a[0]), "r"(a[1]), "r"(a[2]), "r"(a[3]), "r"(b0), "r"(b1));
}
__device__ __forceinline__ void mmaf16(float* d, const u32* a, u32 b0, u32 b1) {
    asm volatile("mma.sync.aligned.m16n8k16.row.col.f32.f16.f16.f32 "
        "{%0,%1,%2,%3}, {%4,%5,%6,%7}, {%8,%9}, {%0,%1,%2,%3};"
        : "+f"(d[0]), "+f"(d[1]), "+f"(d[2]), "+f"(d[3])
        : "r"(a[0]), "r"(a[1]), "r"(a[2]), "r"(a[3]), "r"(b0), "r"(b1));
}
__device__ __forceinline__ void ldm4(u32* r, u32 addr) {
    asm volatile("ldmatrix.sync.aligned.m8n8.x4.shared.b16 {%0,%1,%2,%3}, [%4];"
        : "=r"(r[0]), "=r"(r[1]), "=r"(r[2]), "=r"(r[3]) : "r"(addr));
}
__device__ __forceinline__ void ldm4t(u32* r, u32 addr) {
    asm volatile("ldmatrix.sync.aligned.m8n8.x4.trans.shared.b16 {%0,%1,%2,%3}, [%4];"
        : "=r"(r[0]), "=r"(r[1]), "=r"(r[2]), "=r"(r[3]) : "r"(addr));
}
// pack two f32 -> f16x2 (lo = first arg)
__device__ __forceinline__ u32 f16x2pack(float lo, float hi) {
    u32 r;
    asm("cvt.rn.f16x2.f32 %0, %1, %2;" : "=r"(r) : "f"(hi), "f"(lo));
    return r;
}
__device__ __forceinline__ u32 ex2h2(u32 s) {
    u32 r;
    asm("ex2.approx.f16x2 %0, %1;" : "=r"(r) : "r"(s));
    return r;
}

// ---------------- Kernel 0: fused split (inputs + head-padded weights) ------
// 4 elems/thread. inputs: straight bf16 hi/lo split. weights: padded row
// h*64+d; d==0 -> 0, d>=1 -> original row h*63+(d-1).
__global__ void __launch_bounds__(256) split_all(
    const float* __restrict__ q, const float* __restrict__ s,
    const float* __restrict__ Wq, const float* __restrict__ Wk,
    const float* __restrict__ Wv)
{
    int i = (blockIdx.x * blockDim.x + threadIdx.x) * 4;
    const int half = ROWS * EE;
    const int tot_in = 2 * half;
    float4 v;
    bf16* dh;
    bf16* dl;
    int o;
    if (i < tot_in) {
        v = (i < half) ? *(const float4*)(q + i) : *(const float4*)(s + i - half);
        dh = g_ah; dl = g_al; o = i;
    } else {
        int j = i - tot_in;
        int z = j / (EE * EE);
        int rem = j - z * (EE * EE);
        int row = rem >> 9;
        int col = rem & 511;
        int d = row & 63, h = row >> 6;
        const float* W = (z == 0) ? Wq : (z == 1 ? Wk : Wv);
        v = make_float4(0.f, 0.f, 0.f, 0.f);
        if (d > 0) v = *(const float4*)(W + (size_t)(h * 63 + d - 1) * EE + col);
        dh = g_wh; dl = g_wl; o = j;
    }
    bf16 h0, l0, h1, l1, h2, l2, h3, l3;
    bfsplit(v.x, h0, l0);
    bfsplit(v.y, h1, l1);
    bfsplit(v.z, h2, l2);
    bfsplit(v.w, h3, l3);
    __nv_bfloat162 hh0; hh0.x = h0; hh0.y = h1;
    __nv_bfloat162 hh1; hh1.x = h2; hh1.y = h3;
    __nv_bfloat162 ll0; ll0.x = l0; ll0.y = l1;
    __nv_bfloat162 ll1; ll1.x = l2; ll1.y = l3;
    u64 ph, pl;
    asm("mov.b64 %0, {%1, %2};" : "=l"(ph) : "r"(*(u32*)&hh0), "r"(*(u32*)&hh1));
    asm("mov.b64 %0, {%1, %2};" : "=l"(pl) : "r"(*(u32*)&ll0), "r"(*(u32*)&ll1));
    *(u64*)&dh[o] = ph;
    *(u64*)&dl[o] = pl;
}

// ---------------- Kernel 1: QKV GEMM + fused hyperboloid lift ----------------
// Block: 256 thr, 8 warps along M (warp tile 16 x 64). Tile M=128, N=64
// (= exactly one head via padded-W layout), k-chunk 32, 2-stage cp.async,
// 3 CTAs/SM. Epilogue: row ||x||^2 via quad shfl -> t -> f16 q/k/v directly.
#define ASTR 40                       // bf16 k-stride (80B rows)
#define ABUF (128 * ASTR)             // 5120
#define WBUF (64 * ASTR)              // 2560
#define GAH 0
#define GAL (2 * ABUF)                // 10240
#define GWH (4 * ABUF)                // 20480
#define GWL (GWH + 2 * WBUF)          // 25600
#define GSM_BYTES ((GWL + 2 * WBUF) * 2)   // 61440

__global__ void __launch_bounds__(256, 3) gemm_lift(
    const float* __restrict__ bq, const float* __restrict__ bk,
    const float* __restrict__ bv, const float* __restrict__ scale_ptr)
{
    extern __shared__ bf16 smbf[];
    u32 smb = (u32)__cvta_generic_to_shared(smbf);

    const int tid = threadIdx.x;
    const int wid = tid >> 5;
    const int lane = tid & 31;
    const int g = lane >> 2;
    const int t4 = lane & 3;
    const int mi = lane >> 3, lr = lane & 7;
    const int a_row = (mi & 1) * 8 + lr;
    const int a_kb  = (mi >> 1) * 16;
    const int b_row = (mi >> 1) * 8 + lr;
    const int b_kb  = (mi & 1) * 16;

    const int mTile = blockIdx.x * 128;
    const int h = blockIdx.y;          // head 0..7
    const int z = blockIdx.z;

    const bf16* ahg = g_ah + (size_t)(z ? 1 : 0) * ROWS * EE;
    const bf16* alg = g_al + (size_t)(z ? 1 : 0) * ROWS * EE;
    const bf16* whg = g_wh + (size_t)z * EE * EE;
    const bf16* wlg = g_wl + (size_t)z * EE * EE;

    float acc[8][4];
#pragma unroll
    for (int n = 0; n < 8; n++)
#pragma unroll
        for (int r = 0; r < 4; r++) acc[n][r] = 0.f;

    auto issue = [&](int chunk, int stg) {
        int k0 = chunk * 32;
#pragma unroll
        for (int it = 0; it < 2; it++) {
            int idx = it * 256 + tid;
            int row = idx >> 2, c = idx & 3;
            size_t go = (size_t)(mTile + row) * EE + k0 + c * 8;
            u32 so = row * (ASTR * 2) + c * 16;
            cpa16(smb + (GAH + stg * ABUF) * 2 + so, ahg + go);
            cpa16(smb + (GAL + stg * ABUF) * 2 + so, alg + go);
        }
        {
            int row = tid >> 2, c = tid & 3;
            size_t go = (size_t)(h * 64 + row) * EE + k0 + c * 8;
            u32 so = row * (ASTR * 2) + c * 16;
            cpa16(smb + (GWH + stg * WBUF) * 2 + so, whg + go);
            cpa16(smb + (GWL + stg * WBUF) * 2 + so, wlg + go);
        }
        cpa_commit();
    };

    issue(0, 0);
    issue(1, 1);

    const int NCH = EE / 32;   // 16
    for (int t = 0; t < NCH; t++) {
        if (t + 1 < NCH) asm volatile("cp.async.wait_group 1;" ::: "memory");
        else             asm volatile("cp.async.wait_group 0;" ::: "memory");
        __syncthreads();

        const int stg = t & 1;
        u32 ahb = smb + (GAH + stg * ABUF) * 2;
        u32 alb = smb + (GAL + stg * ABUF) * 2;
        u32 whb = smb + (GWH + stg * WBUF) * 2;
        u32 wlb = smb + (GWL + stg * WBUF) * 2;

#pragma unroll
        for (int kk = 0; kk < 2; kk++) {
            u32 AHf[4], ALf[4];
            u32 ao = (u32)(wid * 16 + a_row) * (ASTR * 2) + kk * 32 + a_kb;
            ldm4(AHf, ahb + ao);
            ldm4(ALf, alb + ao);
#pragma unroll
            for (int nt = 0; nt < 4; nt++) {
                u32 WH[4], WL[4];
                u32 wo = (u32)(nt * 16 + b_row) * (ASTR * 2) + kk * 32 + b_kb;
                ldm4(WH, whb + wo);
                ldm4(WL, wlb + wo);
                mmabf(acc[2 * nt],     AHf, WH[0], WH[1]);
                mmabf(acc[2 * nt],     AHf, WL[0], WL[1]);
                mmabf(acc[2 * nt],     ALf, WH[0], WH[1]);
                mmabf(acc[2 * nt + 1], AHf, WH[2], WH[3]);
                mmabf(acc[2 * nt + 1], AHf, WL[2], WL[3]);
                mmabf(acc[2 * nt + 1], ALf, WH[2], WH[3]);
            }
        }
        __syncthreads();
        if (t + 2 < NCH) issue(t + 2, stg);
    }

    // ---- fused lift epilogue ----
    const float* bias = (z == 0) ? bq : (z == 1 ? bk : bv);
    float s0 = 0.f, s1 = 0.f;
#pragma unroll
    for (int j = 0; j < 8; j++) {
        int c = j * 8 + 2 * t4;
        float b0 = (c == 0) ? 0.f : __ldg(&bias[h * 63 + c - 1]);
        float b1 = __ldg(&bias[h * 63 + c]);
        acc[j][0] += b0;  acc[j][1] += b1;
        acc[j][2] += b0;  acc[j][3] += b1;
        s0 += acc[j][0] * acc[j][0] + acc[j][1] * acc[j][1];
        s1 += acc[j][2] * acc[j][2] + acc[j][3] * acc[j][3];
    }
    s0 += __shfl_xor_sync(0xffffffffu, s0, 1);
    s0 += __shfl_xor_sync(0xffffffffu, s0, 2);
    s1 += __shfl_xor_sync(0xffffffffu, s1, 1);
    s1 += __shfl_xor_sync(0xffffffffu, s1, 2);
    float t0 = sqrtf(s0 + 1.0f);
    float t1 = sqrtf(s1 + 1.0f);

    int n0 = mTile + wid * 16 + g;      // global row (0..4095)
    int n1 = n0 + 8;
    int b0i = n0 >> 11;
    int bh = b0i * HH + h;
    size_t base0 = ((size_t)bh * NN + (n0 & (NN - 1))) * DD;
    size_t base1 = ((size_t)bh * NN + (n1 & (NN - 1))) * DD;

    if (z == 0) {
        // fold 2/scale AND log2(e) so attention exp becomes ex2
        float sc = (2.0f * 1.44269504088896f) / __ldg(scale_ptr);
#pragma unroll
        for (int j = 0; j < 8; j++) {
            int c = j * 8 + 2 * t4;
            float a0 = (c == 0) ? -t0 : acc[j][0];
            float a2 = (c == 0) ? -t1 : acc[j][2];
            __half2 p0 = __floats2half2_rn(a0 * sc, acc[j][1] * sc);
            __half2 p1 = __floats2half2_rn(a2 * sc, acc[j][3] * sc);
            *(u32*)&g_qh[base0 + c] = *(u32*)&p0;
            *(u32*)&g_qh[base1 + c] = *(u32*)&p1;
        }
    } else if (z == 1) {
#pragma unroll
        for (int j = 0; j < 8; j++) {
            int c = j * 8 + 2 * t4;
            float a0 = (c == 0) ? t0 : acc[j][0];
            float a2 = (c == 0) ? t1 : acc[j][2];
            __half2 p0 = __floats2half2_rn(a0, acc[j][1]);
            __half2 p1 = __floats2half2_rn(a2, acc[j][3]);
            *(u32*)&g_kh[base0 + c] = *(u32*)&p0;
            *(u32*)&g_kh[base1 + c] = *(u32*)&p1;
        }
    } else {
#pragma unroll
        for (int j = 0; j < 8; j++) {
            int c = j * 8 + 2 * t4;
            float a0 = (c == 0) ? t0 : acc[j][0];
            float a2 = (c == 0) ? t1 : acc[j][2];
            __half2 p0 = __floats2half2_rn(a0, acc[j][1]);
            __half2 p1 = __floats2half2_rn(a2, acc[j][3]);
            *(u32*)&g_vh[base0 + c] = *(u32*)&p0;
            *(u32*)&g_vh[base1 + c] = *(u32*)&p1;
        }
    }
}

// ---------------- Kernel 3: f16 mma flash attention --------------------------
// 256 thr (8 warps), 128 queries/block (M=16/warp). Key tiles of 64, 2-stage
// cp.async, 2 CTAs/SM. QK: q*k single f16 MMA per k16. exp via ex2.f16x2
// (log2e pre-folded into q). PV: P_f16 x V_f16.
// No online max (hyperboloid: log2-logits bounded in [~-3.6, -0.127]).
#define QT 128
#define KT 64
#define NTILES 32

#define KSTR 72                        // f16 stride (144B rows)
#define TBUF (64 * KSTR)               // 4608 halfs
#define KH_OFF 0
#define VH_OFF (2 * TBUF)              // 9216
#define P_OFF  (4 * TBUF)              // 18432
#define PW_SZ  (16 * KSTR)             // 1152
#define ASM_BYTES ((P_OFF + 8 * PW_SZ) * 2)   // 55296

__global__ void __launch_bounds__(256, 2) attn_mma()
{
    extern __shared__ __half smh[];
    u32 smb = (u32)__cvta_generic_to_shared(smh);

    const int tid = threadIdx.x;
    const int wid = tid >> 5;
    const int lane = tid & 31;
    const int g = lane >> 2;
    const int t4 = lane & 3;
    const int mi = lane >> 3, lr = lane & 7;
    const int a_row = (mi & 1) * 8 + lr;
    const int a_kb  = (mi >> 1) * 16;
    const int b_row = (mi >> 1) * 8 + lr;
    const int b_kb  = (mi & 1) * 16;

    const int qt = blockIdx.x;
    const int bh = blockIdx.y;
    const int n0 = qt * QT;
    const int b = bh >> 3, h = bh & 7;

    // ---- persistent Q A-fragments (f16), M=16 rows per warp ----
    u32 AH[4][4];
    {
        const __half* qh = g_qh + ((size_t)bh * NN + n0 + wid * 16) * DD;
#pragma unroll
        for (int kk = 0; kk < 4; kk++) {
            int c = kk * 16 + 2 * t4;
            AH[kk][0] = *(const u32*)(qh + g * DD + c);
            AH[kk][1] = *(const u32*)(qh + (g + 8) * DD + c);
            AH[kk][2] = *(const u32*)(qh + g * DD + c + 8);
            AH[kk][3] = *(const u32*)(qh + (g + 8) * DD + c + 8);
        }
    }

    float O[8][4];
#pragma unroll
    for (int j = 0; j < 8; j++)
#pragma unroll
        for (int r = 0; r < 4; r++) O[j][r] = 0.f;
    float lac0 = 0.f, lac1 = 0.f;

    const __half* khg = g_kh + (size_t)bh * NN * DD;
    const __half* vhg = g_vh + (size_t)bh * NN * DD;

    auto issue = [&](int tile, int buf) {
#pragma unroll
        for (int j = 0; j < 4; j++) {
            int idx = j * 256 + tid;
            int arr = idx >> 9;
            int w = idx & 511;
            int row = w >> 3, c = w & 7;
            const __half* src = (arr == 0 ? khg : vhg)
                                + (size_t)(tile * KT + row) * DD + c * 8;
            u32 off = (arr == 0 ? KH_OFF : VH_OFF);
            cpa16(smb + (off + buf * TBUF + row * KSTR) * 2 + c * 16, src);
        }
        cpa_commit();
    };

    issue(0, 0);
    issue(1, 1);

    u32 pwb = smb + (P_OFF + wid * PW_SZ) * 2;
    __half* pwp = smh + P_OFF + wid * PW_SZ;

    for (int t = 0; t < NTILES; t++) {
        if (t + 1 < NTILES) asm volatile("cp.async.wait_group 1;" ::: "memory");
        else                asm volatile("cp.async.wait_group 0;" ::: "memory");
        __syncthreads();

        const int buf = t & 1;
        u32 khb = smb + (KH_OFF + buf * TBUF) * 2;
        u32 vhb = smb + (VH_OFF + buf * TBUF) * 2;

        // ---- S = Q K^T  (single f16 MMA per k16) ----
        float S[8][4];
#pragma unroll
        for (int j = 0; j < 8; j++)
#pragma unroll
            for (int r = 0; r < 4; r++) S[j][r] = 0.f;

#pragma unroll
        for (int kk = 0; kk < 4; kk++) {
#pragma unroll
            for (int jj = 0; jj < 4; jj++) {
                u32 ko = (u32)(jj * 16 + b_row) * (KSTR * 2) + kk * 32 + b_kb;
                u32 BH[4];
                ldm4(BH, khb + ko);
                mmaf16(S[2 * jj],     AH[kk], BH[0], BH[1]);
                mmaf16(S[2 * jj + 1], AH[kk], BH[2], BH[3]);
            }
        }

        // ---- p = 2^s via packed f16 ex2 (log2e folded into q) ----
#pragma unroll
        for (int j = 0; j < 8; j++) {
            u32 s0 = f16x2pack(S[j][0], S[j][1]);
            u32 s1 = f16x2pack(S[j][2], S[j][3]);
            u32 p0 = ex2h2(s0);
            u32 p1 = ex2h2(s1);
            float2 f0 = __half22float2(*(__half2*)&p0);
            float2 f1 = __half22float2(*(__half2*)&p1);
            lac0 += f0.x + f0.y;
            lac1 += f1.x + f1.y;
            int col = j * 8 + 2 * t4;
            *(u32*)(pwp + g * KSTR + col) = p0;
            *(u32*)(pwp + (g + 8) * KSTR + col) = p1;
        }
        __syncwarp();

        // ---- O += P V  (f16 MMA; trans ldmatrix for V) ----
#pragma unroll
        for (int kk = 0; kk < 4; kk++) {
            u32 PA[4];
            ldm4(PA, pwb + (u32)a_row * (KSTR * 2) + kk * 32 + a_kb);
#pragma unroll
            for (int jj = 0; jj < 4; jj++) {
                u32 BV[4];
                ldm4t(BV, vhb + (u32)(kk * 16 + a_row) * (KSTR * 2) + jj * 32 + a_kb);
                mmaf16(O[2 * jj],     PA, BV[0], BV[1]);
                mmaf16(O[2 * jj + 1], PA, BV[2], BV[3]);
            }
        }

        __syncthreads();
        if (t + 2 < NTILES) issue(t + 2, buf);
    }

    // ---- epilogue ----
    lac0 += __shfl_xor_sync(0xffffffffu, lac0, 1);
    lac0 += __shfl_xor_sync(0xffffffffu, lac0, 2);
    lac1 += __shfl_xor_sync(0xffffffffu, lac1, 1);
    lac1 += __shfl_xor_sync(0xffffffffu, lac1, 2);
    float inv0 = 1.0f / lac0;
    float inv1 = 1.0f / lac1;

    int nq0 = n0 + wid * 16 + g;
    int nq1 = nq0 + 8;
    float* d0 = g_ave + (((size_t)(b * NN + nq0)) * HH + h) * DD;
    float* d1 = g_ave + (((size_t)(b * NN + nq1)) * HH + h) * DD;
#pragma unroll
    for (int j = 0; j < 8; j++) {
        int dcol = j * 8 + 2 * t4;
        *(float2*)&d0[dcol] = make_float2(O[j][0] * inv0, O[j][1] * inv0);
        *(float2*)&d1[dcol] = make_float2(O[j][2] * inv1, O[j][3] * inv1);
    }
}

// ---------------- Kernel 4: centroid epilogue -------------------------------
// warp per (b,n): prefetch ALL 8 heads first (parallel loads), then 8
// independent interleaved shuffle-reduction chains.
__device__ __forceinline__ float warp_sum(float v)
{
#pragma unroll
    for (int o = 16; o; o >>= 1) v += __shfl_xor_sync(0xffffffffu, v, o);
    return v;
}

__global__ void __launch_bounds__(256) centroid_kernel(float* __restrict__ out)
{
    int w = (blockIdx.x * blockDim.x + threadIdx.x) >> 5;
    int lane = threadIdx.x & 31;
    const float* a = g_ave + (size_t)w * HH * DD;

    float a0[HH], a1[HH];
#pragma unroll
    for (int h = 0; h < HH; h++) {
        a0[h] = a[h * DD + lane];
        a1[h] = a[h * DD + lane + 32];
    }

    float part[HH];
#pragma unroll
    for (int h = 0; h < HH; h++) {
        part[h] = a0[h] * a0[h] + a1[h] * a1[h];
        if (lane == 0) part[h] -= 2.0f * a0[h] * a0[h];
    }
    // 8 independent reduction chains (ILP across h)
#pragma unroll
    for (int o = 16; o; o >>= 1) {
#pragma unroll
        for (int h = 0; h < HH; h++)
            part[h] += __shfl_xor_sync(0xffffffffu, part[h], o);
    }

    float m0 = 0.f, m1 = 0.f;
#pragma unroll
    for (int h = 0; h < HH; h++) {
        float inv = rsqrtf(fmaxf(fabsf(part[h]), 1e-8f));
        m0 += a0[h] * inv;
        m1 += a1[h] * inv;
    }
    m0 *= (1.0f / HH); m1 *= (1.0f / HH);
    float p = m0 * m0 + m1 * m1;
    if (lane == 0) p -= 2.0f * m0 * m0;
    float inner = warp_sum(p);
    float inv = rsqrtf(fmaxf(fabsf(inner), 1e-8f));
    out[(size_t)w * DD + lane] = m0 * inv;
    out[(size_t)w * DD + lane + 32] = m1 * inv;
}

// ---------------- launch -----------------------------------------------------
extern "C" void kernel_launch(void* const* d_in, const int* in_sizes, int n_in,
                              void* d_out, int out_size)
{
    const float* query  = (const float*)d_in[0];
    const float* source = (const float*)d_in[1];
    const float* Wq = (const float*)d_in[2];
    const float* bq = (const float*)d_in[3];
    const float* Wk = (const float*)d_in[4];
    const float* bk = (const float*)d_in[5];
    const float* Wv = (const float*)d_in[6];
    const float* bv = (const float*)d_in[7];
    const float* scale = (const float*)d_in[8];
    float* out = (float*)d_out;

    cudaFuncSetAttribute(gemm_lift, cudaFuncAttributeMaxDynamicSharedMemorySize, GSM_BYTES);
    cudaFuncSetAttribute(attn_mma, cudaFuncAttributeMaxDynamicSharedMemorySize, ASM_BYTES);

    // total split elements: 2*ROWS*EE + 3*EE*EE, processed 4 per thread
    int split_blocks = (2 * ROWS * EE + 3 * EE * EE) / 4 / 256;
    split_all<<<split_blocks, 256>>>(query, source, Wq, Wk, Wv);

    gemm_lift<<<dim3(ROWS / 128, HH, 3), 256, GSM_BYTES>>>(bq, bk, bv, scale);

    attn_mma<<<dim3(NN / QT, BHN), 256, ASM_BYTES>>>();

    centroid_kernel<<<ROWS * 32 / 256, 256>>>(out);
}

// round 15
// speedup vs baseline: 11.6104x; 1.1497x over previous
#include <cuda_runtime.h>
#include <cuda_bf16.h>
#include <cuda_fp16.h>
#include <cstdint>

// Problem constants
#define BB 2
#define NN 2048
#define HH 8
#define EE 512
#define DOUT 504          // H * 63
#define DD 64             // lifted dim
#define ROWS 4096         // B*N
#define BHN (BB*HH)       // 16

typedef unsigned long long u64;
typedef uint32_t u32;

// ---------------- scratch (device globals; no allocation allowed) ----------
__device__ alignas(16) __half g_af[2 * ROWS * EE];  // inputs (query, source), f16
__device__ alignas(16) __half g_wh[3 * EE * EE];    // W f16 hi, head-padded rows (h*64+d)
__device__ alignas(16) __half g_wl[3 * EE * EE];    // W f16 lo
__device__ alignas(16) __half g_qh[BHN * NN * DD];  // lifted q (sign, 2*log2e/scale folded)
__device__ alignas(16) __half g_kh[BHN * NN * DD];  // lifted k (f16)
__device__ alignas(16) __half g_vh[BHN * NN * DD];  // lifted v (f16)
__device__ float g_ave[ROWS * HH * DD];             // attention output per head

// ---------------- helpers ----------------------------------------------------
__device__ __forceinline__ void f16split(float x, __half& hi, __half& lo) {
    hi = __float2half_rn(x);
    lo = __float2half_rn(x - __half2float(hi));
}
__device__ __forceinline__ void cpa16(u32 dst, const void* src) {
    asm volatile("cp.async.cg.shared.global [%0], [%1], 16;" :: "r"(dst), "l"(src));
}
__device__ __forceinline__ void cpa_commit() {
    asm volatile("cp.async.commit_group;" ::: "memory");
}
__device__ __forceinline__ void mmaf16(float* d, const u32* a, u32 b0, u32 b1) {
    asm volatile("mma.sync.aligned.m16n8k16.row.col.f32.f16.f16.f32 "
        "{%0,%1,%2,%3}, {%4,%5,%6,%7}, {%8,%9}, {%0,%1,%2,%3};"
        : "+f"(d[0]), "+f"(d[1]), "+f"(d[2]), "+f"(d[3])
        : "r"(a[0]), "r"(a[1]), "r"(a[2]), "r"(a[3]), "r"(b0), "r"(b1));
}
__device__ __forceinline__ void ldm4(u32* r, u32 addr) {
    asm volatile("ldmatrix.sync.aligned.m8n8.x4.shared.b16 {%0,%1,%2,%3}, [%4];"
        : "=r"(r[0]), "=r"(r[1]), "=r"(r[2]), "=r"(r[3]) : "r"(addr));
}
__device__ __forceinline__ void ldm4t(u32* r, u32 addr) {
    asm volatile("ldmatrix.sync.aligned.m8n8.x4.trans.shared.b16 {%0,%1,%2,%3}, [%4];"
        : "=r"(r[0]), "=r"(r[1]), "=r"(r[2]), "=r"(r[3]) : "r"(addr));
}
// pack two f32 -> f16x2 (lo = first arg)
__device__ __forceinline__ u32 f16x2pack(float lo, float hi) {
    u32 r;
    asm("cvt.rn.f16x2.f32 %0, %1, %2;" : "=r"(r) : "f"(hi), "f"(lo));
    return r;
}
__device__ __forceinline__ u32 ex2h2(u32 s) {
    u32 r;
    asm("ex2.approx.f16x2 %0, %1;" : "=r"(r) : "r"(s));
    return r;
}

// ---------------- Kernel 0: fused split (inputs f16 + weights f16 hi/lo) ----
// 4 elems/thread. weights use padded row h*64+d; d==0 -> 0, d>=1 -> h*63+(d-1).
__global__ void __launch_bounds__(256) split_all(
    const float* __restrict__ q, const float* __restrict__ s,
    const float* __restrict__ Wq, const float* __restrict__ Wk,
    const float* __restrict__ Wv)
{
    int i = (blockIdx.x * blockDim.x + threadIdx.x) * 4;
    const int half = ROWS * EE;
    const int tot_in = 2 * half;
    if (i < tot_in) {
        float4 v = (i < half) ? *(const float4*)(q + i) : *(const float4*)(s + i - half);
        __half2 p0 = __floats2half2_rn(v.x, v.y);
        __half2 p1 = __floats2half2_rn(v.z, v.w);
        u64 pk;
        asm("mov.b64 %0, {%1, %2};" : "=l"(pk) : "r"(*(u32*)&p0), "r"(*(u32*)&p1));
        *(u64*)&g_af[i] = pk;
    } else {
        int j = i - tot_in;
        int z = j / (EE * EE);
        int rem = j - z * (EE * EE);
        int row = rem >> 9;
        int col = rem & 511;
        int d = row & 63, h = row >> 6;
        const float* W = (z == 0) ? Wq : (z == 1 ? Wk : Wv);
        float4 v = make_float4(0.f, 0.f, 0.f, 0.f);
        if (d > 0) v = *(const float4*)(W + (size_t)(h * 63 + d - 1) * EE + col);
        __half h0, l0, h1, l1, h2, l2, h3, l3;
        f16split(v.x, h0, l0);
        f16split(v.y, h1, l1);
        f16split(v.z, h2, l2);
        f16split(v.w, h3, l3);
        __half2 hh0; hh0.x = h0; hh0.y = h1;
        __half2 hh1; hh1.x = h2; hh1.y = h3;
        __half2 ll0; ll0.x = l0; ll0.y = l1;
        __half2 ll1; ll1.x = l2; ll1.y = l3;
        u64 ph, pl;
        asm("mov.b64 %0, {%1, %2};" : "=l"(ph) : "r"(*(u32*)&hh0), "r"(*(u32*)&hh1));
        asm("mov.b64 %0, {%1, %2};" : "=l"(pl) : "r"(*(u32*)&ll0), "r"(*(u32*)&ll1));
        *(u64*)&g_wh[j] = ph;
        *(u64*)&g_wl[j] = pl;
    }
}

// ---------------- Kernel 1: QKV GEMM + fused hyperboloid lift ----------------
// Block: 256 thr, 8 warps along M (warp tile 16 x 64). Tile M=128, N=64
// (= one head via padded-W layout), k-chunk 32, 2-stage cp.async, 3 CTAs/SM.
// f16 A (single) x f16 W (hi+lo) = 2 MMAs. Epilogue: row ||x||^2 via quad
// shfl -> t -> f16 q/k/v directly.
#define ASTR 40                       // f16 k-stride (80B rows)
#define ABUF (128 * ASTR)             // 5120
#define WBUF (64 * ASTR)              // 2560
#define GAF 0
#define GWH (2 * ABUF)                // 10240
#define GWL (GWH + 2 * WBUF)          // 15360
#define GSM_BYTES ((GWL + 2 * WBUF) * 2)   // 40960

__global__ void __launch_bounds__(256, 3) gemm_lift(
    const float* __restrict__ bq, const float* __restrict__ bk,
    const float* __restrict__ bv, const float* __restrict__ scale_ptr)
{
    extern __shared__ __half smh[];
    u32 smb = (u32)__cvta_generic_to_shared(smh);

    const int tid = threadIdx.x;
    const int wid = tid >> 5;
    const int lane = tid & 31;
    const int g = lane >> 2;
    const int t4 = lane & 3;
    const int mi = lane >> 3, lr = lane & 7;
    const int a_row = (mi & 1) * 8 + lr;
    const int a_kb  = (mi >> 1) * 16;
    const int b_row = (mi >> 1) * 8 + lr;
    const int b_kb  = (mi & 1) * 16;

    const int mTile = blockIdx.x * 128;
    const int h = blockIdx.y;          // head 0..7
    const int z = blockIdx.z;

    const __half* afg = g_af + (size_t)(z ? 1 : 0) * ROWS * EE;
    const __half* whg = g_wh + (size_t)z * EE * EE;
    const __half* wlg = g_wl + (size_t)z * EE * EE;

    float acc[8][4];
#pragma unroll
    for (int n = 0; n < 8; n++)
#pragma unroll
        for (int r = 0; r < 4; r++) acc[n][r] = 0.f;

    auto issue = [&](int chunk, int stg) {
        int k0 = chunk * 32;
#pragma unroll
        for (int it = 0; it < 2; it++) {
            int idx = it * 256 + tid;
            int row = idx >> 2, c = idx & 3;
            size_t go = (size_t)(mTile + row) * EE + k0 + c * 8;
            u32 so = row * (ASTR * 2) + c * 16;
            cpa16(smb + (GAF + stg * ABUF) * 2 + so, afg + go);
        }
        {
            int row = tid >> 2, c = tid & 3;
            size_t go = (size_t)(h * 64 + row) * EE + k0 + c * 8;
            u32 so = row * (ASTR * 2) + c * 16;
            cpa16(smb + (GWH + stg * WBUF) * 2 + so, whg + go);
            cpa16(smb + (GWL + stg * WBUF) * 2 + so, wlg + go);
        }
        cpa_commit();
    };

    issue(0, 0);
    issue(1, 1);

    const int NCH = EE / 32;   // 16
    for (int t = 0; t < NCH; t++) {
        if (t + 1 < NCH) asm volatile("cp.async.wait_group 1;" ::: "memory");
        else             asm volatile("cp.async.wait_group 0;" ::: "memory");
        __syncthreads();

        const int stg = t & 1;
        u32 afb = smb + (GAF + stg * ABUF) * 2;
        u32 whb = smb + (GWH + stg * WBUF) * 2;
        u32 wlb = smb + (GWL + stg * WBUF) * 2;

#pragma unroll
        for (int kk = 0; kk < 2; kk++) {
            u32 AF[4];
            u32 ao = (u32)(wid * 16 + a_row) * (ASTR * 2) + kk * 32 + a_kb;
            ldm4(AF, afb + ao);
#pragma unroll
            for (int nt = 0; nt < 4; nt++) {
                u32 WH[4], WL[4];
                u32 wo = (u32)(nt * 16 + b_row) * (ASTR * 2) + kk * 32 + b_kb;
                ldm4(WH, whb + wo);
                ldm4(WL, wlb + wo);
                mmaf16(acc[2 * nt],     AF, WH[0], WH[1]);
                mmaf16(acc[2 * nt],     AF, WL[0], WL[1]);
                mmaf16(acc[2 * nt + 1], AF, WH[2], WH[3]);
                mmaf16(acc[2 * nt + 1], AF, WL[2], WL[3]);
            }
        }
        __syncthreads();
        if (t + 2 < NCH) issue(t + 2, stg);
    }

    // ---- fused lift epilogue ----
    const float* bias = (z == 0) ? bq : (z == 1 ? bk : bv);
    float s0 = 0.f, s1 = 0.f;
#pragma unroll
    for (int j = 0; j < 8; j++) {
        int c = j * 8 + 2 * t4;
        float b0 = (c == 0) ? 0.f : __ldg(&bias[h * 63 + c - 1]);
        float b1 = __ldg(&bias[h * 63 + c]);
        acc[j][0] += b0;  acc[j][1] += b1;
        acc[j][2] += b0;  acc[j][3] += b1;
        s0 += acc[j][0] * acc[j][0] + acc[j][1] * acc[j][1];
        s1 += acc[j][2] * acc[j][2] + acc[j][3] * acc[j][3];
    }
    s0 += __shfl_xor_sync(0xffffffffu, s0, 1);
    s0 += __shfl_xor_sync(0xffffffffu, s0, 2);
    s1 += __shfl_xor_sync(0xffffffffu, s1, 1);
    s1 += __shfl_xor_sync(0xffffffffu, s1, 2);
    float t0 = sqrtf(s0 + 1.0f);
    float t1 = sqrtf(s1 + 1.0f);

    int n0 = mTile + wid * 16 + g;      // global row (0..4095)
    int n1 = n0 + 8;
    int b0i = n0 >> 11;
    int bh = b0i * HH + h;
    size_t base0 = ((size_t)bh * NN + (n0 & (NN - 1))) * DD;
    size_t base1 = ((size_t)bh * NN + (n1 & (NN - 1))) * DD;

    if (z == 0) {
        // fold 2/scale AND log2(e) so attention exp becomes ex2
        float sc = (2.0f * 1.44269504088896f) / __ldg(scale_ptr);
#pragma unroll
        for (int j = 0; j < 8; j++) {
            int c = j * 8 + 2 * t4;
            float a0 = (c == 0) ? -t0 : acc[j][0];
            float a2 = (c == 0) ? -t1 : acc[j][2];
            __half2 p0 = __floats2half2_rn(a0 * sc, acc[j][1] * sc);
            __half2 p1 = __floats2half2_rn(a2 * sc, acc[j][3] * sc);
            *(u32*)&g_qh[base0 + c] = *(u32*)&p0;
            *(u32*)&g_qh[base1 + c] = *(u32*)&p1;
        }
    } else if (z == 1) {
#pragma unroll
        for (int j = 0; j < 8; j++) {
            int c = j * 8 + 2 * t4;
            float a0 = (c == 0) ? t0 : acc[j][0];
            float a2 = (c == 0) ? t1 : acc[j][2];
            __half2 p0 = __floats2half2_rn(a0, acc[j][1]);
            __half2 p1 = __floats2half2_rn(a2, acc[j][3]);
            *(u32*)&g_kh[base0 + c] = *(u32*)&p0;
            *(u32*)&g_kh[base1 + c] = *(u32*)&p1;
        }
    } else {
#pragma unroll
        for (int j = 0; j < 8; j++) {
            int c = j * 8 + 2 * t4;
            float a0 = (c == 0) ? t0 : acc[j][0];
            float a2 = (c == 0) ? t1 : acc[j][2];
            __half2 p0 = __floats2half2_rn(a0, acc[j][1]);
            __half2 p1 = __floats2half2_rn(a2, acc[j][3]);
            *(u32*)&g_vh[base0 + c] = *(u32*)&p0;
            *(u32*)&g_vh[base1 + c] = *(u32*)&p1;
        }
    }
}

// ---------------- Kernel 3: f16 mma flash attention --------------------------
// 256 thr (8 warps), 128 queries/block (M=16/warp). Key tiles of 64, 2-stage
// cp.async, 2 CTAs/SM. QK: q*k single f16 MMA per k16. exp via ex2.f16x2
// (log2e pre-folded into q). PV: P_f16 x V_f16.
// No online max (hyperboloid: log2-logits bounded in [~-3.6, -0.127]).
#define QT 128
#define KT 64
#define NTILES 32

#define KSTR 72                        // f16 stride (144B rows)
#define TBUF (64 * KSTR)               // 4608 halfs
#define KH_OFF 0
#define VH_OFF (2 * TBUF)              // 9216
#define P_OFF  (4 * TBUF)              // 18432
#define PW_SZ  (16 * KSTR)             // 1152
#define ASM_BYTES ((P_OFF + 8 * PW_SZ) * 2)   // 55296

__global__ void __launch_bounds__(256, 2) attn_mma()
{
    extern __shared__ __half smh[];
    u32 smb = (u32)__cvta_generic_to_shared(smh);

    const int tid = threadIdx.x;
    const int wid = tid >> 5;
    const int lane = tid & 31;
    const int g = lane >> 2;
    const int t4 = lane & 3;
    const int mi = lane >> 3, lr = lane & 7;
    const int a_row = (mi & 1) * 8 + lr;
    const int a_kb  = (mi >> 1) * 16;
    const int b_row = (mi >> 1) * 8 + lr;
    const int b_kb  = (mi & 1) * 16;

    const int qt = blockIdx.x;
    const int bh = blockIdx.y;
    const int n0 = qt * QT;
    const int b = bh >> 3, h = bh & 7;

    // ---- persistent Q A-fragments (f16), M=16 rows per warp ----
    u32 AH[4][4];
    {
        const __half* qh = g_qh + ((size_t)bh * NN + n0 + wid * 16) * DD;
#pragma unroll
        for (int kk = 0; kk < 4; kk++) {
            int c = kk * 16 + 2 * t4;
            AH[kk][0] = *(const u32*)(qh + g * DD + c);
            AH[kk][1] = *(const u32*)(qh + (g + 8) * DD + c);
            AH[kk][2] = *(const u32*)(qh + g * DD + c + 8);
            AH[kk][3] = *(const u32*)(qh + (g + 8) * DD + c + 8);
        }
    }

    float O[8][4];
#pragma unroll
    for (int j = 0; j < 8; j++)
#pragma unroll
        for (int r = 0; r < 4; r++) O[j][r] = 0.f;
    float lac0 = 0.f, lac1 = 0.f;

    const __half* khg = g_kh + (size_t)bh * NN * DD;
    const __half* vhg = g_vh + (size_t)bh * NN * DD;

    auto issue = [&](int tile, int buf) {
#pragma unroll
        for (int j = 0; j < 4; j++) {
            int idx = j * 256 + tid;
            int arr = idx >> 9;
            int w = idx & 511;
            int row = w >> 3, c = w & 7;
            const __half* src = (arr == 0 ? khg : vhg)
                                + (size_t)(tile * KT + row) * DD + c * 8;
            u32 off = (arr == 0 ? KH_OFF : VH_OFF);
            cpa16(smb + (off + buf * TBUF + row * KSTR) * 2 + c * 16, src);
        }
        cpa_commit();
    };

    issue(0, 0);
    issue(1, 1);

    u32 pwb = smb + (P_OFF + wid * PW_SZ) * 2;
    __half* pwp = smh + P_OFF + wid * PW_SZ;

    for (int t = 0; t < NTILES; t++) {
        if (t + 1 < NTILES) asm volatile("cp.async.wait_group 1;" ::: "memory");
        else                asm volatile("cp.async.wait_group 0;" ::: "memory");
        __syncthreads();

        const int buf = t & 1;
        u32 khb = smb + (KH_OFF + buf * TBUF) * 2;
        u32 vhb = smb + (VH_OFF + buf * TBUF) * 2;

        // ---- S = Q K^T  (single f16 MMA per k16) ----
        float S[8][4];
#pragma unroll
        for (int j = 0; j < 8; j++)
#pragma unroll
            for (int r = 0; r < 4; r++) S[j][r] = 0.f;

#pragma unroll
        for (int kk = 0; kk < 4; kk++) {
#pragma unroll
            for (int jj = 0; jj < 4; jj++) {
                u32 ko = (u32)(jj * 16 + b_row) * (KSTR * 2) + kk * 32 + b_kb;
                u32 BH[4];
                ldm4(BH, khb + ko);
                mmaf16(S[2 * jj],     AH[kk], BH[0], BH[1]);
                mmaf16(S[2 * jj + 1], AH[kk], BH[2], BH[3]);
            }
        }

        // ---- p = 2^s via packed f16 ex2 (log2e folded into q) ----
#pragma unroll
        for (int j = 0; j < 8; j++) {
            u32 s0 = f16x2pack(S[j][0], S[j][1]);
            u32 s1 = f16x2pack(S[j][2], S[j][3]);
            u32 p0 = ex2h2(s0);
            u32 p1 = ex2h2(s1);
            float2 f0 = __half22float2(*(__half2*)&p0);
            float2 f1 = __half22float2(*(__half2*)&p1);
            lac0 += f0.x + f0.y;
            lac1 += f1.x + f1.y;
            int col = j * 8 + 2 * t4;
            *(u32*)(pwp + g * KSTR + col) = p0;
            *(u32*)(pwp + (g + 8) * KSTR + col) = p1;
        }
        __syncwarp();

        // ---- O += P V  (f16 MMA; trans ldmatrix for V) ----
#pragma unroll
        for (int kk = 0; kk < 4; kk++) {
            u32 PA[4];
            ldm4(PA, pwb + (u32)a_row * (KSTR * 2) + kk * 32 + a_kb);
#pragma unroll
            for (int jj = 0; jj < 4; jj++) {
                u32 BV[4];
                ldm4t(BV, vhb + (u32)(kk * 16 + a_row) * (KSTR * 2) + jj * 32 + a_kb);
                mmaf16(O[2 * jj],     PA, BV[0], BV[1]);
                mmaf16(O[2 * jj + 1], PA, BV[2], BV[3]);
            }
        }

        __syncthreads();
        if (t + 2 < NTILES) issue(t + 2, buf);
    }

    // ---- epilogue ----
    lac0 += __shfl_xor_sync(0xffffffffu, lac0, 1);
    lac0 += __shfl_xor_sync(0xffffffffu, lac0, 2);
    lac1 += __shfl_xor_sync(0xffffffffu, lac1, 1);
    lac1 += __shfl_xor_sync(0xffffffffu, lac1, 2);
    float inv0 = 1.0f / lac0;
    float inv1 = 1.0f / lac1;

    int nq0 = n0 + wid * 16 + g;
    int nq1 = nq0 + 8;
    float* d0 = g_ave + (((size_t)(b * NN + nq0)) * HH + h) * DD;
    float* d1 = g_ave + (((size_t)(b * NN + nq1)) * HH + h) * DD;
#pragma unroll
    for (int j = 0; j < 8; j++) {
        int dcol = j * 8 + 2 * t4;
        *(float2*)&d0[dcol] = make_float2(O[j][0] * inv0, O[j][1] * inv0);
        *(float2*)&d1[dcol] = make_float2(O[j][2] * inv1, O[j][3] * inv1);
    }
}

// ---------------- Kernel 4: centroid epilogue -------------------------------
// warp per (b,n): prefetch ALL 8 heads first (parallel loads), then 8
// independent interleaved shuffle-reduction chains.
__device__ __forceinline__ float warp_sum(float v)
{
#pragma unroll
    for (int o = 16; o; o >>= 1) v += __shfl_xor_sync(0xffffffffu, v, o);
    return v;
}

__global__ void __launch_bounds__(256) centroid_kernel(float* __restrict__ out)
{
    int w = (blockIdx.x * blockDim.x + threadIdx.x) >> 5;
    int lane = threadIdx.x & 31;
    const float* a = g_ave + (size_t)w * HH * DD;

    float a0[HH], a1[HH];
#pragma unroll
    for (int h = 0; h < HH; h++) {
        a0[h] = a[h * DD + lane];
        a1[h] = a[h * DD + lane + 32];
    }

    float part[HH];
#pragma unroll
    for (int h = 0; h < HH; h++) {
        part[h] = a0[h] * a0[h] + a1[h] * a1[h];
        if (lane == 0) part[h] -= 2.0f * a0[h] * a0[h];
    }
    // 8 independent reduction chains (ILP across h)
#pragma unroll
    for (int o = 16; o; o >>= 1) {
#pragma unroll
        for (int h = 0; h < HH; h++)
            part[h] += __shfl_xor_sync(0xffffffffu, part[h], o);
    }

    float m0 = 0.f, m1 = 0.f;
#pragma unroll
    for (int h = 0; h < HH; h++) {
        float inv = rsqrtf(fmaxf(fabsf(part[h]), 1e-8f));
        m0 += a0[h] * inv;
        m1 += a1[h] * inv;
    }
    m0 *= (1.0f / HH); m1 *= (1.0f / HH);
    float p = m0 * m0 + m1 * m1;
    if (lane == 0) p -= 2.0f * m0 * m0;
    float inner = warp_sum(p);
    float inv = rsqrtf(fmaxf(fabsf(inner), 1e-8f));
    out[(size_t)w * DD + lane] = m0 * inv;
    out[(size_t)w * DD + lane + 32] = m1 * inv;
}

// ---------------- launch -----------------------------------------------------
extern "C" void kernel_launch(void* const* d_in, const int* in_sizes, int n_in,
                              void* d_out, int out_size)
{
    const float* query  = (const float*)d_in[0];
    const float* source = (const float*)d_in[1];
    const float* Wq = (const float*)d_in[2];
    const float* bq = (const float*)d_in[3];
    const float* Wk = (const float*)d_in[4];
    const float* bk = (const float*)d_in[5];
    const float* Wv = (const float*)d_in[6];
    const float* bv = (const float*)d_in[7];
    const float* scale = (const float*)d_in[8];
    float* out = (float*)d_out;

    cudaFuncSetAttribute(gemm_lift, cudaFuncAttributeMaxDynamicSharedMemorySize, GSM_BYTES);
    cudaFuncSetAttribute(attn_mma, cudaFuncAttributeMaxDynamicSharedMemorySize, ASM_BYTES);

    // total split elements: 2*ROWS*EE + 3*EE*EE, processed 4 per thread
    int split_blocks = (2 * ROWS * EE + 3 * EE * EE) / 4 / 256;
    split_all<<<split_blocks, 256>>>(query, source, Wq, Wk, Wv);

    gemm_lift<<<dim3(ROWS / 128, HH, 3), 256, GSM_BYTES>>>(bq, bk, bv, scale);

    attn_mma<<<dim3(NN / QT, BHN), 256, ASM_BYTES>>>();

    centroid_kernel<<<ROWS * 32 / 256, 256>>>(out);
}

// round 17
// speedup vs baseline: 13.6499x; 1.1757x over previous
#include <cuda_runtime.h>
#include <cuda_bf16.h>
#include <cuda_fp16.h>
#include <cstdint>

// Problem constants
#define BB 2
#define NN 2048
#define HH 8
#define EE 512
#define DOUT 504          // H * 63
#define DD 64             // lifted dim
#define ROWS 4096         // B*N
#define BHN (BB*HH)       // 16

typedef unsigned long long u64;
typedef uint32_t u32;

// ---------------- scratch (device globals; no allocation allowed) ----------
__device__ alignas(16) __half g_af[2 * ROWS * EE];  // inputs (query, source), f16
__device__ alignas(16) __half g_wf[3 * EE * EE];    // W f16, head-padded rows (h*64+d)
__device__ alignas(16) __half g_qh[BHN * NN * DD];  // lifted q (sign, 2*log2e/scale folded)
__device__ alignas(16) __half g_kh[BHN * NN * DD];  // lifted k (f16)
__device__ alignas(16) __half g_vh[BHN * NN * DD];  // lifted v (f16)
__device__ float g_ave[ROWS * HH * DD];             // attention output per head

// ---------------- helpers ----------------------------------------------------
__device__ __forceinline__ void cpa16(u32 dst, const void* src) {
    asm volatile("cp.async.cg.shared.global [%0], [%1], 16;" :: "r"(dst), "l"(src));
}
__device__ __forceinline__ void cpa_commit() {
    asm volatile("cp.async.commit_group;" ::: "memory");
}
__device__ __forceinline__ void mmaf16(float* d, const u32* a, u32 b0, u32 b1) {
    asm volatile("mma.sync.aligned.m16n8k16.row.col.f32.f16.f16.f32 "
        "{%0,%1,%2,%3}, {%4,%5,%6,%7}, {%8,%9}, {%0,%1,%2,%3};"
        : "+f"(d[0]), "+f"(d[1]), "+f"(d[2]), "+f"(d[3])
        : "r"(a[0]), "r"(a[1]), "r"(a[2]), "r"(a[3]), "r"(b0), "r"(b1));
}
__device__ __forceinline__ void ldm4(u32* r, u32 addr) {
    asm volatile("ldmatrix.sync.aligned.m8n8.x4.shared.b16 {%0,%1,%2,%3}, [%4];"
        : "=r"(r[0]), "=r"(r[1]), "=r"(r[2]), "=r"(r[3]) : "r"(addr));
}
__device__ __forceinline__ void ldm4t(u32* r, u32 addr) {
    asm volatile("ldmatrix.sync.aligned.m8n8.x4.trans.shared.b16 {%0,%1,%2,%3}, [%4];"
        : "=r"(r[0]), "=r"(r[1]), "=r"(r[2]), "=r"(r[3]) : "r"(addr));
}
// pack two f32 -> f16x2 (lo = first arg)
__device__ __forceinline__ u32 f16x2pack(float lo, float hi) {
    u32 r;
    asm("cvt.rn.f16x2.f32 %0, %1, %2;" : "=r"(r) : "f"(hi), "f"(lo));
    return r;
}
__device__ __forceinline__ u32 ex2h2(u32 s) {
    u32 r;
    asm("ex2.approx.f16x2 %0, %1;" : "=r"(r) : "r"(s));
    return r;
}

// ---------------- Kernel 0: fused convert (inputs f16 + weights f16) --------
// 4 elems/thread. weights use padded row h*64+d; d==0 -> 0, d>=1 -> h*63+(d-1).
__global__ void __launch_bounds__(256) split_all(
    const float* __restrict__ q, const float* __restrict__ s,
    const float* __restrict__ Wq, const float* __restrict__ Wk,
    const float* __restrict__ Wv)
{
    int i = (blockIdx.x * blockDim.x + threadIdx.x) * 4;
    const int half = ROWS * EE;
    const int tot_in = 2 * half;
    float4 v;
    __half* dst;
    int o;
    if (i < tot_in) {
        v = (i < half) ? *(const float4*)(q + i) : *(const float4*)(s + i - half);
        dst = g_af; o = i;
    } else {
        int j = i - tot_in;
        int z = j / (EE * EE);
        int rem = j - z * (EE * EE);
        int row = rem >> 9;
        int col = rem & 511;
        int d = row & 63, h = row >> 6;
        const float* W = (z == 0) ? Wq : (z == 1 ? Wk : Wv);
        v = make_float4(0.f, 0.f, 0.f, 0.f);
        if (d > 0) v = *(const float4*)(W + (size_t)(h * 63 + d - 1) * EE + col);
        dst = g_wf; o = j;
    }
    __half2 p0 = __floats2half2_rn(v.x, v.y);
    __half2 p1 = __floats2half2_rn(v.z, v.w);
    u64 pk;
    asm("mov.b64 %0, {%1, %2};" : "=l"(pk) : "r"(*(u32*)&p0), "r"(*(u32*)&p1));
    *(u64*)&dst[o] = pk;
}

// ---------------- Kernel 1: QKV GEMM + fused hyperboloid lift ----------------
// Block: 256 thr, 8 warps along M (warp tile 16 x 64). Tile M=128, N=64
// (= one head via padded-W layout), k-chunk 32, 2-stage cp.async, 3 CTAs/SM.
// Pure f16 single MMA. Epilogue: row ||x||^2 via quad shfl -> t -> f16 q/k/v.
#define ASTR 40                       // f16 k-stride (80B rows)
#define ABUF (128 * ASTR)             // 5120
#define WBUF (64 * ASTR)              // 2560
#define GAF 0
#define GWF (2 * ABUF)                // 10240
#define GSM_BYTES ((GWF + 2 * WBUF) * 2)   // 30720

__global__ void __launch_bounds__(256, 3) gemm_lift(
    const float* __restrict__ bq, const float* __restrict__ bk,
    const float* __restrict__ bv, const float* __restrict__ scale_ptr)
{
    extern __shared__ __half smh[];
    u32 smb = (u32)__cvta_generic_to_shared(smh);

    const int tid = threadIdx.x;
    const int wid = tid >> 5;
    const int lane = tid & 31;
    const int g = lane >> 2;
    const int t4 = lane & 3;
    const int mi = lane >> 3, lr = lane & 7;
    const int a_row = (mi & 1) * 8 + lr;
    const int a_kb  = (mi >> 1) * 16;
    const int b_row = (mi >> 1) * 8 + lr;
    const int b_kb  = (mi & 1) * 16;

    const int mTile = blockIdx.x * 128;
    const int h = blockIdx.y;          // head 0..7
    const int z = blockIdx.z;

    const __half* afg = g_af + (size_t)(z ? 1 : 0) * ROWS * EE;
    const __half* wfg = g_wf + (size_t)z * EE * EE;

    float acc[8][4];
#pragma unroll
    for (int n = 0; n < 8; n++)
#pragma unroll
        for (int r = 0; r < 4; r++) acc[n][r] = 0.f;

    auto issue = [&](int chunk, int stg) {
        int k0 = chunk * 32;
#pragma unroll
        for (int it = 0; it < 2; it++) {
            int idx = it * 256 + tid;
            int row = idx >> 2, c = idx & 3;
            size_t go = (size_t)(mTile + row) * EE + k0 + c * 8;
            u32 so = row * (ASTR * 2) + c * 16;
            cpa16(smb + (GAF + stg * ABUF) * 2 + so, afg + go);
        }
        {
            int row = tid >> 2, c = tid & 3;
            size_t go = (size_t)(h * 64 + row) * EE + k0 + c * 8;
            u32 so = row * (ASTR * 2) + c * 16;
            cpa16(smb + (GWF + stg * WBUF) * 2 + so, wfg + go);
        }
        cpa_commit();
    };

    issue(0, 0);
    issue(1, 1);

    const int NCH = EE / 32;   // 16
    for (int t = 0; t < NCH; t++) {
        if (t + 1 < NCH) asm volatile("cp.async.wait_group 1;" ::: "memory");
        else             asm volatile("cp.async.wait_group 0;" ::: "memory");
        __syncthreads();

        const int stg = t & 1;
        u32 afb = smb + (GAF + stg * ABUF) * 2;
        u32 wfb = smb + (GWF + stg * WBUF) * 2;

#pragma unroll
        for (int kk = 0; kk < 2; kk++) {
            u32 AF[4];
            u32 ao = (u32)(wid * 16 + a_row) * (ASTR * 2) + kk * 32 + a_kb;
            ldm4(AF, afb + ao);
#pragma unroll
            for (int nt = 0; nt < 4; nt++) {
                u32 WF[4];
                u32 wo = (u32)(nt * 16 + b_row) * (ASTR * 2) + kk * 32 + b_kb;
                ldm4(WF, wfb + wo);
                mmaf16(acc[2 * nt],     AF, WF[0], WF[1]);
                mmaf16(acc[2 * nt + 1], AF, WF[2], WF[3]);
            }
        }
        __syncthreads();
        if (t + 2 < NCH) issue(t + 2, stg);
    }

    // ---- fused lift epilogue ----
    const float* bias = (z == 0) ? bq : (z == 1 ? bk : bv);
    float s0 = 0.f, s1 = 0.f;
#pragma unroll
    for (int j = 0; j < 8; j++) {
        int c = j * 8 + 2 * t4;
        float b0 = (c == 0) ? 0.f : __ldg(&bias[h * 63 + c - 1]);
        float b1 = __ldg(&bias[h * 63 + c]);
        acc[j][0] += b0;  acc[j][1] += b1;
        acc[j][2] += b0;  acc[j][3] += b1;
        s0 += acc[j][0] * acc[j][0] + acc[j][1] * acc[j][1];
        s1 += acc[j][2] * acc[j][2] + acc[j][3] * acc[j][3];
    }
    s0 += __shfl_xor_sync(0xffffffffu, s0, 1);
    s0 += __shfl_xor_sync(0xffffffffu, s0, 2);
    s1 += __shfl_xor_sync(0xffffffffu, s1, 1);
    s1 += __shfl_xor_sync(0xffffffffu, s1, 2);
    float t0 = sqrtf(s0 + 1.0f);
    float t1 = sqrtf(s1 + 1.0f);

    int n0 = mTile + wid * 16 + g;      // global row (0..4095)
    int n1 = n0 + 8;
    int b0i = n0 >> 11;
    int bh = b0i * HH + h;
    size_t base0 = ((size_t)bh * NN + (n0 & (NN - 1))) * DD;
    size_t base1 = ((size_t)bh * NN + (n1 & (NN - 1))) * DD;

    if (z == 0) {
        // fold 2/scale AND log2(e) so attention exp becomes ex2
        float sc = (2.0f * 1.44269504088896f) / __ldg(scale_ptr);
#pragma unroll
        for (int j = 0; j < 8; j++) {
            int c = j * 8 + 2 * t4;
            float a0 = (c == 0) ? -t0 : acc[j][0];
            float a2 = (c == 0) ? -t1 : acc[j][2];
            __half2 p0 = __floats2half2_rn(a0 * sc, acc[j][1] * sc);
            __half2 p1 = __floats2half2_rn(a2 * sc, acc[j][3] * sc);
            *(u32*)&g_qh[base0 + c] = *(u32*)&p0;
            *(u32*)&g_qh[base1 + c] = *(u32*)&p1;
        }
    } else if (z == 1) {
#pragma unroll
        for (int j = 0; j < 8; j++) {
            int c = j * 8 + 2 * t4;
            float a0 = (c == 0) ? t0 : acc[j][0];
            float a2 = (c == 0) ? t1 : acc[j][2];
            __half2 p0 = __floats2half2_rn(a0, acc[j][1]);
            __half2 p1 = __floats2half2_rn(a2, acc[j][3]);
            *(u32*)&g_kh[base0 + c] = *(u32*)&p0;
            *(u32*)&g_kh[base1 + c] = *(u32*)&p1;
        }
    } else {
#pragma unroll
        for (int j = 0; j < 8; j++) {
            int c = j * 8 + 2 * t4;
            float a0 = (c == 0) ? t0 : acc[j][0];
            float a2 = (c == 0) ? t1 : acc[j][2];
            __half2 p0 = __floats2half2_rn(a0, acc[j][1]);
            __half2 p1 = __floats2half2_rn(a2, acc[j][3]);
            *(u32*)&g_vh[base0 + c] = *(u32*)&p0;
            *(u32*)&g_vh[base1 + c] = *(u32*)&p1;
        }
    }
}

// ---------------- Kernel 3: f16 mma flash attention --------------------------
// 256 thr (8 warps), 128 queries/block (M=16/warp). Key tiles of 64, 2-stage
// cp.async, 2 CTAs/SM. QK: q*k single f16 MMA per k16. exp via ex2.f16x2
// (log2e pre-folded into q). PV: P_f16 x V_f16.
// No online max (hyperboloid: log2-logits bounded in [~-3.6, -0.127]).
#define QT 128
#define KT 64
#define NTILES 32

#define KSTR 72                        // f16 stride (144B rows)
#define TBUF (64 * KSTR)               // 4608 halfs
#define KH_OFF 0
#define VH_OFF (2 * TBUF)              // 9216
#define P_OFF  (4 * TBUF)              // 18432
#define PW_SZ  (16 * KSTR)             // 1152
#define ASM_BYTES ((P_OFF + 8 * PW_SZ) * 2)   // 55296

__global__ void __launch_bounds__(256, 2) attn_mma()
{
    extern __shared__ __half smh[];
    u32 smb = (u32)__cvta_generic_to_shared(smh);

    const int tid = threadIdx.x;
    const int wid = tid >> 5;
    const int lane = tid & 31;
    const int g = lane >> 2;
    const int t4 = lane & 3;
    const int mi = lane >> 3, lr = lane & 7;
    const int a_row = (mi & 1) * 8 + lr;
    const int a_kb  = (mi >> 1) * 16;
    const int b_row = (mi >> 1) * 8 + lr;
    const int b_kb  = (mi & 1) * 16;

    const int qt = blockIdx.x;
    const int bh = blockIdx.y;
    const int n0 = qt * QT;
    const int b = bh >> 3, h = bh & 7;

    // ---- persistent Q A-fragments (f16), M=16 rows per warp ----
    u32 AH[4][4];
    {
        const __half* qh = g_qh + ((size_t)bh * NN + n0 + wid * 16) * DD;
#pragma unroll
        for (int kk = 0; kk < 4; kk++) {
            int c = kk * 16 + 2 * t4;
            AH[kk][0] = *(const u32*)(qh + g * DD + c);
            AH[kk][1] = *(const u32*)(qh + (g + 8) * DD + c);
            AH[kk][2] = *(const u32*)(qh + g * DD + c + 8);
            AH[kk][3] = *(const u32*)(qh + (g + 8) * DD + c + 8);
        }
    }

    float O[8][4];
#pragma unroll
    for (int j = 0; j < 8; j++)
#pragma unroll
        for (int r = 0; r < 4; r++) O[j][r] = 0.f;
    float lac0 = 0.f, lac1 = 0.f;

    const __half* khg = g_kh + (size_t)bh * NN * DD;
    const __half* vhg = g_vh + (size_t)bh * NN * DD;

    auto issue = [&](int tile, int buf) {
#pragma unroll
        for (int j = 0; j < 4; j++) {
            int idx = j * 256 + tid;
            int arr = idx >> 9;
            int w = idx & 511;
            int row = w >> 3, c = w & 7;
            const __half* src = (arr == 0 ? khg : vhg)
                                + (size_t)(tile * KT + row) * DD + c * 8;
            u32 off = (arr == 0 ? KH_OFF : VH_OFF);
            cpa16(smb + (off + buf * TBUF + row * KSTR) * 2 + c * 16, src);
        }
        cpa_commit();
    };

    issue(0, 0);
    issue(1, 1);

    u32 pwb = smb + (P_OFF + wid * PW_SZ) * 2;
    __half* pwp = smh + P_OFF + wid * PW_SZ;

    for (int t = 0; t < NTILES; t++) {
        if (t + 1 < NTILES) asm volatile("cp.async.wait_group 1;" ::: "memory");
        else                asm volatile("cp.async.wait_group 0;" ::: "memory");
        __syncthreads();

        const int buf = t & 1;
        u32 khb = smb + (KH_OFF + buf * TBUF) * 2;
        u32 vhb = smb + (VH_OFF + buf * TBUF) * 2;

        // ---- S = Q K^T  (single f16 MMA per k16) ----
        float S[8][4];
#pragma unroll
        for (int j = 0; j < 8; j++)
#pragma unroll
            for (int r = 0; r < 4; r++) S[j][r] = 0.f;

#pragma unroll
        for (int kk = 0; kk < 4; kk++) {
#pragma unroll
            for (int jj = 0; jj < 4; jj++) {
                u32 ko = (u32)(jj * 16 + b_row) * (KSTR * 2) + kk * 32 + b_kb;
                u32 BH[4];
                ldm4(BH, khb + ko);
                mmaf16(S[2 * jj],     AH[kk], BH[0], BH[1]);
                mmaf16(S[2 * jj + 1], AH[kk], BH[2], BH[3]);
            }
        }

        // ---- p = 2^s via packed f16 ex2 (log2e folded into q) ----
#pragma unroll
        for (int j = 0; j < 8; j++) {
            u32 s0 = f16x2pack(S[j][0], S[j][1]);
            u32 s1 = f16x2pack(S[j][2], S[j][3]);
            u32 p0 = ex2h2(s0);
            u32 p1 = ex2h2(s1);
            float2 f0 = __half22float2(*(__half2*)&p0);
            float2 f1 = __half22float2(*(__half2*)&p1);
            lac0 += f0.x + f0.y;
            lac1 += f1.x + f1.y;
            int col = j * 8 + 2 * t4;
            *(u32*)(pwp + g * KSTR + col) = p0;
            *(u32*)(pwp + (g + 8) * KSTR + col) = p1;
        }
        __syncwarp();

        // ---- O += P V  (f16 MMA; trans ldmatrix for V) ----
#pragma unroll
        for (int kk = 0; kk < 4; kk++) {
            u32 PA[4];
            ldm4(PA, pwb + (u32)a_row * (KSTR * 2) + kk * 32 + a_kb);
#pragma unroll
            for (int jj = 0; jj < 4; jj++) {
                u32 BV[4];
                ldm4t(BV, vhb + (u32)(kk * 16 + a_row) * (KSTR * 2) + jj * 32 + a_kb);
                mmaf16(O[2 * jj],     PA, BV[0], BV[1]);
                mmaf16(O[2 * jj + 1], PA, BV[2], BV[3]);
            }
        }

        __syncthreads();
        if (t + 2 < NTILES) issue(t + 2, buf);
    }

    // ---- epilogue ----
    lac0 += __shfl_xor_sync(0xffffffffu, lac0, 1);
    lac0 += __shfl_xor_sync(0xffffffffu, lac0, 2);
    lac1 += __shfl_xor_sync(0xffffffffu, lac1, 1);
    lac1 += __shfl_xor_sync(0xffffffffu, lac1, 2);
    float inv0 = 1.0f / lac0;
    float inv1 = 1.0f / lac1;

    int nq0 = n0 + wid * 16 + g;
    int nq1 = nq0 + 8;
    float* d0 = g_ave + (((size_t)(b * NN + nq0)) * HH + h) * DD;
    float* d1 = g_ave + (((size_t)(b * NN + nq1)) * HH + h) * DD;
#pragma unroll
    for (int j = 0; j < 8; j++) {
        int dcol = j * 8 + 2 * t4;
        *(float2*)&d0[dcol] = make_float2(O[j][0] * inv0, O[j][1] * inv0);
        *(float2*)&d1[dcol] = make_float2(O[j][2] * inv1, O[j][3] * inv1);
    }
}

// ---------------- Kernel 4: centroid epilogue -------------------------------
// warp per (b,n): prefetch ALL 8 heads first (parallel loads), then 8
// independent interleaved shuffle-reduction chains.
__device__ __forceinline__ float warp_sum(float v)
{
#pragma unroll
    for (int o = 16; o; o >>= 1) v += __shfl_xor_sync(0xffffffffu, v, o);
    return v;
}

__global__ void __launch_bounds__(256) centroid_kernel(float* __restrict__ out)
{
    int w = (blockIdx.x * blockDim.x + threadIdx.x) >> 5;
    int lane = threadIdx.x & 31;
    const float* a = g_ave + (size_t)w * HH * DD;

    float a0[HH], a1[HH];
#pragma unroll
    for (int h = 0; h < HH; h++) {
        a0[h] = a[h * DD + lane];
        a1[h] = a[h * DD + lane + 32];
    }

    float part[HH];
#pragma unroll
    for (int h = 0; h < HH; h++) {
        part[h] = a0[h] * a0[h] + a1[h] * a1[h];
        if (lane == 0) part[h] -= 2.0f * a0[h] * a0[h];
    }
    // 8 independent reduction chains (ILP across h)
#pragma unroll
    for (int o = 16; o; o >>= 1) {
#pragma unroll
        for (int h = 0; h < HH; h++)
            part[h] += __shfl_xor_sync(0xffffffffu, part[h], o);
    }

    float m0 = 0.f, m1 = 0.f;
#pragma unroll
    for (int h = 0; h < HH; h++) {
        float inv = rsqrtf(fmaxf(fabsf(part[h]), 1e-8f));
        m0 += a0[h] * inv;
        m1 += a1[h] * inv;
    }
    m0 *= (1.0f / HH); m1 *= (1.0f / HH);
    float p = m0 * m0 + m1 * m1;
    if (lane == 0) p -= 2.0f * m0 * m0;
    float inner = warp_sum(p);
    float inv = rsqrtf(fmaxf(fabsf(inner), 1e-8f));
    out[(size_t)w * DD + lane] = m0 * inv;
    out[(size_t)w * DD + lane + 32] = m1 * inv;
}

// ---------------- launch -----------------------------------------------------
extern "C" void kernel_launch(void* const* d_in, const int* in_sizes, int n_in,
                              void* d_out, int out_size)
{
    const float* query  = (const float*)d_in[0];
    const float* source = (const float*)d_in[1];
    const float* Wq = (const float*)d_in[2];
    const float* bq = (const float*)d_in[3];
    const float* Wk = (const float*)d_in[4];
    const float* bk = (const float*)d_in[5];
    const float* Wv = (const float*)d_in[6];
    const float* bv = (const float*)d_in[7];
    const float* scale = (const float*)d_in[8];
    float* out = (float*)d_out;

    cudaFuncSetAttribute(gemm_lift, cudaFuncAttributeMaxDynamicSharedMemorySize, GSM_BYTES);
    cudaFuncSetAttribute(attn_mma, cudaFuncAttributeMaxDynamicSharedMemorySize, ASM_BYTES);

    // total convert elements: 2*ROWS*EE + 3*EE*EE, processed 4 per thread
    int split_blocks = (2 * ROWS * EE + 3 * EE * EE) / 4 / 256;
    split_all<<<split_blocks, 256>>>(query, source, Wq, Wk, Wv);

    gemm_lift<<<dim3(ROWS / 128, HH, 3), 256, GSM_BYTES>>>(bq, bk, bv, scale);

    attn_mma<<<dim3(NN / QT, BHN), 256, ASM_BYTES>>>();

    centroid_kernel<<<ROWS * 32 / 256, 256>>>(out);
}